// round 1
// baseline (speedup 1.0000x reference)
#include <cuda_runtime.h>
#include <cuda_bf16.h>
#include <math.h>

#define SEQ 2048
#define HID 2048
#define NH 16
#define QL 1536
#define KVL 512
#define DN 128
#define DR 64
#define DV 128
#define DQK 192
#define CKVW (KVL + DR)   // 576
#define QW (NH * DQK)     // 3072
#define KVW (NH * (DN + DV)) // 4096
#define AW (NH * DV)      // 2048

// ---------------- scratch (no allocations allowed) ----------------
__device__ float g_qa_s [(size_t)SEQ * QL];
__device__ float g_q_s  [(size_t)SEQ * QW];
__device__ float g_ckv_s[(size_t)SEQ * CKVW];
__device__ float g_kv_s [(size_t)SEQ * KVW];
__device__ float g_kpe_s[(size_t)SEQ * DR];
__device__ float g_at_s [(size_t)SEQ * AW];

// ---------------- generic SGEMM: C[M,N] = A[M,K] @ B[K,N] ----------------
// 128x128 block tile, K-step 8, 256 threads, 8x8 per-thread microtile.
// M, K must be multiples of 128 / 8 respectively; N guarded.
__global__ __launch_bounds__(256) void sgemm128(
    const float* __restrict__ A, int lda,
    const float* __restrict__ B, int ldb,
    float* __restrict__ C, int ldc,
    int M, int N, int K)
{
    __shared__ float As[8 * 128];
    __shared__ float Bs[8 * 128];

    const int tid  = threadIdx.x;
    const int row0 = blockIdx.y * 128;
    const int col0 = blockIdx.x * 128;
    const int tx = tid & 15;
    const int ty = tid >> 4;

    // A-load mapping: each thread loads float4 (row am, cols k0+ak..+3)
    const int am = tid >> 1;
    const int ak = (tid & 1) * 4;
    // B-load mapping: row k0+bk, cols col0+bn..+3
    const int bk = tid >> 5;
    const int bn = (tid & 31) * 4;

    float acc[8][8];
#pragma unroll
    for (int i = 0; i < 8; ++i)
#pragma unroll
        for (int j = 0; j < 8; ++j) acc[i][j] = 0.f;

    for (int k0 = 0; k0 < K; k0 += 8) {
        float4 a4 = *(const float4*)(A + (size_t)(row0 + am) * lda + k0 + ak);
        As[(ak + 0) * 128 + am] = a4.x;
        As[(ak + 1) * 128 + am] = a4.y;
        As[(ak + 2) * 128 + am] = a4.z;
        As[(ak + 3) * 128 + am] = a4.w;

        const float* Brow = B + (size_t)(k0 + bk) * ldb;
        int bcol = col0 + bn;
        float4 b4;
        if (bcol + 3 < N) {
            b4 = *(const float4*)(Brow + bcol);
        } else {
            b4.x = (bcol + 0 < N) ? Brow[bcol + 0] : 0.f;
            b4.y = (bcol + 1 < N) ? Brow[bcol + 1] : 0.f;
            b4.z = (bcol + 2 < N) ? Brow[bcol + 2] : 0.f;
            b4.w = (bcol + 3 < N) ? Brow[bcol + 3] : 0.f;
        }
        *(float4*)(Bs + bk * 128 + bn) = b4;

        __syncthreads();
#pragma unroll
        for (int kk = 0; kk < 8; ++kk) {
            float4 a0 = *(const float4*)(As + kk * 128 + ty * 8);
            float4 a1 = *(const float4*)(As + kk * 128 + ty * 8 + 4);
            float4 b0 = *(const float4*)(Bs + kk * 128 + tx * 8);
            float4 b1 = *(const float4*)(Bs + kk * 128 + tx * 8 + 4);
            float ra[8] = {a0.x, a0.y, a0.z, a0.w, a1.x, a1.y, a1.z, a1.w};
            float rb[8] = {b0.x, b0.y, b0.z, b0.w, b1.x, b1.y, b1.z, b1.w};
#pragma unroll
            for (int i = 0; i < 8; ++i)
#pragma unroll
                for (int j = 0; j < 8; ++j) acc[i][j] += ra[i] * rb[j];
        }
        __syncthreads();
    }

#pragma unroll
    for (int i = 0; i < 8; ++i) {
        int r = row0 + ty * 8 + i;
#pragma unroll
        for (int j = 0; j < 8; ++j) {
            int c = col0 + tx * 8 + j;
            if (c < N) C[(size_t)r * ldc + c] = acc[i][j];
        }
    }
}

// ---------------- RMSNorm (in place on a row slice) ----------------
__global__ __launch_bounds__(256) void rmsnorm_kernel(
    float* __restrict__ x, const float* __restrict__ g, int width, int stride)
{
    __shared__ float red[256];
    float* p = x + (size_t)blockIdx.x * stride;
    float s = 0.f;
    for (int i = threadIdx.x; i < width; i += 256) { float v = p[i]; s += v * v; }
    red[threadIdx.x] = s;
    __syncthreads();
#pragma unroll
    for (int off = 128; off > 0; off >>= 1) {
        if (threadIdx.x < off) red[threadIdx.x] += red[threadIdx.x + off];
        __syncthreads();
    }
    float inv = rsqrtf(red[0] / (float)width + 1e-6f);
    for (int i = threadIdx.x; i < width; i += 256) p[i] = p[i] * inv * g[i];
}

// ---------------- RoPE (deinterleave + rotate_half fused) ----------------
// y[i]    = x[2i]*cos - x[2i+1]*sin
// y[i+32] = x[2i+1]*cos + x[2i]*sin      (i in [0,32), cos[s,i]==cos[s,i+32])
__global__ __launch_bounds__(256) void rope_kernel(
    float* __restrict__ q, const float* __restrict__ ckv, float* __restrict__ kpe,
    const float* __restrict__ cosb, const float* __restrict__ sinb)
{
    int gw   = (blockIdx.x * blockDim.x + threadIdx.x) >> 5;
    int lane = threadIdx.x & 31;
    const int total_q = SEQ * NH;
    if (gw < total_q) {
        int s = gw / NH, h = gw % NH;
        float* x = q + (size_t)s * QW + h * DQK + DN;
        float c  = cosb[s * DR + lane];
        float sn = sinb[s * DR + lane];
        float x0 = x[2 * lane], x1 = x[2 * lane + 1];
        __syncwarp();
        x[lane]      = x0 * c - x1 * sn;
        x[lane + 32] = x1 * c + x0 * sn;
    } else if (gw < total_q + SEQ) {
        int s = gw - total_q;
        const float* x = ckv + (size_t)s * CKVW + KVL;
        float c  = cosb[s * DR + lane];
        float sn = sinb[s * DR + lane];
        float x0 = x[2 * lane], x1 = x[2 * lane + 1];
        kpe[s * DR + lane]      = x0 * c - x1 * sn;
        kpe[s * DR + lane + 32] = x1 * c + x0 * sn;
    }
}

// ---------------- flash attention (causal, fp32, BQ=BK=64) ----------------
#define QK_PAD 196   // 192 rounded; %32==4 -> bank spread, 16B aligned
#define V_PAD  132
#define S_PAD  68
#define ATTN_SMEM_FLOATS (2 * 64 * QK_PAD + 64 * V_PAD + 64 * S_PAD + 3 * 64)
#define ATTN_SMEM_BYTES  (ATTN_SMEM_FLOATS * 4)

__global__ __launch_bounds__(256) void attn_kernel(
    const float* __restrict__ q, const float* __restrict__ kv,
    const float* __restrict__ kpe, float* __restrict__ out)
{
    extern __shared__ float sm[];
    float* Qs = sm;                       // [64][QK_PAD]
    float* Ks = Qs + 64 * QK_PAD;         // [64][QK_PAD]
    float* Vs = Ks + 64 * QK_PAD;         // [64][V_PAD]
    float* Ss = Vs + 64 * V_PAD;          // [64][S_PAD]
    float* mrow = Ss + 64 * S_PAD;
    float* lrow = mrow + 64;
    float* arow = lrow + 64;

    const int qb  = gridDim.x - 1 - blockIdx.x;  // big tiles first (balance)
    const int h   = blockIdx.y;
    const int tid = threadIdx.x;
    const int q0  = qb * 64;
    const int rg  = tid >> 4;   // 16 row groups of 4
    const int cg  = tid & 15;   // 16 col groups
    const float scale = rsqrtf((float)DQK);

    for (int idx = tid; idx < 64 * DQK; idx += 256) {
        int r = idx / DQK, c = idx % DQK;
        Qs[r * QK_PAD + c] = q[(size_t)(q0 + r) * QW + h * DQK + c];
    }
    if (tid < 64) { mrow[tid] = -1e30f; lrow[tid] = 0.f; }

    float acc[4][8];
#pragma unroll
    for (int i = 0; i < 4; ++i)
#pragma unroll
        for (int j = 0; j < 8; ++j) acc[i][j] = 0.f;

    __syncthreads();

    for (int kb = 0; kb <= qb; ++kb) {
        const int k0 = kb * 64;
        for (int idx = tid; idx < 64 * DQK; idx += 256) {
            int r = idx / DQK, c = idx % DQK;
            float v = (c < DN) ? kv[(size_t)(k0 + r) * KVW + h * (DN + DV) + c]
                               : kpe[(size_t)(k0 + r) * DR + (c - DN)];
            Ks[r * QK_PAD + c] = v;
        }
        for (int idx = tid; idx < 64 * DV; idx += 256) {
            int r = idx / DV, c = idx % DV;
            Vs[r * V_PAD + c] = kv[(size_t)(k0 + r) * KVW + h * (DN + DV) + DN + c];
        }
        __syncthreads();

        // S = Q K^T (4x4 per thread), scaled + causal masked
        float s4[4][4];
#pragma unroll
        for (int i = 0; i < 4; ++i)
#pragma unroll
            for (int j = 0; j < 4; ++j) s4[i][j] = 0.f;

        for (int d = 0; d < DQK; d += 4) {
            float4 a[4], b[4];
#pragma unroll
            for (int i = 0; i < 4; ++i) a[i] = *(const float4*)(Qs + (rg * 4 + i) * QK_PAD + d);
#pragma unroll
            for (int j = 0; j < 4; ++j) b[j] = *(const float4*)(Ks + (cg * 4 + j) * QK_PAD + d);
#pragma unroll
            for (int i = 0; i < 4; ++i)
#pragma unroll
                for (int j = 0; j < 4; ++j)
                    s4[i][j] += a[i].x * b[j].x + a[i].y * b[j].y + a[i].z * b[j].z + a[i].w * b[j].w;
        }
#pragma unroll
        for (int i = 0; i < 4; ++i) {
            int r = rg * 4 + i;
#pragma unroll
            for (int j = 0; j < 4; ++j) {
                int c = cg * 4 + j;
                float v = s4[i][j] * scale;
                if (k0 + c > q0 + r) v = -1e30f;
                Ss[r * S_PAD + c] = v;
            }
        }
        __syncthreads();

        // online softmax: one thread per row
        if (tid < 64) {
            float mold = mrow[tid];
            float mnew = mold;
#pragma unroll 8
            for (int j = 0; j < 64; ++j) mnew = fmaxf(mnew, Ss[tid * S_PAD + j]);
            float alpha = __expf(mold - mnew);
            float sum = 0.f;
#pragma unroll 8
            for (int j = 0; j < 64; ++j) {
                float p = __expf(Ss[tid * S_PAD + j] - mnew);
                Ss[tid * S_PAD + j] = p;
                sum += p;
            }
            mrow[tid] = mnew;
            lrow[tid] = lrow[tid] * alpha + sum;
            arow[tid] = alpha;
        }
        __syncthreads();

        // rescale + O += P @ V  (4 rows x 8 cols per thread)
        float al[4];
#pragma unroll
        for (int i = 0; i < 4; ++i) al[i] = arow[rg * 4 + i];
#pragma unroll
        for (int i = 0; i < 4; ++i)
#pragma unroll
            for (int j = 0; j < 8; ++j) acc[i][j] *= al[i];

        for (int kk = 0; kk < 64; ++kk) {
            float p[4];
#pragma unroll
            for (int i = 0; i < 4; ++i) p[i] = Ss[(rg * 4 + i) * S_PAD + kk];
            float4 v0 = *(const float4*)(Vs + kk * V_PAD + cg * 8);
            float4 v1 = *(const float4*)(Vs + kk * V_PAD + cg * 8 + 4);
            float vv[8] = {v0.x, v0.y, v0.z, v0.w, v1.x, v1.y, v1.z, v1.w};
#pragma unroll
            for (int i = 0; i < 4; ++i)
#pragma unroll
                for (int j = 0; j < 8; ++j) acc[i][j] += p[i] * vv[j];
        }
        __syncthreads();
    }

#pragma unroll
    for (int i = 0; i < 4; ++i) {
        int r = rg * 4 + i;
        float inv = 1.f / lrow[r];
#pragma unroll
        for (int j = 0; j < 8; ++j) {
            out[(size_t)(q0 + r) * AW + h * DV + cg * 8 + j] = acc[i][j] * inv;
        }
    }
}

// ---------------- launch ----------------
extern "C" void kernel_launch(void* const* d_in, const int* in_sizes, int n_in,
                              void* d_out, int out_size)
{
    const float* hidden = (const float*)d_in[0];
    const float* cosb   = (const float*)d_in[1];
    const float* sinb   = (const float*)d_in[2];
    const float* w_qa   = (const float*)d_in[3];
    const float* gm_qa  = (const float*)d_in[4];
    const float* w_qb   = (const float*)d_in[5];
    const float* w_kva  = (const float*)d_in[6];
    const float* gm_kva = (const float*)d_in[7];
    const float* w_kvb  = (const float*)d_in[8];
    const float* w_o    = (const float*)d_in[9];
    float* out = (float*)d_out;

    float *qa, *qq, *ckv, *kv, *kpe, *attn;
    cudaGetSymbolAddress((void**)&qa,   g_qa_s);
    cudaGetSymbolAddress((void**)&qq,   g_q_s);
    cudaGetSymbolAddress((void**)&ckv,  g_ckv_s);
    cudaGetSymbolAddress((void**)&kv,   g_kv_s);
    cudaGetSymbolAddress((void**)&kpe,  g_kpe_s);
    cudaGetSymbolAddress((void**)&attn, g_at_s);

    static bool attr_done = false;
    if (!attr_done) {
        cudaFuncSetAttribute(attn_kernel, cudaFuncAttributeMaxDynamicSharedMemorySize,
                             ATTN_SMEM_BYTES);
        attr_done = true;
    }

    // q_a = hidden @ w_qa   [2048,1536]
    sgemm128<<<dim3(QL / 128, SEQ / 128), 256>>>(hidden, HID, w_qa, QL, qa, QL, SEQ, QL, HID);
    // ckv = hidden @ w_kva  [2048,576]
    sgemm128<<<dim3((CKVW + 127) / 128, SEQ / 128), 256>>>(hidden, HID, w_kva, CKVW, ckv, CKVW, SEQ, CKVW, HID);
    // rmsnorms (in place)
    rmsnorm_kernel<<<SEQ, 256>>>(qa, gm_qa, QL, QL);
    rmsnorm_kernel<<<SEQ, 256>>>(ckv, gm_kva, KVL, CKVW);
    // q = qa_n @ w_qb  [2048,3072]
    sgemm128<<<dim3(QW / 128, SEQ / 128), 256>>>(qa, QL, w_qb, QW, qq, QW, SEQ, QW, QL);
    // kv = ckv_n @ w_kvb  [2048,4096]
    sgemm128<<<dim3(KVW / 128, SEQ / 128), 256>>>(ckv, CKVW, w_kvb, KVW, kv, KVW, SEQ, KVW, KVL);
    // RoPE on q_pe (in place) + k_pe -> kpe
    rope_kernel<<<(SEQ * (NH + 1)) / 8, 256>>>(qq, ckv, kpe, cosb, sinb);
    // attention
    attn_kernel<<<dim3(SEQ / 64, NH), 256, ATTN_SMEM_BYTES>>>(qq, kv, kpe, attn);
    // out = attn @ w_o  [2048,2048]
    sgemm128<<<dim3(HID / 128, SEQ / 128), 256>>>(attn, AW, w_o, HID, out, HID, SEQ, AW, HID);
}

// round 2
// speedup vs baseline: 1.2336x; 1.2336x over previous
#include <cuda_runtime.h>
#include <cuda_bf16.h>
#include <math.h>

#define SEQ 2048
#define HID 2048
#define NH 16
#define QL 1536
#define KVL 512
#define DN 128
#define DR 64
#define DV 128
#define DQK 192
#define CKVW (KVL + DR)      // 576
#define QW (NH * DQK)        // 3072
#define KVW (NH * (DN + DV)) // 4096
#define AW (NH * DV)         // 2048

// ---------------- scratch ----------------
__device__ float g_qa_s [(size_t)SEQ * QL];
__device__ float g_q_s  [(size_t)SEQ * QW];
__device__ float g_ckv_s[(size_t)SEQ * CKVW];
__device__ float g_kv_s [(size_t)SEQ * KVW];
__device__ float g_kpe_s[(size_t)SEQ * DR];
__device__ float g_at_s [(size_t)SEQ * AW];

// ================= 3xTF32 tensor-core GEMM =================
// C[M,N] = A[M,K] @ B[K,N], fp32 in/out, near-fp32 accuracy via hi/lo split.
// Block 128x128x32, 256 threads, warp grid 4(M) x 2(N), warp tile 32x64.
#define AP 36    // A smem row pad (floats): frag bank = 4g+t -> conflict free
#define BP 136   // B smem row pad (floats): frag bank = 8t+g -> conflict free
#define GEMM_SMEM_BYTES ((2 * 128 * AP + 2 * 32 * BP) * 4)   // 71680

__device__ __forceinline__ void tf32_split(float x, float& h, float& l) {
    unsigned hu; asm("cvt.rna.tf32.f32 %0, %1;" : "=r"(hu) : "f"(x));
    h = __uint_as_float(hu);
    float r = x - h;
    unsigned lu; asm("cvt.rna.tf32.f32 %0, %1;" : "=r"(lu) : "f"(r));
    l = __uint_as_float(lu);
}

#define MMA_TF32(d, a, b)                                                     \
    asm volatile("mma.sync.aligned.m16n8k8.row.col.f32.tf32.tf32.f32 "        \
                 "{%0,%1,%2,%3}, {%4,%5,%6,%7}, {%8,%9}, {%0,%1,%2,%3};"      \
                 : "+f"(d[0]), "+f"(d[1]), "+f"(d[2]), "+f"(d[3])             \
                 : "r"(a[0]), "r"(a[1]), "r"(a[2]), "r"(a[3]),                \
                   "r"(b[0]), "r"(b[1]))

__device__ __forceinline__ void gemm_ldg(
    const float* __restrict__ A, int lda, const float* __restrict__ B, int ldb,
    int row0, int col0, int N, int k0, int tid, float4* Ar, float4* Br)
{
#pragma unroll
    for (int i = 0; i < 4; ++i) {
        int idx = tid + i * 256;
        int r = idx >> 3, c4 = idx & 7;
        Ar[i] = *(const float4*)(A + (size_t)(row0 + r) * lda + k0 + c4 * 4);
    }
#pragma unroll
    for (int i = 0; i < 4; ++i) {
        int idx = tid + i * 256;
        int r = idx >> 5, c4 = idx & 31;
        int c = col0 + c4 * 4;
        const float* p = B + (size_t)(k0 + r) * ldb;
        float4 v;
        if (c + 3 < N) {
            v = *(const float4*)(p + c);
        } else {
            v.x = (c + 0 < N) ? p[c + 0] : 0.f;
            v.y = (c + 1 < N) ? p[c + 1] : 0.f;
            v.z = (c + 2 < N) ? p[c + 2] : 0.f;
            v.w = (c + 3 < N) ? p[c + 3] : 0.f;
        }
        Br[i] = v;
    }
}

__device__ __forceinline__ void gemm_sts(
    float* Ah, float* Al, float* Bh, float* Bl,
    int tid, const float4* Ar, const float4* Br)
{
#pragma unroll
    for (int i = 0; i < 4; ++i) {
        int idx = tid + i * 256;
        int r = idx >> 3, c4 = idx & 7;
        float4 h, l;
        tf32_split(Ar[i].x, h.x, l.x); tf32_split(Ar[i].y, h.y, l.y);
        tf32_split(Ar[i].z, h.z, l.z); tf32_split(Ar[i].w, h.w, l.w);
        *(float4*)(Ah + r * AP + c4 * 4) = h;
        *(float4*)(Al + r * AP + c4 * 4) = l;
    }
#pragma unroll
    for (int i = 0; i < 4; ++i) {
        int idx = tid + i * 256;
        int r = idx >> 5, c4 = idx & 31;
        float4 h, l;
        tf32_split(Br[i].x, h.x, l.x); tf32_split(Br[i].y, h.y, l.y);
        tf32_split(Br[i].z, h.z, l.z); tf32_split(Br[i].w, h.w, l.w);
        *(float4*)(Bh + r * BP + c4 * 4) = h;
        *(float4*)(Bl + r * BP + c4 * 4) = l;
    }
}

__global__ __launch_bounds__(256, 2) void gemm_tf32x3(
    const float* __restrict__ A, int lda,
    const float* __restrict__ B, int ldb,
    float* __restrict__ C, int ldc,
    int N, int K)
{
    extern __shared__ float sm[];
    float* Ah = sm;
    float* Al = Ah + 128 * AP;
    float* Bh = Al + 128 * AP;
    float* Bl = Bh + 32 * BP;

    const int tid  = threadIdx.x;
    const int row0 = blockIdx.y * 128;
    const int col0 = blockIdx.x * 128;
    const int w    = tid >> 5, lane = tid & 31;
    const int wm   = w & 3, wn = w >> 2;
    const int g    = lane >> 2, t = lane & 3;

    float acc[2][8][4];
#pragma unroll
    for (int mt = 0; mt < 2; ++mt)
#pragma unroll
        for (int nt = 0; nt < 8; ++nt)
#pragma unroll
            for (int i = 0; i < 4; ++i) acc[mt][nt][i] = 0.f;

    float4 Ar[4], Br[4];
    gemm_ldg(A, lda, B, ldb, row0, col0, N, 0, tid, Ar, Br);
    gemm_sts(Ah, Al, Bh, Bl, tid, Ar, Br);
    __syncthreads();

    for (int k0 = 0; k0 < K; k0 += 32) {
        const bool last = (k0 + 32 >= K);
        if (!last) gemm_ldg(A, lda, B, ldb, row0, col0, N, k0 + 32, tid, Ar, Br);

#pragma unroll
        for (int ks = 0; ks < 4; ++ks) {
            const int kk = ks * 8;
            unsigned ah[2][4], al[2][4];
#pragma unroll
            for (int mt = 0; mt < 2; ++mt) {
                int r = wm * 32 + mt * 16 + g;
                ah[mt][0] = __float_as_uint(Ah[(r    ) * AP + kk + t    ]);
                ah[mt][1] = __float_as_uint(Ah[(r + 8) * AP + kk + t    ]);
                ah[mt][2] = __float_as_uint(Ah[(r    ) * AP + kk + t + 4]);
                ah[mt][3] = __float_as_uint(Ah[(r + 8) * AP + kk + t + 4]);
                al[mt][0] = __float_as_uint(Al[(r    ) * AP + kk + t    ]);
                al[mt][1] = __float_as_uint(Al[(r + 8) * AP + kk + t    ]);
                al[mt][2] = __float_as_uint(Al[(r    ) * AP + kk + t + 4]);
                al[mt][3] = __float_as_uint(Al[(r + 8) * AP + kk + t + 4]);
            }
#pragma unroll
            for (int nt = 0; nt < 8; ++nt) {
                int c = wn * 64 + nt * 8 + g;
                unsigned bh[2], bl[2];
                bh[0] = __float_as_uint(Bh[(kk + t    ) * BP + c]);
                bh[1] = __float_as_uint(Bh[(kk + t + 4) * BP + c]);
                bl[0] = __float_as_uint(Bl[(kk + t    ) * BP + c]);
                bl[1] = __float_as_uint(Bl[(kk + t + 4) * BP + c]);
#pragma unroll
                for (int mt = 0; mt < 2; ++mt) {
                    MMA_TF32(acc[mt][nt], ah[mt], bl);   // hi * lo
                    MMA_TF32(acc[mt][nt], al[mt], bh);   // lo * hi
                    MMA_TF32(acc[mt][nt], ah[mt], bh);   // hi * hi
                }
            }
        }
        __syncthreads();
        if (!last) {
            gemm_sts(Ah, Al, Bh, Bl, tid, Ar, Br);
            __syncthreads();
        }
    }

#pragma unroll
    for (int mt = 0; mt < 2; ++mt) {
        int r = row0 + wm * 32 + mt * 16 + g;
#pragma unroll
        for (int nt = 0; nt < 8; ++nt) {
            int c = col0 + wn * 64 + nt * 8 + 2 * t;
            if (c < N) {
                *(float2*)(C + (size_t)r * ldc + c)       = make_float2(acc[mt][nt][0], acc[mt][nt][1]);
                *(float2*)(C + (size_t)(r + 8) * ldc + c) = make_float2(acc[mt][nt][2], acc[mt][nt][3]);
            }
        }
    }
}

// ---------------- RMSNorm ----------------
__global__ __launch_bounds__(256) void rmsnorm_kernel(
    float* __restrict__ x, const float* __restrict__ g, int width, int stride)
{
    __shared__ float red[256];
    float* p = x + (size_t)blockIdx.x * stride;
    float s = 0.f;
    for (int i = threadIdx.x; i < width; i += 256) { float v = p[i]; s += v * v; }
    red[threadIdx.x] = s;
    __syncthreads();
#pragma unroll
    for (int off = 128; off > 0; off >>= 1) {
        if (threadIdx.x < off) red[threadIdx.x] += red[threadIdx.x + off];
        __syncthreads();
    }
    float inv = rsqrtf(red[0] / (float)width + 1e-6f);
    for (int i = threadIdx.x; i < width; i += 256) p[i] = p[i] * inv * g[i];
}

// ---------------- RoPE ----------------
__global__ __launch_bounds__(256) void rope_kernel(
    float* __restrict__ q, const float* __restrict__ ckv, float* __restrict__ kpe,
    const float* __restrict__ cosb, const float* __restrict__ sinb)
{
    int gw   = (blockIdx.x * blockDim.x + threadIdx.x) >> 5;
    int lane = threadIdx.x & 31;
    const int total_q = SEQ * NH;
    if (gw < total_q) {
        int s = gw / NH, h = gw % NH;
        float* x = q + (size_t)s * QW + h * DQK + DN;
        float c  = cosb[s * DR + lane];
        float sn = sinb[s * DR + lane];
        float x0 = x[2 * lane], x1 = x[2 * lane + 1];
        __syncwarp();
        x[lane]      = x0 * c - x1 * sn;
        x[lane + 32] = x1 * c + x0 * sn;
    } else if (gw < total_q + SEQ) {
        int s = gw - total_q;
        const float* x = ckv + (size_t)s * CKVW + KVL;
        float c  = cosb[s * DR + lane];
        float sn = sinb[s * DR + lane];
        float x0 = x[2 * lane], x1 = x[2 * lane + 1];
        kpe[s * DR + lane]      = x0 * c - x1 * sn;
        kpe[s * DR + lane + 32] = x1 * c + x0 * sn;
    }
}

// ---------------- flash attention (causal, fp32, BQ=BK=64) ----------------
#define QK_PAD 196
#define V_PAD  132
#define S_PAD  68
#define ATTN_SMEM_FLOATS (2 * 64 * QK_PAD + 64 * V_PAD + 64 * S_PAD + 3 * 64)
#define ATTN_SMEM_BYTES  (ATTN_SMEM_FLOATS * 4)

__global__ __launch_bounds__(256) void attn_kernel(
    const float* __restrict__ q, const float* __restrict__ kv,
    const float* __restrict__ kpe, float* __restrict__ out)
{
    extern __shared__ float sm[];
    float* Qs = sm;
    float* Ks = Qs + 64 * QK_PAD;
    float* Vs = Ks + 64 * QK_PAD;
    float* Ss = Vs + 64 * V_PAD;
    float* mrow = Ss + 64 * S_PAD;
    float* lrow = mrow + 64;
    float* arow = lrow + 64;

    const int qb  = gridDim.x - 1 - blockIdx.x;
    const int h   = blockIdx.y;
    const int tid = threadIdx.x;
    const int q0  = qb * 64;
    const int rg  = tid >> 4;
    const int cg  = tid & 15;
    const float scale = rsqrtf((float)DQK);

    for (int idx = tid; idx < 64 * DQK; idx += 256) {
        int r = idx / DQK, c = idx % DQK;
        Qs[r * QK_PAD + c] = q[(size_t)(q0 + r) * QW + h * DQK + c];
    }
    if (tid < 64) { mrow[tid] = -1e30f; lrow[tid] = 0.f; }

    float acc[4][8];
#pragma unroll
    for (int i = 0; i < 4; ++i)
#pragma unroll
        for (int j = 0; j < 8; ++j) acc[i][j] = 0.f;

    __syncthreads();

    for (int kb = 0; kb <= qb; ++kb) {
        const int k0 = kb * 64;
        for (int idx = tid; idx < 64 * DQK; idx += 256) {
            int r = idx / DQK, c = idx % DQK;
            float v = (c < DN) ? kv[(size_t)(k0 + r) * KVW + h * (DN + DV) + c]
                               : kpe[(size_t)(k0 + r) * DR + (c - DN)];
            Ks[r * QK_PAD + c] = v;
        }
        for (int idx = tid; idx < 64 * DV; idx += 256) {
            int r = idx / DV, c = idx % DV;
            Vs[r * V_PAD + c] = kv[(size_t)(k0 + r) * KVW + h * (DN + DV) + DN + c];
        }
        __syncthreads();

        float s4[4][4];
#pragma unroll
        for (int i = 0; i < 4; ++i)
#pragma unroll
            for (int j = 0; j < 4; ++j) s4[i][j] = 0.f;

        for (int d = 0; d < DQK; d += 4) {
            float4 a[4], b[4];
#pragma unroll
            for (int i = 0; i < 4; ++i) a[i] = *(const float4*)(Qs + (rg * 4 + i) * QK_PAD + d);
#pragma unroll
            for (int j = 0; j < 4; ++j) b[j] = *(const float4*)(Ks + (cg * 4 + j) * QK_PAD + d);
#pragma unroll
            for (int i = 0; i < 4; ++i)
#pragma unroll
                for (int j = 0; j < 4; ++j)
                    s4[i][j] += a[i].x * b[j].x + a[i].y * b[j].y + a[i].z * b[j].z + a[i].w * b[j].w;
        }
#pragma unroll
        for (int i = 0; i < 4; ++i) {
            int r = rg * 4 + i;
#pragma unroll
            for (int j = 0; j < 4; ++j) {
                int c = cg * 4 + j;
                float v = s4[i][j] * scale;
                if (k0 + c > q0 + r) v = -1e30f;
                Ss[r * S_PAD + c] = v;
            }
        }
        __syncthreads();

        if (tid < 64) {
            float mold = mrow[tid];
            float mnew = mold;
#pragma unroll 8
            for (int j = 0; j < 64; ++j) mnew = fmaxf(mnew, Ss[tid * S_PAD + j]);
            float alpha = __expf(mold - mnew);
            float sum = 0.f;
#pragma unroll 8
            for (int j = 0; j < 64; ++j) {
                float p = __expf(Ss[tid * S_PAD + j] - mnew);
                Ss[tid * S_PAD + j] = p;
                sum += p;
            }
            mrow[tid] = mnew;
            lrow[tid] = lrow[tid] * alpha + sum;
            arow[tid] = alpha;
        }
        __syncthreads();

        float al4[4];
#pragma unroll
        for (int i = 0; i < 4; ++i) al4[i] = arow[rg * 4 + i];
#pragma unroll
        for (int i = 0; i < 4; ++i)
#pragma unroll
            for (int j = 0; j < 8; ++j) acc[i][j] *= al4[i];

        for (int kk = 0; kk < 64; ++kk) {
            float p[4];
#pragma unroll
            for (int i = 0; i < 4; ++i) p[i] = Ss[(rg * 4 + i) * S_PAD + kk];
            float4 v0 = *(const float4*)(Vs + kk * V_PAD + cg * 8);
            float4 v1 = *(const float4*)(Vs + kk * V_PAD + cg * 8 + 4);
            float vv[8] = {v0.x, v0.y, v0.z, v0.w, v1.x, v1.y, v1.z, v1.w};
#pragma unroll
            for (int i = 0; i < 4; ++i)
#pragma unroll
                for (int j = 0; j < 8; ++j) acc[i][j] += p[i] * vv[j];
        }
        __syncthreads();
    }

#pragma unroll
    for (int i = 0; i < 4; ++i) {
        int r = rg * 4 + i;
        float inv = 1.f / lrow[r];
#pragma unroll
        for (int j = 0; j < 8; ++j) {
            out[(size_t)(q0 + r) * AW + h * DV + cg * 8 + j] = acc[i][j] * inv;
        }
    }
}

// ---------------- launch ----------------
extern "C" void kernel_launch(void* const* d_in, const int* in_sizes, int n_in,
                              void* d_out, int out_size)
{
    const float* hidden = (const float*)d_in[0];
    const float* cosb   = (const float*)d_in[1];
    const float* sinb   = (const float*)d_in[2];
    const float* w_qa   = (const float*)d_in[3];
    const float* gm_qa  = (const float*)d_in[4];
    const float* w_qb   = (const float*)d_in[5];
    const float* w_kva  = (const float*)d_in[6];
    const float* gm_kva = (const float*)d_in[7];
    const float* w_kvb  = (const float*)d_in[8];
    const float* w_o    = (const float*)d_in[9];
    float* out = (float*)d_out;

    float *qa, *qq, *ckv, *kv, *kpe, *attn;
    cudaGetSymbolAddress((void**)&qa,   g_qa_s);
    cudaGetSymbolAddress((void**)&qq,   g_q_s);
    cudaGetSymbolAddress((void**)&ckv,  g_ckv_s);
    cudaGetSymbolAddress((void**)&kv,   g_kv_s);
    cudaGetSymbolAddress((void**)&kpe,  g_kpe_s);
    cudaGetSymbolAddress((void**)&attn, g_at_s);

    static bool attr_done = false;
    if (!attr_done) {
        cudaFuncSetAttribute(attn_kernel, cudaFuncAttributeMaxDynamicSharedMemorySize,
                             ATTN_SMEM_BYTES);
        cudaFuncSetAttribute(gemm_tf32x3, cudaFuncAttributeMaxDynamicSharedMemorySize,
                             GEMM_SMEM_BYTES);
        attr_done = true;
    }

    // q_a = hidden @ w_qa   [2048,1536]
    gemm_tf32x3<<<dim3(QL / 128, SEQ / 128), 256, GEMM_SMEM_BYTES>>>(
        hidden, HID, w_qa, QL, qa, QL, QL, HID);
    // ckv = hidden @ w_kva  [2048,576]
    gemm_tf32x3<<<dim3((CKVW + 127) / 128, SEQ / 128), 256, GEMM_SMEM_BYTES>>>(
        hidden, HID, w_kva, CKVW, ckv, CKVW, CKVW, HID);
    // rmsnorms (in place)
    rmsnorm_kernel<<<SEQ, 256>>>(qa, gm_qa, QL, QL);
    rmsnorm_kernel<<<SEQ, 256>>>(ckv, gm_kva, KVL, CKVW);
    // q = qa_n @ w_qb  [2048,3072]
    gemm_tf32x3<<<dim3(QW / 128, SEQ / 128), 256, GEMM_SMEM_BYTES>>>(
        qa, QL, w_qb, QW, qq, QW, QW, QL);
    // kv = ckv_n @ w_kvb  [2048,4096]
    gemm_tf32x3<<<dim3(KVW / 128, SEQ / 128), 256, GEMM_SMEM_BYTES>>>(
        ckv, CKVW, w_kvb, KVW, kv, KVW, KVW, KVL);
    // RoPE
    rope_kernel<<<(SEQ * (NH + 1)) / 8, 256>>>(qq, ckv, kpe, cosb, sinb);
    // attention
    attn_kernel<<<dim3(SEQ / 64, NH), 256, ATTN_SMEM_BYTES>>>(qq, kv, kpe, attn);
    // out = attn @ w_o  [2048,2048]
    gemm_tf32x3<<<dim3(HID / 128, SEQ / 128), 256, GEMM_SMEM_BYTES>>>(
        attn, AW, w_o, HID, out, HID, HID, AW);
}

// round 4
// speedup vs baseline: 1.4977x; 1.2141x over previous
#include <cuda_runtime.h>
#include <cuda_fp16.h>
#include <cuda_bf16.h>
#include <stdint.h>
#include <math.h>

#define SEQ 2048
#define HID 2048
#define NH 16
#define QL 1536
#define KVL 512
#define DN 128
#define DR 64
#define DV 128
#define DQK 192
#define CKVW (KVL + DR)      // 576
#define QW (NH * DQK)        // 3072
#define KVW (NH * (DN + DV)) // 4096
#define AW (NH * DV)         // 2048

// ---------------- scratch ----------------
__device__ float g_qa_s [(size_t)SEQ * QL];
__device__ float g_q_s  [(size_t)SEQ * QW];
__device__ float g_ckv_s[(size_t)SEQ * CKVW];
__device__ float g_kv_s [(size_t)SEQ * KVW];
__device__ float g_kpe_s[(size_t)SEQ * DR];
__device__ float g_at_s [(size_t)SEQ * AW];

// ================= fp16x3 tensor-core GEMM =================
// C[M,N] = A[M,K] @ B[K,N], fp32 in/out, near-fp32 accuracy:
// x = h + l (both fp16); x*y ~ hh + hl + lh (ll term ~eps^2 dropped).
// Block 128x128x32, 256 threads, warp grid 4(M) x 2(N), warp tile 32x64.
// Smem: A [128 rows][64 halves pitch=128B, 8 chunks], swizzle chunk^=(row&7)
//       B [32 rows][128 halves pitch=256B, 16 chunks], swizzle chunk^=(row&7)

#define GA_BYTES (128 * 128)         // one A half-tile (hi or lo): 16384
#define GB_BYTES (32 * 256)          // one B half-tile: 8192
#define GBUF (2 * GA_BYTES + 2 * GB_BYTES)   // 49152 per buffer
#define GEMM_SMEM_BYTES (2 * GBUF)           // 98304

__device__ __forceinline__ uint32_t smem_u32(const void* p) {
    return (uint32_t)__cvta_generic_to_shared(p);
}

#define LDSM_X4(r0, r1, r2, r3, a)                                            \
    asm volatile("ldmatrix.sync.aligned.m8n8.x4.shared.b16 {%0,%1,%2,%3},[%4];" \
                 : "=r"(r0), "=r"(r1), "=r"(r2), "=r"(r3) : "r"(a))
#define LDSM_X4_T(r0, r1, r2, r3, a)                                          \
    asm volatile("ldmatrix.sync.aligned.m8n8.x4.trans.shared.b16 {%0,%1,%2,%3},[%4];" \
                 : "=r"(r0), "=r"(r1), "=r"(r2), "=r"(r3) : "r"(a))

#define MMA16816(d, a0, a1, a2, a3, b0, b1)                                   \
    asm volatile("mma.sync.aligned.m16n8k16.row.col.f32.f16.f16.f32 "         \
                 "{%0,%1,%2,%3},{%4,%5,%6,%7},{%8,%9},{%0,%1,%2,%3};"          \
                 : "+f"(d[0]), "+f"(d[1]), "+f"(d[2]), "+f"(d[3])              \
                 : "r"(a0), "r"(a1), "r"(a2), "r"(a3), "r"(b0), "r"(b1))

__device__ __forceinline__ void split_h2(float x, float y, uint32_t& h, uint32_t& l) {
    __half hx = __float2half_rn(x), hy = __float2half_rn(y);
    __half2 hp = __halves2half2(hx, hy);
    h = *(uint32_t*)&hp;
    __half2 lp = __halves2half2(__float2half_rn(x - __half2float(hx)),
                                __float2half_rn(y - __half2float(hy)));
    l = *(uint32_t*)&lp;
}

__global__ __launch_bounds__(256) void gemm_f16x3(
    const float* __restrict__ A, int lda,
    const float* __restrict__ B, int ldb,
    float* __restrict__ C, int ldc,
    int N, int K)
{
    extern __shared__ char sm[];

    const int tid  = threadIdx.x;
    const int lane = tid & 31, w = tid >> 5;
    const int wm = w & 3, wn = w >> 2;
    const int row0 = blockIdx.y * 128;
    const int col0 = blockIdx.x * 128;

    float acc[2][8][4];
#pragma unroll
    for (int mt = 0; mt < 2; ++mt)
#pragma unroll
        for (int nt = 0; nt < 8; ++nt)
#pragma unroll
            for (int i = 0; i < 4; ++i) acc[mt][nt][i] = 0.f;

    float4 Ar[4], Br[4];

    auto do_ldg = [&](int k0) {
#pragma unroll
        for (int i = 0; i < 4; ++i) {
            int idx = i * 256 + tid;
            int r = idx >> 3, c4 = idx & 7;
            Ar[i] = *(const float4*)(A + (size_t)(row0 + r) * lda + k0 + 4 * c4);
        }
#pragma unroll
        for (int i = 0; i < 4; ++i) {
            int idx = i * 256 + tid;
            int r = idx >> 5, c4 = idx & 31;
            int c = col0 + 4 * c4;
            const float* p = B + (size_t)(k0 + r) * ldb;
            float4 v;
            if (c + 3 < N) v = *(const float4*)(p + c);
            else {
                v.x = (c + 0 < N) ? p[c + 0] : 0.f;
                v.y = (c + 1 < N) ? p[c + 1] : 0.f;
                v.z = (c + 2 < N) ? p[c + 2] : 0.f;
                v.w = (c + 3 < N) ? p[c + 3] : 0.f;
            }
            Br[i] = v;
        }
    };

    auto do_sts = [&](int buf) {
        char* base = sm + buf * GBUF;
#pragma unroll
        for (int i = 0; i < 4; ++i) {
            int idx = i * 256 + tid;
            int r = idx >> 3, c4 = idx & 7;
            uint32_t h0, l0, h1, l1;
            split_h2(Ar[i].x, Ar[i].y, h0, l0);
            split_h2(Ar[i].z, Ar[i].w, h1, l1);
            int off = r * 128 + (((c4 >> 1) ^ (r & 7)) << 4) + ((c4 & 1) << 3);
            *(uint2*)(base + off)            = make_uint2(h0, h1);
            *(uint2*)(base + GA_BYTES + off) = make_uint2(l0, l1);
        }
#pragma unroll
        for (int i = 0; i < 4; ++i) {
            int idx = i * 256 + tid;
            int r = idx >> 5, c4 = idx & 31;
            uint32_t h0, l0, h1, l1;
            split_h2(Br[i].x, Br[i].y, h0, l0);
            split_h2(Br[i].z, Br[i].w, h1, l1);
            int off = 2 * GA_BYTES + r * 256 + (((c4 >> 1) ^ (r & 7)) << 4) + ((c4 & 1) << 3);
            *(uint2*)(base + off)            = make_uint2(h0, h1);
            *(uint2*)(base + GB_BYTES + off) = make_uint2(l0, l1);
        }
    };

    do_ldg(0);
    do_sts(0);
    __syncthreads();

    const int nIter = K >> 5;
    for (int it = 0; it < nIter; ++it) {
        const int buf = it & 1;
        const bool last = (it + 1 == nIter);
        if (!last) do_ldg((it + 1) << 5);

        char* base = sm + buf * GBUF;
#pragma unroll
        for (int kg = 0; kg < 2; ++kg) {
            // A fragments (hi, lo) for both 16-row tiles
            uint32_t ah[2][4], al[2][4];
#pragma unroll
            for (int mt = 0; mt < 2; ++mt) {
                int row = wm * 32 + mt * 16 + (lane & 15);
                int kc = kg * 2 + (lane >> 4);
                uint32_t ad = smem_u32(base + row * 128 + ((kc ^ (row & 7)) << 4));
                LDSM_X4(ah[mt][0], ah[mt][1], ah[mt][2], ah[mt][3], ad);
                LDSM_X4(al[mt][0], al[mt][1], al[mt][2], al[mt][3], ad + GA_BYTES);
            }
            // B fragments (hi, lo), 8 n-tiles via 4 trans-ldmatrix
            uint32_t bh[8][2], bl[8][2];
#pragma unroll
            for (int pr = 0; pr < 4; ++pr) {
                int k = kg * 16 + (lane & 15);
                int nc = wn * 8 + pr * 2 + (lane >> 4);
                uint32_t bd = smem_u32(base + 2 * GA_BYTES + k * 256 + ((nc ^ (k & 7)) << 4));
                uint32_t t0, t1, t2, t3;
                LDSM_X4_T(t0, t1, t2, t3, bd);
                bh[2 * pr][0] = t0; bh[2 * pr][1] = t1;
                bh[2 * pr + 1][0] = t2; bh[2 * pr + 1][1] = t3;
                LDSM_X4_T(t0, t1, t2, t3, bd + GB_BYTES);
                bl[2 * pr][0] = t0; bl[2 * pr][1] = t1;
                bl[2 * pr + 1][0] = t2; bl[2 * pr + 1][1] = t3;
            }
#pragma unroll
            for (int mt = 0; mt < 2; ++mt)
#pragma unroll
                for (int nt = 0; nt < 8; ++nt) {
                    MMA16816(acc[mt][nt], ah[mt][0], ah[mt][1], ah[mt][2], ah[mt][3],
                             bl[nt][0], bl[nt][1]);
                    MMA16816(acc[mt][nt], al[mt][0], al[mt][1], al[mt][2], al[mt][3],
                             bh[nt][0], bh[nt][1]);
                    MMA16816(acc[mt][nt], ah[mt][0], ah[mt][1], ah[mt][2], ah[mt][3],
                             bh[nt][0], bh[nt][1]);
                }
        }
        if (!last) do_sts(buf ^ 1);
        __syncthreads();
    }

    // epilogue: c0,c1 -> row g, cols 2t,2t+1; c2,c3 -> row g+8
    const int g = lane >> 2, t = lane & 3;
#pragma unroll
    for (int mt = 0; mt < 2; ++mt) {
        int r = row0 + wm * 32 + mt * 16 + g;
#pragma unroll
        for (int nt = 0; nt < 8; ++nt) {
            int c = col0 + wn * 64 + nt * 8 + 2 * t;
            if (c < N) {
                *(float2*)(C + (size_t)r * ldc + c)       = make_float2(acc[mt][nt][0], acc[mt][nt][1]);
                *(float2*)(C + (size_t)(r + 8) * ldc + c) = make_float2(acc[mt][nt][2], acc[mt][nt][3]);
            }
        }
    }
}

// ---------------- RMSNorm ----------------
__global__ __launch_bounds__(256) void rmsnorm_kernel(
    float* __restrict__ x, const float* __restrict__ g, int width, int stride)
{
    __shared__ float red[256];
    float* p = x + (size_t)blockIdx.x * stride;
    float s = 0.f;
    for (int i = threadIdx.x; i < width; i += 256) { float v = p[i]; s += v * v; }
    red[threadIdx.x] = s;
    __syncthreads();
#pragma unroll
    for (int off = 128; off > 0; off >>= 1) {
        if (threadIdx.x < off) red[threadIdx.x] += red[threadIdx.x + off];
        __syncthreads();
    }
    float inv = rsqrtf(red[0] / (float)width + 1e-6f);
    for (int i = threadIdx.x; i < width; i += 256) p[i] = p[i] * inv * g[i];
}

// ---------------- RoPE ----------------
__global__ __launch_bounds__(256) void rope_kernel(
    float* __restrict__ q, const float* __restrict__ ckv, float* __restrict__ kpe,
    const float* __restrict__ cosb, const float* __restrict__ sinb)
{
    int gw   = (blockIdx.x * blockDim.x + threadIdx.x) >> 5;
    int lane = threadIdx.x & 31;
    const int total_q = SEQ * NH;
    if (gw < total_q) {
        int s = gw / NH, h = gw % NH;
        float* x = q + (size_t)s * QW + h * DQK + DN;
        float c  = cosb[s * DR + lane];
        float sn = sinb[s * DR + lane];
        float x0 = x[2 * lane], x1 = x[2 * lane + 1];
        __syncwarp();
        x[lane]      = x0 * c - x1 * sn;
        x[lane + 32] = x1 * c + x0 * sn;
    } else if (gw < total_q + SEQ) {
        int s = gw - total_q;
        const float* x = ckv + (size_t)s * CKVW + KVL;
        float c  = cosb[s * DR + lane];
        float sn = sinb[s * DR + lane];
        float x0 = x[2 * lane], x1 = x[2 * lane + 1];
        kpe[s * DR + lane]      = x0 * c - x1 * sn;
        kpe[s * DR + lane + 32] = x1 * c + x0 * sn;
    }
}

// ---------------- flash attention (causal, fp32, BQ=BK=64) ----------------
#define QK_PAD 196
#define V_PAD  132
#define S_PAD  68
#define ATTN_SMEM_FLOATS (2 * 64 * QK_PAD + 64 * V_PAD + 64 * S_PAD + 3 * 64)
#define ATTN_SMEM_BYTES  (ATTN_SMEM_FLOATS * 4)

__global__ __launch_bounds__(256) void attn_kernel(
    const float* __restrict__ q, const float* __restrict__ kv,
    const float* __restrict__ kpe, float* __restrict__ out)
{
    extern __shared__ float smf[];
    float* Qs = smf;
    float* Ks = Qs + 64 * QK_PAD;
    float* Vs = Ks + 64 * QK_PAD;
    float* Ss = Vs + 64 * V_PAD;
    float* mrow = Ss + 64 * S_PAD;
    float* lrow = mrow + 64;
    float* arow = lrow + 64;

    const int qb  = gridDim.x - 1 - blockIdx.x;
    const int h   = blockIdx.y;
    const int tid = threadIdx.x;
    const int q0  = qb * 64;
    const int rg  = tid >> 4;
    const int cg  = tid & 15;
    const float scale = rsqrtf((float)DQK);

    for (int idx = tid; idx < 64 * DQK; idx += 256) {
        int r = idx / DQK, c = idx % DQK;
        Qs[r * QK_PAD + c] = q[(size_t)(q0 + r) * QW + h * DQK + c];
    }
    if (tid < 64) { mrow[tid] = -1e30f; lrow[tid] = 0.f; }

    float acc[4][8];
#pragma unroll
    for (int i = 0; i < 4; ++i)
#pragma unroll
        for (int j = 0; j < 8; ++j) acc[i][j] = 0.f;

    __syncthreads();

    for (int kb = 0; kb <= qb; ++kb) {
        const int k0 = kb * 64;
        for (int idx = tid; idx < 64 * DQK; idx += 256) {
            int r = idx / DQK, c = idx % DQK;
            float v = (c < DN) ? kv[(size_t)(k0 + r) * KVW + h * (DN + DV) + c]
                               : kpe[(size_t)(k0 + r) * DR + (c - DN)];
            Ks[r * QK_PAD + c] = v;
        }
        for (int idx = tid; idx < 64 * DV; idx += 256) {
            int r = idx / DV, c = idx % DV;
            Vs[r * V_PAD + c] = kv[(size_t)(k0 + r) * KVW + h * (DN + DV) + DN + c];
        }
        __syncthreads();

        float s4[4][4];
#pragma unroll
        for (int i = 0; i < 4; ++i)
#pragma unroll
            for (int j = 0; j < 4; ++j) s4[i][j] = 0.f;

        for (int d = 0; d < DQK; d += 4) {
            float4 a[4], b[4];
#pragma unroll
            for (int i = 0; i < 4; ++i) a[i] = *(const float4*)(Qs + (rg * 4 + i) * QK_PAD + d);
#pragma unroll
            for (int j = 0; j < 4; ++j) b[j] = *(const float4*)(Ks + (cg * 4 + j) * QK_PAD + d);
#pragma unroll
            for (int i = 0; i < 4; ++i)
#pragma unroll
                for (int j = 0; j < 4; ++j)
                    s4[i][j] += a[i].x * b[j].x + a[i].y * b[j].y + a[i].z * b[j].z + a[i].w * b[j].w;
        }
#pragma unroll
        for (int i = 0; i < 4; ++i) {
            int r = rg * 4 + i;
#pragma unroll
            for (int j = 0; j < 4; ++j) {
                int c = cg * 4 + j;
                float v = s4[i][j] * scale;
                if (k0 + c > q0 + r) v = -1e30f;
                Ss[r * S_PAD + c] = v;
            }
        }
        __syncthreads();

        if (tid < 64) {
            float mold = mrow[tid];
            float mnew = mold;
#pragma unroll 8
            for (int j = 0; j < 64; ++j) mnew = fmaxf(mnew, Ss[tid * S_PAD + j]);
            float alpha = __expf(mold - mnew);
            float sum = 0.f;
#pragma unroll 8
            for (int j = 0; j < 64; ++j) {
                float p = __expf(Ss[tid * S_PAD + j] - mnew);
                Ss[tid * S_PAD + j] = p;
                sum += p;
            }
            mrow[tid] = mnew;
            lrow[tid] = lrow[tid] * alpha + sum;
            arow[tid] = alpha;
        }
        __syncthreads();

        float al4[4];
#pragma unroll
        for (int i = 0; i < 4; ++i) al4[i] = arow[rg * 4 + i];
#pragma unroll
        for (int i = 0; i < 4; ++i)
#pragma unroll
            for (int j = 0; j < 8; ++j) acc[i][j] *= al4[i];

        for (int kk = 0; kk < 64; ++kk) {
            float p[4];
#pragma unroll
            for (int i = 0; i < 4; ++i) p[i] = Ss[(rg * 4 + i) * S_PAD + kk];
            float4 v0 = *(const float4*)(Vs + kk * V_PAD + cg * 8);
            float4 v1 = *(const float4*)(Vs + kk * V_PAD + cg * 8 + 4);
            float vv[8] = {v0.x, v0.y, v0.z, v0.w, v1.x, v1.y, v1.z, v1.w};
#pragma unroll
            for (int i = 0; i < 4; ++i)
#pragma unroll
                for (int j = 0; j < 8; ++j) acc[i][j] += p[i] * vv[j];
        }
        __syncthreads();
    }

#pragma unroll
    for (int i = 0; i < 4; ++i) {
        int r = rg * 4 + i;
        float inv = 1.f / lrow[r];
#pragma unroll
        for (int j = 0; j < 8; ++j) {
            out[(size_t)(q0 + r) * AW + h * DV + cg * 8 + j] = acc[i][j] * inv;
        }
    }
}

// ---------------- launch ----------------
extern "C" void kernel_launch(void* const* d_in, const int* in_sizes, int n_in,
                              void* d_out, int out_size)
{
    const float* hidden = (const float*)d_in[0];
    const float* cosb   = (const float*)d_in[1];
    const float* sinb   = (const float*)d_in[2];
    const float* w_qa   = (const float*)d_in[3];
    const float* gm_qa  = (const float*)d_in[4];
    const float* w_qb   = (const float*)d_in[5];
    const float* w_kva  = (const float*)d_in[6];
    const float* gm_kva = (const float*)d_in[7];
    const float* w_kvb  = (const float*)d_in[8];
    const float* w_o    = (const float*)d_in[9];
    float* out = (float*)d_out;

    float *qa, *qq, *ckv, *kv, *kpe, *attn;
    cudaGetSymbolAddress((void**)&qa,   g_qa_s);
    cudaGetSymbolAddress((void**)&qq,   g_q_s);
    cudaGetSymbolAddress((void**)&ckv,  g_ckv_s);
    cudaGetSymbolAddress((void**)&kv,   g_kv_s);
    cudaGetSymbolAddress((void**)&kpe,  g_kpe_s);
    cudaGetSymbolAddress((void**)&attn, g_at_s);

    static bool attr_done = false;
    if (!attr_done) {
        cudaFuncSetAttribute(attn_kernel, cudaFuncAttributeMaxDynamicSharedMemorySize,
                             ATTN_SMEM_BYTES);
        cudaFuncSetAttribute(gemm_f16x3, cudaFuncAttributeMaxDynamicSharedMemorySize,
                             GEMM_SMEM_BYTES);
        attr_done = true;
    }

    // q_a = hidden @ w_qa   [2048,1536]
    gemm_f16x3<<<dim3(QL / 128, SEQ / 128), 256, GEMM_SMEM_BYTES>>>(
        hidden, HID, w_qa, QL, qa, QL, QL, HID);
    // ckv = hidden @ w_kva  [2048,576]
    gemm_f16x3<<<dim3((CKVW + 127) / 128, SEQ / 128), 256, GEMM_SMEM_BYTES>>>(
        hidden, HID, w_kva, CKVW, ckv, CKVW, CKVW, HID);
    // rmsnorms (in place)
    rmsnorm_kernel<<<SEQ, 256>>>(qa, gm_qa, QL, QL);
    rmsnorm_kernel<<<SEQ, 256>>>(ckv, gm_kva, KVL, CKVW);
    // q = qa_n @ w_qb  [2048,3072]
    gemm_f16x3<<<dim3(QW / 128, SEQ / 128), 256, GEMM_SMEM_BYTES>>>(
        qa, QL, w_qb, QW, qq, QW, QW, QL);
    // kv = ckv_n @ w_kvb  [2048,4096]
    gemm_f16x3<<<dim3(KVW / 128, SEQ / 128), 256, GEMM_SMEM_BYTES>>>(
        ckv, CKVW, w_kvb, KVW, kv, KVW, KVW, KVL);
    // RoPE
    rope_kernel<<<(SEQ * (NH + 1)) / 8, 256>>>(qq, ckv, kpe, cosb, sinb);
    // attention
    attn_kernel<<<dim3(SEQ / 64, NH), 256, ATTN_SMEM_BYTES>>>(qq, kv, kpe, attn);
    // out = attn @ w_o  [2048,2048]
    gemm_f16x3<<<dim3(HID / 128, SEQ / 128), 256, GEMM_SMEM_BYTES>>>(
        attn, AW, w_o, HID, out, HID, HID, AW);
}

// round 6
// speedup vs baseline: 3.5641x; 2.3798x over previous
#include <cuda_runtime.h>
#include <cuda_fp16.h>
#include <cuda_bf16.h>
#include <stdint.h>
#include <math.h>

#define SEQ 2048
#define HID 2048
#define NH 16
#define QL 1536
#define KVL 512
#define DN 128
#define DR 64
#define DV 128
#define DQK 192
#define CKVW (KVL + DR)      // 576
#define QW (NH * DQK)        // 3072
#define KVW (NH * (DN + DV)) // 4096
#define AW (NH * DV)         // 2048

// ---------------- scratch ----------------
__device__ float g_qa_s [(size_t)SEQ * QL];
__device__ float g_q_s  [(size_t)SEQ * QW];
__device__ float g_ckv_s[(size_t)SEQ * CKVW];
__device__ float g_kv_s [(size_t)SEQ * KVW];
__device__ float g_kpe_s[(size_t)SEQ * DR];
__device__ float g_at_s [(size_t)SEQ * AW];

__device__ __forceinline__ uint32_t smem_u32(const void* p) {
    return (uint32_t)__cvta_generic_to_shared(p);
}

#define LDSM_X4(r0, r1, r2, r3, a)                                            \
    asm volatile("ldmatrix.sync.aligned.m8n8.x4.shared.b16 {%0,%1,%2,%3},[%4];" \
                 : "=r"(r0), "=r"(r1), "=r"(r2), "=r"(r3) : "r"(a))
#define LDSM_X2(r0, r1, a)                                                    \
    asm volatile("ldmatrix.sync.aligned.m8n8.x2.shared.b16 {%0,%1},[%2];"     \
                 : "=r"(r0), "=r"(r1) : "r"(a))
#define LDSM_X4_T(r0, r1, r2, r3, a)                                          \
    asm volatile("ldmatrix.sync.aligned.m8n8.x4.trans.shared.b16 {%0,%1,%2,%3},[%4];" \
                 : "=r"(r0), "=r"(r1), "=r"(r2), "=r"(r3) : "r"(a))

#define MMA16816(d, a0, a1, a2, a3, b0, b1)                                   \
    asm volatile("mma.sync.aligned.m16n8k16.row.col.f32.f16.f16.f32 "         \
                 "{%0,%1,%2,%3},{%4,%5,%6,%7},{%8,%9},{%0,%1,%2,%3};"          \
                 : "+f"(d[0]), "+f"(d[1]), "+f"(d[2]), "+f"(d[3])              \
                 : "r"(a0), "r"(a1), "r"(a2), "r"(a3), "r"(b0), "r"(b1))

__device__ __forceinline__ void split_h2(float x, float y, uint32_t& h, uint32_t& l) {
    __half hx = __float2half_rn(x), hy = __float2half_rn(y);
    __half2 hp = __halves2half2(hx, hy);
    h = *(uint32_t*)&hp;
    __half2 lp = __halves2half2(__float2half_rn(x - __half2float(hx)),
                                __float2half_rn(y - __half2float(hy)));
    l = *(uint32_t*)&lp;
}

// ================= fp16x3 tensor-core GEMM (validated R4) =================
#define GA_BYTES (128 * 128)
#define GB_BYTES (32 * 256)
#define GBUF (2 * GA_BYTES + 2 * GB_BYTES)
#define GEMM_SMEM_BYTES (2 * GBUF)

__global__ __launch_bounds__(256) void gemm_f16x3(
    const float* __restrict__ A, int lda,
    const float* __restrict__ B, int ldb,
    float* __restrict__ C, int ldc,
    int N, int K)
{
    extern __shared__ char sm[];

    const int tid  = threadIdx.x;
    const int lane = tid & 31, w = tid >> 5;
    const int wm = w & 3, wn = w >> 2;
    const int row0 = blockIdx.y * 128;
    const int col0 = blockIdx.x * 128;

    float acc[2][8][4];
#pragma unroll
    for (int mt = 0; mt < 2; ++mt)
#pragma unroll
        for (int nt = 0; nt < 8; ++nt)
#pragma unroll
            for (int i = 0; i < 4; ++i) acc[mt][nt][i] = 0.f;

    float4 Ar[4], Br[4];

    auto do_ldg = [&](int k0) {
#pragma unroll
        for (int i = 0; i < 4; ++i) {
            int idx = i * 256 + tid;
            int r = idx >> 3, c4 = idx & 7;
            Ar[i] = *(const float4*)(A + (size_t)(row0 + r) * lda + k0 + 4 * c4);
        }
#pragma unroll
        for (int i = 0; i < 4; ++i) {
            int idx = i * 256 + tid;
            int r = idx >> 5, c4 = idx & 31;
            int c = col0 + 4 * c4;
            const float* p = B + (size_t)(k0 + r) * ldb;
            float4 v;
            if (c + 3 < N) v = *(const float4*)(p + c);
            else {
                v.x = (c + 0 < N) ? p[c + 0] : 0.f;
                v.y = (c + 1 < N) ? p[c + 1] : 0.f;
                v.z = (c + 2 < N) ? p[c + 2] : 0.f;
                v.w = (c + 3 < N) ? p[c + 3] : 0.f;
            }
            Br[i] = v;
        }
    };

    auto do_sts = [&](int buf) {
        char* base = sm + buf * GBUF;
#pragma unroll
        for (int i = 0; i < 4; ++i) {
            int idx = i * 256 + tid;
            int r = idx >> 3, c4 = idx & 7;
            uint32_t h0, l0, h1, l1;
            split_h2(Ar[i].x, Ar[i].y, h0, l0);
            split_h2(Ar[i].z, Ar[i].w, h1, l1);
            int off = r * 128 + (((c4 >> 1) ^ (r & 7)) << 4) + ((c4 & 1) << 3);
            *(uint2*)(base + off)            = make_uint2(h0, h1);
            *(uint2*)(base + GA_BYTES + off) = make_uint2(l0, l1);
        }
#pragma unroll
        for (int i = 0; i < 4; ++i) {
            int idx = i * 256 + tid;
            int r = idx >> 5, c4 = idx & 31;
            uint32_t h0, l0, h1, l1;
            split_h2(Br[i].x, Br[i].y, h0, l0);
            split_h2(Br[i].z, Br[i].w, h1, l1);
            int off = 2 * GA_BYTES + r * 256 + (((c4 >> 1) ^ (r & 7)) << 4) + ((c4 & 1) << 3);
            *(uint2*)(base + off)            = make_uint2(h0, h1);
            *(uint2*)(base + GB_BYTES + off) = make_uint2(l0, l1);
        }
    };

    do_ldg(0);
    do_sts(0);
    __syncthreads();

    const int nIter = K >> 5;
    for (int it = 0; it < nIter; ++it) {
        const int buf = it & 1;
        const bool last = (it + 1 == nIter);
        if (!last) do_ldg((it + 1) << 5);

        char* base = sm + buf * GBUF;
#pragma unroll
        for (int kg = 0; kg < 2; ++kg) {
            uint32_t ah[2][4], al[2][4];
#pragma unroll
            for (int mt = 0; mt < 2; ++mt) {
                int row = wm * 32 + mt * 16 + (lane & 15);
                int kc = kg * 2 + (lane >> 4);
                uint32_t ad = smem_u32(base + row * 128 + ((kc ^ (row & 7)) << 4));
                LDSM_X4(ah[mt][0], ah[mt][1], ah[mt][2], ah[mt][3], ad);
                LDSM_X4(al[mt][0], al[mt][1], al[mt][2], al[mt][3], ad + GA_BYTES);
            }
            uint32_t bh[8][2], bl[8][2];
#pragma unroll
            for (int pr = 0; pr < 4; ++pr) {
                int k = kg * 16 + (lane & 15);
                int nc = wn * 8 + pr * 2 + (lane >> 4);
                uint32_t bd = smem_u32(base + 2 * GA_BYTES + k * 256 + ((nc ^ (k & 7)) << 4));
                uint32_t t0, t1, t2, t3;
                LDSM_X4_T(t0, t1, t2, t3, bd);
                bh[2 * pr][0] = t0; bh[2 * pr][1] = t1;
                bh[2 * pr + 1][0] = t2; bh[2 * pr + 1][1] = t3;
                LDSM_X4_T(t0, t1, t2, t3, bd + GB_BYTES);
                bl[2 * pr][0] = t0; bl[2 * pr][1] = t1;
                bl[2 * pr + 1][0] = t2; bl[2 * pr + 1][1] = t3;
            }
#pragma unroll
            for (int mt = 0; mt < 2; ++mt)
#pragma unroll
                for (int nt = 0; nt < 8; ++nt) {
                    MMA16816(acc[mt][nt], ah[mt][0], ah[mt][1], ah[mt][2], ah[mt][3],
                             bl[nt][0], bl[nt][1]);
                    MMA16816(acc[mt][nt], al[mt][0], al[mt][1], al[mt][2], al[mt][3],
                             bh[nt][0], bh[nt][1]);
                    MMA16816(acc[mt][nt], ah[mt][0], ah[mt][1], ah[mt][2], ah[mt][3],
                             bh[nt][0], bh[nt][1]);
                }
        }
        if (!last) do_sts(buf ^ 1);
        __syncthreads();
    }

    const int g = lane >> 2, t = lane & 3;
#pragma unroll
    for (int mt = 0; mt < 2; ++mt) {
        int r = row0 + wm * 32 + mt * 16 + g;
#pragma unroll
        for (int nt = 0; nt < 8; ++nt) {
            int c = col0 + wn * 64 + nt * 8 + 2 * t;
            if (c < N) {
                *(float2*)(C + (size_t)r * ldc + c)       = make_float2(acc[mt][nt][0], acc[mt][nt][1]);
                *(float2*)(C + (size_t)(r + 8) * ldc + c) = make_float2(acc[mt][nt][2], acc[mt][nt][3]);
            }
        }
    }
}

// ---------------- RMSNorm ----------------
__global__ __launch_bounds__(256) void rmsnorm_kernel(
    float* __restrict__ x, const float* __restrict__ g, int width, int stride)
{
    __shared__ float red[256];
    float* p = x + (size_t)blockIdx.x * stride;
    float s = 0.f;
    for (int i = threadIdx.x; i < width; i += 256) { float v = p[i]; s += v * v; }
    red[threadIdx.x] = s;
    __syncthreads();
#pragma unroll
    for (int off = 128; off > 0; off >>= 1) {
        if (threadIdx.x < off) red[threadIdx.x] += red[threadIdx.x + off];
        __syncthreads();
    }
    float inv = rsqrtf(red[0] / (float)width + 1e-6f);
    for (int i = threadIdx.x; i < width; i += 256) p[i] = p[i] * inv * g[i];
}

// ---------------- RoPE ----------------
__global__ __launch_bounds__(256) void rope_kernel(
    float* __restrict__ q, const float* __restrict__ ckv, float* __restrict__ kpe,
    const float* __restrict__ cosb, const float* __restrict__ sinb)
{
    int gw   = (blockIdx.x * blockDim.x + threadIdx.x) >> 5;
    int lane = threadIdx.x & 31;
    const int total_q = SEQ * NH;
    if (gw < total_q) {
        int s = gw / NH, h = gw % NH;
        float* x = q + (size_t)s * QW + h * DQK + DN;
        float c  = cosb[s * DR + lane];
        float sn = sinb[s * DR + lane];
        float x0 = x[2 * lane], x1 = x[2 * lane + 1];
        __syncwarp();
        x[lane]      = x0 * c - x1 * sn;
        x[lane + 32] = x1 * c + x0 * sn;
    } else if (gw < total_q + SEQ) {
        int s = gw - total_q;
        const float* x = ckv + (size_t)s * CKVW + KVL;
        float c  = cosb[s * DR + lane];
        float sn = sinb[s * DR + lane];
        float x0 = x[2 * lane], x1 = x[2 * lane + 1];
        kpe[s * DR + lane]      = x0 * c - x1 * sn;
        kpe[s * DR + lane + 32] = x1 * c + x0 * sn;
    }
}

// ============ tensor-core flash attention (fp16x3, BQ=BK=64) ============
// smem byte offsets
#define A_QH 0
#define A_QL 24576
#define A_KH 49152
#define A_KL 73728
#define A_VH 98304
#define A_VL 114688
#define A_PH 131072
#define A_PL 139264
#define A_SS 147456                 // float[64*68]
#define A_MR (A_SS + 17408)
#define A_LR (A_MR + 256)
#define A_AR (A_LR + 256)
#define ATTN_SMEM_BYTES (A_AR + 256)   // 165632

__global__ __launch_bounds__(256) void attn_mma(
    const float* __restrict__ q, const float* __restrict__ kv,
    const float* __restrict__ kpe, float* __restrict__ out)
{
    extern __shared__ char sm[];
    float* Ss   = (float*)(sm + A_SS);
    float* mrow = (float*)(sm + A_MR);
    float* lrow = (float*)(sm + A_LR);
    float* arow = (float*)(sm + A_AR);

    const int tid = threadIdx.x, lane = tid & 31, w = tid >> 5;
    const int wm = w & 3, wn = w >> 2;
    const int qb = gridDim.x - 1 - blockIdx.x;
    const int h  = blockIdx.y;
    const int q0 = qb * 64;
    const float scale = rsqrtf((float)DQK);

    // ---- Q tile fill (64 x 192 fp32 -> fp16 h/l, swizzled, pitch 384B) ----
#pragma unroll
    for (int i = 0; i < 12; ++i) {
        int idx = i * 256 + tid;
        int r = idx / 48, q4 = idx % 48;
        float4 v = *(const float4*)(q + (size_t)(q0 + r) * QW + h * DQK + q4 * 4);
        uint32_t h0, l0, h1, l1;
        split_h2(v.x, v.y, h0, l0);
        split_h2(v.z, v.w, h1, l1);
        int c = q4 >> 1;
        int sc = (c & ~7) | ((c & 7) ^ (r & 7));
        int off = r * 384 + sc * 16 + (q4 & 1) * 8;
        *(uint2*)(sm + A_QH + off) = make_uint2(h0, h1);
        *(uint2*)(sm + A_QL + off) = make_uint2(l0, l1);
    }
    if (tid < 64) { mrow[tid] = -1e30f; lrow[tid] = 0.f; }

    float acc_o[8][4];
#pragma unroll
    for (int nt = 0; nt < 8; ++nt)
#pragma unroll
        for (int i = 0; i < 4; ++i) acc_o[nt][i] = 0.f;

    __syncthreads();

    const int g = lane >> 2, t = lane & 3;
    const int r0 = wm * 16 + g, r1 = r0 + 8;

    for (int kb = 0; kb <= qb; ++kb) {
        const int k0 = kb * 64;

        // ---- K tile fill (64 x 192: kv nope + kpe rope) ----
#pragma unroll
        for (int i = 0; i < 12; ++i) {
            int idx = i * 256 + tid;
            int r = idx / 48, q4 = idx % 48;
            int c0 = q4 * 4;
            float4 v;
            if (c0 < DN) v = *(const float4*)(kv + (size_t)(k0 + r) * KVW + h * (DN + DV) + c0);
            else         v = *(const float4*)(kpe + (size_t)(k0 + r) * DR + (c0 - DN));
            uint32_t h0, l0, h1, l1;
            split_h2(v.x, v.y, h0, l0);
            split_h2(v.z, v.w, h1, l1);
            int c = q4 >> 1;
            int sc = (c & ~7) | ((c & 7) ^ (r & 7));
            int off = r * 384 + sc * 16 + (q4 & 1) * 8;
            *(uint2*)(sm + A_KH + off) = make_uint2(h0, h1);
            *(uint2*)(sm + A_KL + off) = make_uint2(l0, l1);
        }
        // ---- V tile fill (64 x 128, pitch 256B) ----
#pragma unroll
        for (int i = 0; i < 8; ++i) {
            int idx = i * 256 + tid;
            int r = idx >> 5, q4 = idx & 31;
            float4 v = *(const float4*)(kv + (size_t)(k0 + r) * KVW + h * (DN + DV) + DN + q4 * 4);
            uint32_t h0, l0, h1, l1;
            split_h2(v.x, v.y, h0, l0);
            split_h2(v.z, v.w, h1, l1);
            int c = q4 >> 1;
            int sc = (c & 8) | ((c & 7) ^ (r & 7));
            int off = r * 256 + sc * 16 + (q4 & 1) * 8;
            *(uint2*)(sm + A_VH + off) = make_uint2(h0, h1);
            *(uint2*)(sm + A_VL + off) = make_uint2(l0, l1);
        }
        __syncthreads();

        // ---- S = Q @ K^T (fp16x3) ----
        float acc_s[4][4];
#pragma unroll
        for (int nt = 0; nt < 4; ++nt)
#pragma unroll
            for (int i = 0; i < 4; ++i) acc_s[nt][i] = 0.f;

#pragma unroll
        for (int ks = 0; ks < 12; ++ks) {
            uint32_t qh[4], ql[4];
            {
                int row = wm * 16 + (lane & 15);
                int c = 2 * ks + (lane >> 4);
                int sc = (c & ~7) | ((c & 7) ^ (row & 7));
                uint32_t ad = smem_u32(sm + row * 384 + sc * 16);
                LDSM_X4(qh[0], qh[1], qh[2], qh[3], ad + A_QH);
                LDSM_X4(ql[0], ql[1], ql[2], ql[3], ad + (A_QL - A_QH));
            }
#pragma unroll
            for (int nt = 0; nt < 4; ++nt) {
                int krow = wn * 32 + nt * 8 + (lane & 7);
                int kc = 2 * ks + ((lane >> 3) & 1);
                int ksc = (kc & ~7) | ((kc & 7) ^ (krow & 7));
                uint32_t kd = smem_u32(sm + krow * 384 + ksc * 16);
                uint32_t kh0, kh1, kl0, kl1;
                LDSM_X2(kh0, kh1, kd + A_KH);
                LDSM_X2(kl0, kl1, kd + A_KL);
                MMA16816(acc_s[nt], qh[0], qh[1], qh[2], qh[3], kl0, kl1);
                MMA16816(acc_s[nt], ql[0], ql[1], ql[2], ql[3], kh0, kh1);
                MMA16816(acc_s[nt], qh[0], qh[1], qh[2], qh[3], kh0, kh1);
            }
        }

        // ---- scale + causal mask -> Ss ----
#pragma unroll
        for (int nt = 0; nt < 4; ++nt) {
            int col = wn * 32 + nt * 8 + 2 * t;
            float v00 = acc_s[nt][0] * scale, v01 = acc_s[nt][1] * scale;
            float v10 = acc_s[nt][2] * scale, v11 = acc_s[nt][3] * scale;
            if (k0 + col     > q0 + r0) v00 = -1e30f;
            if (k0 + col + 1 > q0 + r0) v01 = -1e30f;
            if (k0 + col     > q0 + r1) v10 = -1e30f;
            if (k0 + col + 1 > q0 + r1) v11 = -1e30f;
            Ss[r0 * 68 + col] = v00; Ss[r0 * 68 + col + 1] = v01;
            Ss[r1 * 68 + col] = v10; Ss[r1 * 68 + col + 1] = v11;
        }
        __syncthreads();

        // ---- online softmax (one thread per row) ----
        if (tid < 64) {
            float mold = mrow[tid];
            float mnew = mold;
#pragma unroll 8
            for (int j = 0; j < 64; ++j) mnew = fmaxf(mnew, Ss[tid * 68 + j]);
            float alpha = __expf(mold - mnew);
            float sum = 0.f;
#pragma unroll 8
            for (int j = 0; j < 64; ++j) {
                float p = __expf(Ss[tid * 68 + j] - mnew);
                Ss[tid * 68 + j] = p;
                sum += p;
            }
            mrow[tid] = mnew;
            lrow[tid] = lrow[tid] * alpha + sum;
            arow[tid] = alpha;
        }
        __syncthreads();

        // ---- P -> fp16 h/l (coalesced, swizzled pitch 128B) ----
#pragma unroll
        for (int i = 0; i < 8; ++i) {
            int idx = i * 256 + tid;
            int r = idx >> 5, p = idx & 31;
            float x = Ss[r * 68 + 2 * p], y = Ss[r * 68 + 2 * p + 1];
            uint32_t hh, ll;
            split_h2(x, y, hh, ll);
            int c = p >> 2;
            int off = r * 128 + ((c ^ (r & 7)) << 4) + (p & 3) * 4;
            *(uint32_t*)(sm + A_PH + off) = hh;
            *(uint32_t*)(sm + A_PL + off) = ll;
        }
        __syncthreads();

        // ---- rescale O, then O += P @ V (fp16x3) ----
        {
            float a0 = arow[r0], a1 = arow[r1];
#pragma unroll
            for (int nt = 0; nt < 8; ++nt) {
                acc_o[nt][0] *= a0; acc_o[nt][1] *= a0;
                acc_o[nt][2] *= a1; acc_o[nt][3] *= a1;
            }
        }
#pragma unroll
        for (int ks = 0; ks < 4; ++ks) {
            uint32_t ph[4], pl[4];
            {
                int row = wm * 16 + (lane & 15);
                int c = 2 * ks + (lane >> 4);
                uint32_t pd = smem_u32(sm + row * 128 + ((c ^ (row & 7)) << 4));
                LDSM_X4(ph[0], ph[1], ph[2], ph[3], pd + A_PH);
                LDSM_X4(pl[0], pl[1], pl[2], pl[3], pd + A_PL);
            }
#pragma unroll
            for (int pr = 0; pr < 4; ++pr) {
                int vk = ks * 16 + (lane & 15);
                int vc = wn * 8 + pr * 2 + (lane >> 4);
                int vsc = (vc & 8) | ((vc & 7) ^ (vk & 7));
                uint32_t vd = smem_u32(sm + vk * 256 + vsc * 16);
                uint32_t b0, b1, b2, b3, c0, c1, c2, c3;
                LDSM_X4_T(b0, b1, b2, b3, vd + A_VH);
                LDSM_X4_T(c0, c1, c2, c3, vd + A_VL);
                int nt0 = 2 * pr, nt1 = 2 * pr + 1;
                MMA16816(acc_o[nt0], ph[0], ph[1], ph[2], ph[3], c0, c1);
                MMA16816(acc_o[nt0], pl[0], pl[1], pl[2], pl[3], b0, b1);
                MMA16816(acc_o[nt0], ph[0], ph[1], ph[2], ph[3], b0, b1);
                MMA16816(acc_o[nt1], ph[0], ph[1], ph[2], ph[3], c2, c3);
                MMA16816(acc_o[nt1], pl[0], pl[1], pl[2], pl[3], b2, b3);
                MMA16816(acc_o[nt1], ph[0], ph[1], ph[2], ph[3], b2, b3);
            }
        }
        __syncthreads();
    }

    // ---- output ----
    float inv0 = 1.f / lrow[r0];
    float inv1 = 1.f / lrow[r1];
#pragma unroll
    for (int nt = 0; nt < 8; ++nt) {
        int col = wn * 64 + nt * 8 + 2 * t;
        *(float2*)(out + (size_t)(q0 + r0) * AW + h * DV + col) =
            make_float2(acc_o[nt][0] * inv0, acc_o[nt][1] * inv0);
        *(float2*)(out + (size_t)(q0 + r1) * AW + h * DV + col) =
            make_float2(acc_o[nt][2] * inv1, acc_o[nt][3] * inv1);
    }
}

// ---------------- launch ----------------
extern "C" void kernel_launch(void* const* d_in, const int* in_sizes, int n_in,
                              void* d_out, int out_size)
{
    const float* hidden = (const float*)d_in[0];
    const float* cosb   = (const float*)d_in[1];
    const float* sinb   = (const float*)d_in[2];
    const float* w_qa   = (const float*)d_in[3];
    const float* gm_qa  = (const float*)d_in[4];
    const float* w_qb   = (const float*)d_in[5];
    const float* w_kva  = (const float*)d_in[6];
    const float* gm_kva = (const float*)d_in[7];
    const float* w_kvb  = (const float*)d_in[8];
    const float* w_o    = (const float*)d_in[9];
    float* out = (float*)d_out;

    float *qa, *qq, *ckv, *kv, *kpe, *attn;
    cudaGetSymbolAddress((void**)&qa,   g_qa_s);
    cudaGetSymbolAddress((void**)&qq,   g_q_s);
    cudaGetSymbolAddress((void**)&ckv,  g_ckv_s);
    cudaGetSymbolAddress((void**)&kv,   g_kv_s);
    cudaGetSymbolAddress((void**)&kpe,  g_kpe_s);
    cudaGetSymbolAddress((void**)&attn, g_at_s);

    static bool attr_done = false;
    if (!attr_done) {
        cudaFuncSetAttribute(attn_mma, cudaFuncAttributeMaxDynamicSharedMemorySize,
                             ATTN_SMEM_BYTES);
        cudaFuncSetAttribute(gemm_f16x3, cudaFuncAttributeMaxDynamicSharedMemorySize,
                             GEMM_SMEM_BYTES);
        attr_done = true;
    }

    // q_a = hidden @ w_qa   [2048,1536]
    gemm_f16x3<<<dim3(QL / 128, SEQ / 128), 256, GEMM_SMEM_BYTES>>>(
        hidden, HID, w_qa, QL, qa, QL, QL, HID);
    // ckv = hidden @ w_kva  [2048,576]
    gemm_f16x3<<<dim3((CKVW + 127) / 128, SEQ / 128), 256, GEMM_SMEM_BYTES>>>(
        hidden, HID, w_kva, CKVW, ckv, CKVW, CKVW, HID);
    // rmsnorms (in place)
    rmsnorm_kernel<<<SEQ, 256>>>(qa, gm_qa, QL, QL);
    rmsnorm_kernel<<<SEQ, 256>>>(ckv, gm_kva, KVL, CKVW);
    // q = qa_n @ w_qb  [2048,3072]
    gemm_f16x3<<<dim3(QW / 128, SEQ / 128), 256, GEMM_SMEM_BYTES>>>(
        qa, QL, w_qb, QW, qq, QW, QW, QL);
    // kv = ckv_n @ w_kvb  [2048,4096]
    gemm_f16x3<<<dim3(KVW / 128, SEQ / 128), 256, GEMM_SMEM_BYTES>>>(
        ckv, CKVW, w_kvb, KVW, kv, KVW, KVW, KVL);
    // RoPE
    rope_kernel<<<(SEQ * (NH + 1)) / 8, 256>>>(qq, ckv, kpe, cosb, sinb);
    // attention (tensor cores)
    attn_mma<<<dim3(SEQ / 64, NH), 256, ATTN_SMEM_BYTES>>>(qq, kv, kpe, attn);
    // out = attn @ w_o  [2048,2048]
    gemm_f16x3<<<dim3(HID / 128, SEQ / 128), 256, GEMM_SMEM_BYTES>>>(
        attn, AW, w_o, HID, out, HID, HID, AW);
}

// round 7
// speedup vs baseline: 4.0209x; 1.1282x over previous
#include <cuda_runtime.h>
#include <cuda_fp16.h>
#include <cuda_bf16.h>
#include <stdint.h>
#include <math.h>

#define SEQ 2048
#define HID 2048
#define NH 16
#define QL 1536
#define KVL 512
#define DN 128
#define DR 64
#define DV 128
#define DQK 192
#define CKVW (KVL + DR)      // 576
#define FW (QL + CKVW)       // 2112 fused qa|ckv width
#define QW (NH * DQK)        // 3072
#define KVW (NH * (DN + DV)) // 4096
#define AW (NH * DV)         // 2048

// ---------------- scratch ----------------
__device__ float g_qc_s [(size_t)SEQ * FW];    // fused qa|ckv activations
__device__ float g_wf_s [(size_t)HID * FW];    // fused w_qa|w_kva weights
__device__ float g_q_s  [(size_t)SEQ * QW];
__device__ float g_kv_s [(size_t)SEQ * KVW];
__device__ float g_kpe_s[(size_t)SEQ * DR];
__device__ float g_at_s [(size_t)SEQ * AW];

__device__ __forceinline__ uint32_t smem_u32(const void* p) {
    return (uint32_t)__cvta_generic_to_shared(p);
}

#define LDSM_X4(r0, r1, r2, r3, a)                                            \
    asm volatile("ldmatrix.sync.aligned.m8n8.x4.shared.b16 {%0,%1,%2,%3},[%4];" \
                 : "=r"(r0), "=r"(r1), "=r"(r2), "=r"(r3) : "r"(a))
#define LDSM_X2(r0, r1, a)                                                    \
    asm volatile("ldmatrix.sync.aligned.m8n8.x2.shared.b16 {%0,%1},[%2];"     \
                 : "=r"(r0), "=r"(r1) : "r"(a))
#define LDSM_X4_T(r0, r1, r2, r3, a)                                          \
    asm volatile("ldmatrix.sync.aligned.m8n8.x4.trans.shared.b16 {%0,%1,%2,%3},[%4];" \
                 : "=r"(r0), "=r"(r1), "=r"(r2), "=r"(r3) : "r"(a))

#define MMA16816(d, a0, a1, a2, a3, b0, b1)                                   \
    asm volatile("mma.sync.aligned.m16n8k16.row.col.f32.f16.f16.f32 "         \
                 "{%0,%1,%2,%3},{%4,%5,%6,%7},{%8,%9},{%0,%1,%2,%3};"          \
                 : "+f"(d[0]), "+f"(d[1]), "+f"(d[2]), "+f"(d[3])              \
                 : "r"(a0), "r"(a1), "r"(a2), "r"(a3), "r"(b0), "r"(b1))

__device__ __forceinline__ void split_h2(float x, float y, uint32_t& h, uint32_t& l) {
    __half hx = __float2half_rn(x), hy = __float2half_rn(y);
    __half2 hp = __halves2half2(hx, hy);
    h = *(uint32_t*)&hp;
    __half2 lp = __halves2half2(__float2half_rn(x - __half2float(hx)),
                                __float2half_rn(y - __half2float(hy)));
    l = *(uint32_t*)&lp;
}

// ---------------- fused weight build: wf = [w_qa | w_kva] ----------------
__global__ __launch_bounds__(256) void wfuse_kernel(
    const float* __restrict__ wqa, const float* __restrict__ wkva,
    float* __restrict__ wf)
{
    int idx = blockIdx.x * 256 + threadIdx.x;           // one float4 each
    int row = idx / (FW / 4), c4 = idx % (FW / 4);
    int col = c4 * 4;
    float4 v;
    if (col < QL) v = *(const float4*)(wqa + (size_t)row * QL + col);
    else          v = *(const float4*)(wkva + (size_t)row * CKVW + (col - QL));
    *(float4*)(wf + (size_t)row * FW + col) = v;
}

// ================= fp16x3 tensor-core GEMM, 3-stage ring =================
#define GA_BYTES (128 * 128)
#define GB_BYTES (32 * 256)
#define GBUF (2 * GA_BYTES + 2 * GB_BYTES)   // 49152
#define GEMM_SMEM_BYTES (3 * GBUF)           // 147456

__global__ __launch_bounds__(256) void gemm_f16x3(
    const float* __restrict__ A, int lda,
    const float* __restrict__ B, int ldb,
    float* __restrict__ C, int ldc,
    int N, int K)
{
    extern __shared__ char sm[];

    const int tid  = threadIdx.x;
    const int lane = tid & 31, w = tid >> 5;
    const int wm = w & 3, wn = w >> 2;
    const int row0 = blockIdx.y * 128;
    const int col0 = blockIdx.x * 128;

    float acc[2][8][4];
#pragma unroll
    for (int mt = 0; mt < 2; ++mt)
#pragma unroll
        for (int nt = 0; nt < 8; ++nt)
#pragma unroll
            for (int i = 0; i < 4; ++i) acc[mt][nt][i] = 0.f;

    float4 Ar[4], Br[4];

    auto do_ldg = [&](int k0) {
#pragma unroll
        for (int i = 0; i < 4; ++i) {
            int idx = i * 256 + tid;
            int r = idx >> 3, c4 = idx & 7;
            Ar[i] = *(const float4*)(A + (size_t)(row0 + r) * lda + k0 + 4 * c4);
        }
#pragma unroll
        for (int i = 0; i < 4; ++i) {
            int idx = i * 256 + tid;
            int r = idx >> 5, c4 = idx & 31;
            int c = col0 + 4 * c4;
            const float* p = B + (size_t)(k0 + r) * ldb;
            float4 v;
            if (c + 3 < N) v = *(const float4*)(p + c);
            else {
                v.x = (c + 0 < N) ? p[c + 0] : 0.f;
                v.y = (c + 1 < N) ? p[c + 1] : 0.f;
                v.z = (c + 2 < N) ? p[c + 2] : 0.f;
                v.w = (c + 3 < N) ? p[c + 3] : 0.f;
            }
            Br[i] = v;
        }
    };

    auto do_sts = [&](int buf) {
        char* base = sm + buf * GBUF;
#pragma unroll
        for (int i = 0; i < 4; ++i) {
            int idx = i * 256 + tid;
            int r = idx >> 3, c4 = idx & 7;
            uint32_t h0, l0, h1, l1;
            split_h2(Ar[i].x, Ar[i].y, h0, l0);
            split_h2(Ar[i].z, Ar[i].w, h1, l1);
            int off = r * 128 + (((c4 >> 1) ^ (r & 7)) << 4) + ((c4 & 1) << 3);
            *(uint2*)(base + off)            = make_uint2(h0, h1);
            *(uint2*)(base + GA_BYTES + off) = make_uint2(l0, l1);
        }
#pragma unroll
        for (int i = 0; i < 4; ++i) {
            int idx = i * 256 + tid;
            int r = idx >> 5, c4 = idx & 31;
            uint32_t h0, l0, h1, l1;
            split_h2(Br[i].x, Br[i].y, h0, l0);
            split_h2(Br[i].z, Br[i].w, h1, l1);
            int off = 2 * GA_BYTES + r * 256 + (((c4 >> 1) ^ (r & 7)) << 4) + ((c4 & 1) << 3);
            *(uint2*)(base + off)            = make_uint2(h0, h1);
            *(uint2*)(base + GB_BYTES + off) = make_uint2(l0, l1);
        }
    };

    const int nIter = K >> 5;
    do_ldg(0);
    do_sts(0);
    if (nIter > 1) do_ldg(32);
    __syncthreads();

    for (int it = 0; it < nIter; ++it) {
        if (it + 1 < nIter) do_sts((it + 1) % 3);
        if (it + 2 < nIter) do_ldg((it + 2) << 5);

        char* base = sm + (it % 3) * GBUF;
#pragma unroll
        for (int kg = 0; kg < 2; ++kg) {
            uint32_t ah[2][4], al[2][4];
#pragma unroll
            for (int mt = 0; mt < 2; ++mt) {
                int row = wm * 32 + mt * 16 + (lane & 15);
                int kc = kg * 2 + (lane >> 4);
                uint32_t ad = smem_u32(base + row * 128 + ((kc ^ (row & 7)) << 4));
                LDSM_X4(ah[mt][0], ah[mt][1], ah[mt][2], ah[mt][3], ad);
                LDSM_X4(al[mt][0], al[mt][1], al[mt][2], al[mt][3], ad + GA_BYTES);
            }
            uint32_t bh[8][2], bl[8][2];
#pragma unroll
            for (int pr = 0; pr < 4; ++pr) {
                int k = kg * 16 + (lane & 15);
                int nc = wn * 8 + pr * 2 + (lane >> 4);
                uint32_t bd = smem_u32(base + 2 * GA_BYTES + k * 256 + ((nc ^ (k & 7)) << 4));
                uint32_t t0, t1, t2, t3;
                LDSM_X4_T(t0, t1, t2, t3, bd);
                bh[2 * pr][0] = t0; bh[2 * pr][1] = t1;
                bh[2 * pr + 1][0] = t2; bh[2 * pr + 1][1] = t3;
                LDSM_X4_T(t0, t1, t2, t3, bd + GB_BYTES);
                bl[2 * pr][0] = t0; bl[2 * pr][1] = t1;
                bl[2 * pr + 1][0] = t2; bl[2 * pr + 1][1] = t3;
            }
#pragma unroll
            for (int mt = 0; mt < 2; ++mt)
#pragma unroll
                for (int nt = 0; nt < 8; ++nt) {
                    MMA16816(acc[mt][nt], ah[mt][0], ah[mt][1], ah[mt][2], ah[mt][3],
                             bl[nt][0], bl[nt][1]);
                    MMA16816(acc[mt][nt], al[mt][0], al[mt][1], al[mt][2], al[mt][3],
                             bh[nt][0], bh[nt][1]);
                    MMA16816(acc[mt][nt], ah[mt][0], ah[mt][1], ah[mt][2], ah[mt][3],
                             bh[nt][0], bh[nt][1]);
                }
        }
        __syncthreads();
    }

    const int g = lane >> 2, t = lane & 3;
#pragma unroll
    for (int mt = 0; mt < 2; ++mt) {
        int r = row0 + wm * 32 + mt * 16 + g;
#pragma unroll
        for (int nt = 0; nt < 8; ++nt) {
            int c = col0 + wn * 64 + nt * 8 + 2 * t;
            if (c < N) {
                *(float2*)(C + (size_t)r * ldc + c)       = make_float2(acc[mt][nt][0], acc[mt][nt][1]);
                *(float2*)(C + (size_t)(r + 8) * ldc + c) = make_float2(acc[mt][nt][2], acc[mt][nt][3]);
            }
        }
    }
}

// ---------------- RMSNorm ----------------
__global__ __launch_bounds__(256) void rmsnorm_kernel(
    float* __restrict__ x, const float* __restrict__ g, int width, int stride)
{
    __shared__ float red[256];
    float* p = x + (size_t)blockIdx.x * stride;
    float s = 0.f;
    for (int i = threadIdx.x; i < width; i += 256) { float v = p[i]; s += v * v; }
    red[threadIdx.x] = s;
    __syncthreads();
#pragma unroll
    for (int off = 128; off > 0; off >>= 1) {
        if (threadIdx.x < off) red[threadIdx.x] += red[threadIdx.x + off];
        __syncthreads();
    }
    float inv = rsqrtf(red[0] / (float)width + 1e-6f);
    for (int i = threadIdx.x; i < width; i += 256) p[i] = p[i] * inv * g[i];
}

// ---------------- RoPE ----------------
__global__ __launch_bounds__(256) void rope_kernel(
    float* __restrict__ q, const float* __restrict__ qc, float* __restrict__ kpe,
    const float* __restrict__ cosb, const float* __restrict__ sinb)
{
    int gw   = (blockIdx.x * blockDim.x + threadIdx.x) >> 5;
    int lane = threadIdx.x & 31;
    const int total_q = SEQ * NH;
    if (gw < total_q) {
        int s = gw / NH, h = gw % NH;
        float* x = q + (size_t)s * QW + h * DQK + DN;
        float c  = cosb[s * DR + lane];
        float sn = sinb[s * DR + lane];
        float x0 = x[2 * lane], x1 = x[2 * lane + 1];
        __syncwarp();
        x[lane]      = x0 * c - x1 * sn;
        x[lane + 32] = x1 * c + x0 * sn;
    } else if (gw < total_q + SEQ) {
        int s = gw - total_q;
        const float* x = qc + (size_t)s * FW + QL + KVL;   // k_pe slice of fused ckv
        float c  = cosb[s * DR + lane];
        float sn = sinb[s * DR + lane];
        float x0 = x[2 * lane], x1 = x[2 * lane + 1];
        kpe[s * DR + lane]      = x0 * c - x1 * sn;
        kpe[s * DR + lane + 32] = x1 * c + x0 * sn;
    }
}

// ============ tensor-core flash attention (fp16x3, BQ=BK=64) ============
#define A_QH 0
#define A_QL 24576
#define A_KH 49152
#define A_KL 73728
#define A_VH 98304
#define A_VL 114688
#define A_PH 131072
#define A_PL 139264
#define A_MR 147456
#define A_LR (A_MR + 256)
#define A_PM (A_LR + 256)           // pmax[64][2]
#define A_PS (A_PM + 512)           // psum[64][2]
#define ATTN_SMEM_BYTES (A_PS + 512)   // 149504

__global__ __launch_bounds__(256) void attn_mma(
    const float* __restrict__ q, const float* __restrict__ kv,
    const float* __restrict__ kpe, float* __restrict__ out)
{
    extern __shared__ char sm[];
    float* mrow = (float*)(sm + A_MR);
    float* lrow = (float*)(sm + A_LR);
    float* pmax = (float*)(sm + A_PM);
    float* psum = (float*)(sm + A_PS);

    const int tid = threadIdx.x, lane = tid & 31, w = tid >> 5;
    const int wm = w & 3, wn = w >> 2;
    const int qb = gridDim.x - 1 - blockIdx.x;
    const int h  = blockIdx.y;
    const int q0 = qb * 64;
    const float scale = rsqrtf((float)DQK);

    // ---- Q tile fill ----
#pragma unroll
    for (int i = 0; i < 12; ++i) {
        int idx = i * 256 + tid;
        int r = idx / 48, q4 = idx % 48;
        float4 v = *(const float4*)(q + (size_t)(q0 + r) * QW + h * DQK + q4 * 4);
        uint32_t h0, l0, h1, l1;
        split_h2(v.x, v.y, h0, l0);
        split_h2(v.z, v.w, h1, l1);
        int c = q4 >> 1;
        int sc = (c & ~7) | ((c & 7) ^ (r & 7));
        int off = r * 384 + sc * 16 + (q4 & 1) * 8;
        *(uint2*)(sm + A_QH + off) = make_uint2(h0, h1);
        *(uint2*)(sm + A_QL + off) = make_uint2(l0, l1);
    }
    if (tid < 64) { mrow[tid] = -1e30f; lrow[tid] = 0.f; }

    float acc_o[8][4];
#pragma unroll
    for (int nt = 0; nt < 8; ++nt)
#pragma unroll
        for (int i = 0; i < 4; ++i) acc_o[nt][i] = 0.f;

    __syncthreads();

    const int g = lane >> 2, t = lane & 3;
    const int r0 = wm * 16 + g, r1 = r0 + 8;

    for (int kb = 0; kb <= qb; ++kb) {
        const int k0 = kb * 64;

        // ---- K tile fill ----
#pragma unroll
        for (int i = 0; i < 12; ++i) {
            int idx = i * 256 + tid;
            int r = idx / 48, q4 = idx % 48;
            int c0 = q4 * 4;
            float4 v;
            if (c0 < DN) v = *(const float4*)(kv + (size_t)(k0 + r) * KVW + h * (DN + DV) + c0);
            else         v = *(const float4*)(kpe + (size_t)(k0 + r) * DR + (c0 - DN));
            uint32_t h0, l0, h1, l1;
            split_h2(v.x, v.y, h0, l0);
            split_h2(v.z, v.w, h1, l1);
            int c = q4 >> 1;
            int sc = (c & ~7) | ((c & 7) ^ (r & 7));
            int off = r * 384 + sc * 16 + (q4 & 1) * 8;
            *(uint2*)(sm + A_KH + off) = make_uint2(h0, h1);
            *(uint2*)(sm + A_KL + off) = make_uint2(l0, l1);
        }
        // ---- V tile fill ----
#pragma unroll
        for (int i = 0; i < 8; ++i) {
            int idx = i * 256 + tid;
            int r = idx >> 5, q4 = idx & 31;
            float4 v = *(const float4*)(kv + (size_t)(k0 + r) * KVW + h * (DN + DV) + DN + q4 * 4);
            uint32_t h0, l0, h1, l1;
            split_h2(v.x, v.y, h0, l0);
            split_h2(v.z, v.w, h1, l1);
            int c = q4 >> 1;
            int sc = (c & 8) | ((c & 7) ^ (r & 7));
            int off = r * 256 + sc * 16 + (q4 & 1) * 8;
            *(uint2*)(sm + A_VH + off) = make_uint2(h0, h1);
            *(uint2*)(sm + A_VL + off) = make_uint2(l0, l1);
        }
        __syncthreads();

        // ---- S = Q @ K^T (fp16x3) ----
        float acc_s[4][4];
#pragma unroll
        for (int nt = 0; nt < 4; ++nt)
#pragma unroll
            for (int i = 0; i < 4; ++i) acc_s[nt][i] = 0.f;

#pragma unroll
        for (int ks = 0; ks < 12; ++ks) {
            uint32_t qh[4], ql[4];
            {
                int row = wm * 16 + (lane & 15);
                int c = 2 * ks + (lane >> 4);
                int sc = (c & ~7) | ((c & 7) ^ (row & 7));
                uint32_t ad = smem_u32(sm + row * 384 + sc * 16);
                LDSM_X4(qh[0], qh[1], qh[2], qh[3], ad + A_QH);
                LDSM_X4(ql[0], ql[1], ql[2], ql[3], ad + (A_QL - A_QH));
            }
#pragma unroll
            for (int nt = 0; nt < 4; ++nt) {
                int krow = wn * 32 + nt * 8 + (lane & 7);
                int kc = 2 * ks + ((lane >> 3) & 1);
                int ksc = (kc & ~7) | ((kc & 7) ^ (krow & 7));
                uint32_t kd = smem_u32(sm + krow * 384 + ksc * 16);
                uint32_t kh0, kh1, kl0, kl1;
                LDSM_X2(kh0, kh1, kd + A_KH);
                LDSM_X2(kl0, kl1, kd + A_KL);
                MMA16816(acc_s[nt], qh[0], qh[1], qh[2], qh[3], kl0, kl1);
                MMA16816(acc_s[nt], ql[0], ql[1], ql[2], ql[3], kh0, kh1);
                MMA16816(acc_s[nt], qh[0], qh[1], qh[2], qh[3], kh0, kh1);
            }
        }

        // ---- scale + causal mask + warp-local max (in regs) ----
        float vm0 = -1e30f, vm1 = -1e30f;
#pragma unroll
        for (int nt = 0; nt < 4; ++nt) {
            int col = wn * 32 + nt * 8 + 2 * t;
            float v00 = acc_s[nt][0] * scale, v01 = acc_s[nt][1] * scale;
            float v10 = acc_s[nt][2] * scale, v11 = acc_s[nt][3] * scale;
            if (k0 + col     > q0 + r0) v00 = -1e30f;
            if (k0 + col + 1 > q0 + r0) v01 = -1e30f;
            if (k0 + col     > q0 + r1) v10 = -1e30f;
            if (k0 + col + 1 > q0 + r1) v11 = -1e30f;
            acc_s[nt][0] = v00; acc_s[nt][1] = v01;
            acc_s[nt][2] = v10; acc_s[nt][3] = v11;
            vm0 = fmaxf(vm0, fmaxf(v00, v01));
            vm1 = fmaxf(vm1, fmaxf(v10, v11));
        }
        vm0 = fmaxf(vm0, __shfl_xor_sync(0xffffffffu, vm0, 1));
        vm0 = fmaxf(vm0, __shfl_xor_sync(0xffffffffu, vm0, 2));
        vm1 = fmaxf(vm1, __shfl_xor_sync(0xffffffffu, vm1, 1));
        vm1 = fmaxf(vm1, __shfl_xor_sync(0xffffffffu, vm1, 2));
        if (t == 0) { pmax[r0 * 2 + wn] = vm0; pmax[r1 * 2 + wn] = vm1; }
        __syncthreads();

        float mold0 = mrow[r0], mold1 = mrow[r1];
        float mnew0 = fmaxf(mold0, fmaxf(pmax[r0 * 2], pmax[r0 * 2 + 1]));
        float mnew1 = fmaxf(mold1, fmaxf(pmax[r1 * 2], pmax[r1 * 2 + 1]));
        float alpha0 = __expf(mold0 - mnew0);
        float alpha1 = __expf(mold1 - mnew1);

        // ---- exp (regs) + P fp16 h/l straight to swizzled smem ----
        float s0 = 0.f, s1 = 0.f;
#pragma unroll
        for (int nt = 0; nt < 4; ++nt) {
            float p00 = __expf(acc_s[nt][0] - mnew0);
            float p01 = __expf(acc_s[nt][1] - mnew0);
            float p10 = __expf(acc_s[nt][2] - mnew1);
            float p11 = __expf(acc_s[nt][3] - mnew1);
            s0 += p00 + p01;
            s1 += p10 + p11;
            uint32_t hh, ll;
            split_h2(p00, p01, hh, ll);
            int off0 = r0 * 128 + (((wn * 4 + nt) ^ (r0 & 7)) << 4) + t * 4;
            *(uint32_t*)(sm + A_PH + off0) = hh;
            *(uint32_t*)(sm + A_PL + off0) = ll;
            split_h2(p10, p11, hh, ll);
            int off1 = r1 * 128 + (((wn * 4 + nt) ^ (r1 & 7)) << 4) + t * 4;
            *(uint32_t*)(sm + A_PH + off1) = hh;
            *(uint32_t*)(sm + A_PL + off1) = ll;
        }
        s0 += __shfl_xor_sync(0xffffffffu, s0, 1);
        s0 += __shfl_xor_sync(0xffffffffu, s0, 2);
        s1 += __shfl_xor_sync(0xffffffffu, s1, 1);
        s1 += __shfl_xor_sync(0xffffffffu, s1, 2);
        if (t == 0) { psum[r0 * 2 + wn] = s0; psum[r1 * 2 + wn] = s1; }
        __syncthreads();

        if (wn == 0 && t == 0) {
            lrow[r0] = lrow[r0] * alpha0 + psum[r0 * 2] + psum[r0 * 2 + 1];
            mrow[r0] = mnew0;
            lrow[r1] = lrow[r1] * alpha1 + psum[r1 * 2] + psum[r1 * 2 + 1];
            mrow[r1] = mnew1;
        }

        // ---- rescale O, then O += P @ V (fp16x3) ----
#pragma unroll
        for (int nt = 0; nt < 8; ++nt) {
            acc_o[nt][0] *= alpha0; acc_o[nt][1] *= alpha0;
            acc_o[nt][2] *= alpha1; acc_o[nt][3] *= alpha1;
        }
#pragma unroll
        for (int ks = 0; ks < 4; ++ks) {
            uint32_t ph[4], pl[4];
            {
                int row = wm * 16 + (lane & 15);
                int c = 2 * ks + (lane >> 4);
                uint32_t pd = smem_u32(sm + row * 128 + ((c ^ (row & 7)) << 4));
                LDSM_X4(ph[0], ph[1], ph[2], ph[3], pd + A_PH);
                LDSM_X4(pl[0], pl[1], pl[2], pl[3], pd + A_PL);
            }
#pragma unroll
            for (int pr = 0; pr < 4; ++pr) {
                int vk = ks * 16 + (lane & 15);
                int vc = wn * 8 + pr * 2 + (lane >> 4);
                int vsc = (vc & 8) | ((vc & 7) ^ (vk & 7));
                uint32_t vd = smem_u32(sm + vk * 256 + vsc * 16);
                uint32_t b0, b1, b2, b3, c0, c1, c2, c3;
                LDSM_X4_T(b0, b1, b2, b3, vd + A_VH);
                LDSM_X4_T(c0, c1, c2, c3, vd + A_VL);
                int nt0 = 2 * pr, nt1 = 2 * pr + 1;
                MMA16816(acc_o[nt0], ph[0], ph[1], ph[2], ph[3], c0, c1);
                MMA16816(acc_o[nt0], pl[0], pl[1], pl[2], pl[3], b0, b1);
                MMA16816(acc_o[nt0], ph[0], ph[1], ph[2], ph[3], b0, b1);
                MMA16816(acc_o[nt1], ph[0], ph[1], ph[2], ph[3], c2, c3);
                MMA16816(acc_o[nt1], pl[0], pl[1], pl[2], pl[3], b2, b3);
                MMA16816(acc_o[nt1], ph[0], ph[1], ph[2], ph[3], b2, b3);
            }
        }
        __syncthreads();
    }

    // ---- output ----
    float inv0 = 1.f / lrow[r0];
    float inv1 = 1.f / lrow[r1];
#pragma unroll
    for (int nt = 0; nt < 8; ++nt) {
        int col = wn * 64 + nt * 8 + 2 * t;
        *(float2*)(out + (size_t)(q0 + r0) * AW + h * DV + col) =
            make_float2(acc_o[nt][0] * inv0, acc_o[nt][1] * inv0);
        *(float2*)(out + (size_t)(q0 + r1) * AW + h * DV + col) =
            make_float2(acc_o[nt][2] * inv1, acc_o[nt][3] * inv1);
    }
}

// ---------------- launch ----------------
extern "C" void kernel_launch(void* const* d_in, const int* in_sizes, int n_in,
                              void* d_out, int out_size)
{
    const float* hidden = (const float*)d_in[0];
    const float* cosb   = (const float*)d_in[1];
    const float* sinb   = (const float*)d_in[2];
    const float* w_qa   = (const float*)d_in[3];
    const float* gm_qa  = (const float*)d_in[4];
    const float* w_qb   = (const float*)d_in[5];
    const float* w_kva  = (const float*)d_in[6];
    const float* gm_kva = (const float*)d_in[7];
    const float* w_kvb  = (const float*)d_in[8];
    const float* w_o    = (const float*)d_in[9];
    float* out = (float*)d_out;

    float *qc, *wf, *qq, *kv, *kpe, *attn;
    cudaGetSymbolAddress((void**)&qc,   g_qc_s);
    cudaGetSymbolAddress((void**)&wf,   g_wf_s);
    cudaGetSymbolAddress((void**)&qq,   g_q_s);
    cudaGetSymbolAddress((void**)&kv,   g_kv_s);
    cudaGetSymbolAddress((void**)&kpe,  g_kpe_s);
    cudaGetSymbolAddress((void**)&attn, g_at_s);

    static bool attr_done = false;
    if (!attr_done) {
        cudaFuncSetAttribute(attn_mma, cudaFuncAttributeMaxDynamicSharedMemorySize,
                             ATTN_SMEM_BYTES);
        cudaFuncSetAttribute(gemm_f16x3, cudaFuncAttributeMaxDynamicSharedMemorySize,
                             GEMM_SMEM_BYTES);
        attr_done = true;
    }

    // fuse w_qa|w_kva -> wf
    wfuse_kernel<<<(HID * FW / 4) / 256, 256>>>(w_qa, w_kva, wf);
    // [qa|ckv] = hidden @ wf   [2048, 2112]  (merged to fix wave quantization)
    gemm_f16x3<<<dim3((FW + 127) / 128, SEQ / 128), 256, GEMM_SMEM_BYTES>>>(
        hidden, HID, wf, FW, qc, FW, FW, HID);
    // rmsnorms (in place on slices)
    rmsnorm_kernel<<<SEQ, 256>>>(qc, gm_qa, QL, FW);
    rmsnorm_kernel<<<SEQ, 256>>>(qc + QL, gm_kva, KVL, FW);
    // q = qa_n @ w_qb  [2048,3072]
    gemm_f16x3<<<dim3(QW / 128, SEQ / 128), 256, GEMM_SMEM_BYTES>>>(
        qc, FW, w_qb, QW, qq, QW, QW, QL);
    // kv = ckv_n @ w_kvb  [2048,4096]
    gemm_f16x3<<<dim3(KVW / 128, SEQ / 128), 256, GEMM_SMEM_BYTES>>>(
        qc + QL, FW, w_kvb, KVW, kv, KVW, KVW, KVL);
    // RoPE
    rope_kernel<<<(SEQ * (NH + 1)) / 8, 256>>>(qq, qc, kpe, cosb, sinb);
    // attention (tensor cores)
    attn_mma<<<dim3(SEQ / 64, NH), 256, ATTN_SMEM_BYTES>>>(qq, kv, kpe, attn);
    // out = attn @ w_o  [2048,2048]
    gemm_f16x3<<<dim3(HID / 128, SEQ / 128), 256, GEMM_SMEM_BYTES>>>(
        attn, AW, w_o, HID, out, HID, HID, AW);
}

// round 8
// speedup vs baseline: 4.1095x; 1.0220x over previous
#include <cuda_runtime.h>
#include <cuda_fp16.h>
#include <cuda_bf16.h>
#include <stdint.h>
#include <math.h>

#define SEQ 2048
#define HID 2048
#define NH 16
#define QL 1536
#define KVL 512
#define DN 128
#define DR 64
#define DV 128
#define DQK 192
#define CKVW (KVL + DR)      // 576
#define FW (QL + CKVW)       // 2112
#define FWP 2176             // FW padded to 128
#define QW (NH * DQK)        // 3072
#define KVW (NH * (DN + DV)) // 4096
#define AW (NH * DV)         // 2048

// ---------------- scratch ----------------
__device__ float  g_qc_s [(size_t)SEQ * FWP];
__device__ float  g_q_s  [(size_t)SEQ * QW];
__device__ __half g_hid_h[(size_t)SEQ * HID],  g_hid_l[(size_t)SEQ * HID];
__device__ __half g_wf_h [(size_t)HID * FWP],  g_wf_l [(size_t)HID * FWP];
__device__ __half g_qb_h [(size_t)QL * QW],    g_qb_l [(size_t)QL * QW];
__device__ __half g_kvb_h[(size_t)KVL * KVW],  g_kvb_l[(size_t)KVL * KVW];
__device__ __half g_o_h  [(size_t)AW * HID],   g_o_l  [(size_t)AW * HID];
__device__ __half g_qan_h[(size_t)SEQ * QL],   g_qan_l[(size_t)SEQ * QL];
__device__ __half g_ckn_h[(size_t)SEQ * KVL],  g_ckn_l[(size_t)SEQ * KVL];
__device__ __half g_qs_h [(size_t)SEQ * QW],   g_qs_l [(size_t)SEQ * QW];
__device__ __half g_kv_h [(size_t)SEQ * KVW],  g_kv_l [(size_t)SEQ * KVW];
__device__ __half g_kpe_h[(size_t)SEQ * DR],   g_kpe_l[(size_t)SEQ * DR];
__device__ __half g_at_h [(size_t)SEQ * AW],   g_at_l [(size_t)SEQ * AW];

__device__ __forceinline__ uint32_t smem_u32(const void* p) {
    return (uint32_t)__cvta_generic_to_shared(p);
}

#define LDSM_X4(r0, r1, r2, r3, a)                                            \
    asm volatile("ldmatrix.sync.aligned.m8n8.x4.shared.b16 {%0,%1,%2,%3},[%4];" \
                 : "=r"(r0), "=r"(r1), "=r"(r2), "=r"(r3) : "r"(a))
#define LDSM_X2(r0, r1, a)                                                    \
    asm volatile("ldmatrix.sync.aligned.m8n8.x2.shared.b16 {%0,%1},[%2];"     \
                 : "=r"(r0), "=r"(r1) : "r"(a))
#define LDSM_X4_T(r0, r1, r2, r3, a)                                          \
    asm volatile("ldmatrix.sync.aligned.m8n8.x4.trans.shared.b16 {%0,%1,%2,%3},[%4];" \
                 : "=r"(r0), "=r"(r1), "=r"(r2), "=r"(r3) : "r"(a))

#define MMA16816(d, a0, a1, a2, a3, b0, b1)                                   \
    asm volatile("mma.sync.aligned.m16n8k16.row.col.f32.f16.f16.f32 "         \
                 "{%0,%1,%2,%3},{%4,%5,%6,%7},{%8,%9},{%0,%1,%2,%3};"          \
                 : "+f"(d[0]), "+f"(d[1]), "+f"(d[2]), "+f"(d[3])              \
                 : "r"(a0), "r"(a1), "r"(a2), "r"(a3), "r"(b0), "r"(b1))

#define CP_ASYNC16(dst, src)                                                  \
    asm volatile("cp.async.cg.shared.global [%0], [%1], 16;" :: "r"(dst), "l"(src))
#define CP_COMMIT() asm volatile("cp.async.commit_group;" ::: "memory")
#define CP_WAIT1()  asm volatile("cp.async.wait_group 1;" ::: "memory")

__device__ __forceinline__ void split_h2(float x, float y, uint32_t& h, uint32_t& l) {
    __half hx = __float2half_rn(x), hy = __float2half_rn(y);
    __half2 hp = __halves2half2(hx, hy);
    h = *(uint32_t*)&hp;
    __half2 lp = __halves2half2(__float2half_rn(x - __half2float(hx)),
                                __float2half_rn(y - __half2float(hy)));
    l = *(uint32_t*)&lp;
}

// ---------------- generic fp32 -> fp16 h/l split ----------------
__global__ __launch_bounds__(256) void fsplit_kernel(
    const float* __restrict__ x, __half* __restrict__ h, __half* __restrict__ l, int n2)
{
    int i = blockIdx.x * 256 + threadIdx.x;
    if (i < n2) {
        float2 v = ((const float2*)x)[i];
        uint32_t hh, ll;
        split_h2(v.x, v.y, hh, ll);
        ((uint32_t*)h)[i] = hh;
        ((uint32_t*)l)[i] = ll;
    }
}

// ---------------- fused [w_qa | w_kva] split (padded to FWP) ----------------
__global__ __launch_bounds__(256) void wfuse_split_kernel(
    const float* __restrict__ wqa, const float* __restrict__ wkva,
    __half* __restrict__ h, __half* __restrict__ l)
{
    int i = blockIdx.x * 256 + threadIdx.x;        // pair index
    int row = i / (FWP / 2), p = i % (FWP / 2);
    int col = 2 * p;
    float x = 0.f, y = 0.f;
    if (col < QL)      { x = wqa[(size_t)row * QL + col];           y = wqa[(size_t)row * QL + col + 1]; }
    else if (col < FW) { x = wkva[(size_t)row * CKVW + col - QL];   y = wkva[(size_t)row * CKVW + col - QL + 1]; }
    uint32_t hh, ll;
    split_h2(x, y, hh, ll);
    ((uint32_t*)h)[(size_t)row * (FWP / 2) + p] = hh;
    ((uint32_t*)l)[(size_t)row * (FWP / 2) + p] = ll;
}

// ---------------- RMSNorm with split fp16 output ----------------
__global__ __launch_bounds__(256) void rmsnorm_split_kernel(
    const float* __restrict__ x, const float* __restrict__ g,
    __half* __restrict__ oh, __half* __restrict__ ol, int width, int stride_in)
{
    __shared__ float red[256];
    const float* p = x + (size_t)blockIdx.x * stride_in;
    float s = 0.f;
    for (int i = threadIdx.x; i < width; i += 256) { float v = p[i]; s += v * v; }
    red[threadIdx.x] = s;
    __syncthreads();
#pragma unroll
    for (int off = 128; off > 0; off >>= 1) {
        if (threadIdx.x < off) red[threadIdx.x] += red[threadIdx.x + off];
        __syncthreads();
    }
    float inv = rsqrtf(red[0] / (float)width + 1e-6f);
    int w2 = width / 2;
    for (int i = threadIdx.x; i < w2; i += 256) {
        float v0 = p[2 * i] * inv * g[2 * i];
        float v1 = p[2 * i + 1] * inv * g[2 * i + 1];
        uint32_t hh, ll;
        split_h2(v0, v1, hh, ll);
        ((uint32_t*)oh)[(size_t)blockIdx.x * w2 + i] = hh;
        ((uint32_t*)ol)[(size_t)blockIdx.x * w2 + i] = ll;
    }
}

// ============ fp16x3 GEMM, pre-split operands, cp.async, K-stage 64 ============
#define G_AT 16384                       // A half-tile: 128 rows x 128B
#define G_BT 16384                       // B half-tile: 64 rows x 256B
#define G_STAGE (2 * G_AT + 2 * G_BT)    // 65536
#define GEMM_SMEM_BYTES (3 * G_STAGE)    // 196608

template <bool SPLIT_OUT>
__global__ __launch_bounds__(256) void gemm_h(
    const __half* __restrict__ Ah, const __half* __restrict__ Al, int lda,
    const __half* __restrict__ Bh, const __half* __restrict__ Bl, int ldb,
    float* __restrict__ C, __half* __restrict__ Ch, __half* __restrict__ Cl,
    int ldc, int N, int K)
{
    extern __shared__ char sm[];
    const uint32_t sbase = smem_u32(sm);

    const int tid  = threadIdx.x;
    const int lane = tid & 31, w = tid >> 5;
    const int wm = w & 3, wn = w >> 2;
    const int row0 = blockIdx.y * 128;
    const int col0 = blockIdx.x * 128;

    float acc[2][8][4];
#pragma unroll
    for (int mt = 0; mt < 2; ++mt)
#pragma unroll
        for (int nt = 0; nt < 8; ++nt)
#pragma unroll
            for (int i = 0; i < 4; ++i) acc[mt][nt][i] = 0.f;

    auto do_cp = [&](int stage, int k0) {
        uint32_t sb = sbase + stage * G_STAGE;
#pragma unroll
        for (int i = 0; i < 4; ++i) {          // A: 1024 chunks per half-tile
            int idx = i * 256 + tid;
            int r = idx >> 3, u = idx & 7;
            uint32_t off = r * 128 + ((u ^ (r & 7)) << 4);
            const __half* sh = Ah + (size_t)(row0 + r) * lda + k0 + u * 8;
            const __half* sl = Al + (size_t)(row0 + r) * lda + k0 + u * 8;
            CP_ASYNC16(sb + off, sh);
            CP_ASYNC16(sb + G_AT + off, sl);
        }
#pragma unroll
        for (int i = 0; i < 4; ++i) {          // B: 1024 chunks per half-tile
            int idx = i * 256 + tid;
            int r = idx >> 4, u = idx & 15;
            uint32_t off = 2 * G_AT + r * 256 + ((u ^ (r & 7)) << 4);
            const __half* sh = Bh + (size_t)(k0 + r) * ldb + col0 + u * 8;
            const __half* sl = Bl + (size_t)(k0 + r) * ldb + col0 + u * 8;
            CP_ASYNC16(sb + off, sh);
            CP_ASYNC16(sb + G_BT + off, sl);
        }
    };

    const int nIter = K >> 6;
    do_cp(0, 0);
    CP_COMMIT();
    if (nIter > 1) do_cp(1, 64);
    CP_COMMIT();

    for (int it = 0; it < nIter; ++it) {
        CP_WAIT1();
        __syncthreads();
        if (it + 2 < nIter) do_cp((it + 2) % 3, (it + 2) << 6);
        CP_COMMIT();

        char* base = sm + (it % 3) * G_STAGE;
#pragma unroll
        for (int kg = 0; kg < 4; ++kg) {
            uint32_t ah[2][4], al[2][4];
#pragma unroll
            for (int mt = 0; mt < 2; ++mt) {
                int row = wm * 32 + mt * 16 + (lane & 15);
                int kc = kg * 2 + (lane >> 4);
                uint32_t ad = smem_u32(base + row * 128 + ((kc ^ (row & 7)) << 4));
                LDSM_X4(ah[mt][0], ah[mt][1], ah[mt][2], ah[mt][3], ad);
                LDSM_X4(al[mt][0], al[mt][1], al[mt][2], al[mt][3], ad + G_AT);
            }
            uint32_t bh[8][2], bl[8][2];
#pragma unroll
            for (int pr = 0; pr < 4; ++pr) {
                int k = kg * 16 + (lane & 15);
                int nc = wn * 8 + pr * 2 + (lane >> 4);
                uint32_t bd = smem_u32(base + 2 * G_AT + k * 256 + ((nc ^ (k & 7)) << 4));
                uint32_t t0, t1, t2, t3;
                LDSM_X4_T(t0, t1, t2, t3, bd);
                bh[2 * pr][0] = t0; bh[2 * pr][1] = t1;
                bh[2 * pr + 1][0] = t2; bh[2 * pr + 1][1] = t3;
                LDSM_X4_T(t0, t1, t2, t3, bd + G_BT);
                bl[2 * pr][0] = t0; bl[2 * pr][1] = t1;
                bl[2 * pr + 1][0] = t2; bl[2 * pr + 1][1] = t3;
            }
#pragma unroll
            for (int mt = 0; mt < 2; ++mt)
#pragma unroll
                for (int nt = 0; nt < 8; ++nt) {
                    MMA16816(acc[mt][nt], ah[mt][0], ah[mt][1], ah[mt][2], ah[mt][3],
                             bl[nt][0], bl[nt][1]);
                    MMA16816(acc[mt][nt], al[mt][0], al[mt][1], al[mt][2], al[mt][3],
                             bh[nt][0], bh[nt][1]);
                    MMA16816(acc[mt][nt], ah[mt][0], ah[mt][1], ah[mt][2], ah[mt][3],
                             bh[nt][0], bh[nt][1]);
                }
        }
    }

    const int g = lane >> 2, t = lane & 3;
#pragma unroll
    for (int mt = 0; mt < 2; ++mt) {
        int r = row0 + wm * 32 + mt * 16 + g;
#pragma unroll
        for (int nt = 0; nt < 8; ++nt) {
            int c = col0 + wn * 64 + nt * 8 + 2 * t;
            if (SPLIT_OUT) {
                uint32_t hh, ll;
                split_h2(acc[mt][nt][0], acc[mt][nt][1], hh, ll);
                *(uint32_t*)(Ch + (size_t)r * ldc + c) = hh;
                *(uint32_t*)(Cl + (size_t)r * ldc + c) = ll;
                split_h2(acc[mt][nt][2], acc[mt][nt][3], hh, ll);
                *(uint32_t*)(Ch + (size_t)(r + 8) * ldc + c) = hh;
                *(uint32_t*)(Cl + (size_t)(r + 8) * ldc + c) = ll;
            } else if (c < N) {
                *(float2*)(C + (size_t)r * ldc + c)       = make_float2(acc[mt][nt][0], acc[mt][nt][1]);
                *(float2*)(C + (size_t)(r + 8) * ldc + c) = make_float2(acc[mt][nt][2], acc[mt][nt][3]);
            }
        }
    }
}

// ---------------- RoPE (q fp32 in place; kpe -> split fp16) ----------------
__global__ __launch_bounds__(256) void rope_kernel(
    float* __restrict__ q, const float* __restrict__ qc,
    __half* __restrict__ kpeh, __half* __restrict__ kpel,
    const float* __restrict__ cosb, const float* __restrict__ sinb)
{
    int gw   = (blockIdx.x * blockDim.x + threadIdx.x) >> 5;
    int lane = threadIdx.x & 31;
    const int total_q = SEQ * NH;
    if (gw < total_q) {
        int s = gw / NH, h = gw % NH;
        float* x = q + (size_t)s * QW + h * DQK + DN;
        float c  = cosb[s * DR + lane];
        float sn = sinb[s * DR + lane];
        float x0 = x[2 * lane], x1 = x[2 * lane + 1];
        __syncwarp();
        x[lane]      = x0 * c - x1 * sn;
        x[lane + 32] = x1 * c + x0 * sn;
    } else if (gw < total_q + SEQ) {
        int s = gw - total_q;
        const float* x = qc + (size_t)s * FWP + QL + KVL;
        float c  = cosb[s * DR + lane];
        float sn = sinb[s * DR + lane];
        float x0 = x[2 * lane], x1 = x[2 * lane + 1];
        float y0 = x0 * c - x1 * sn;
        float y1 = x1 * c + x0 * sn;
        __half h0 = __float2half_rn(y0);
        __half h1 = __float2half_rn(y1);
        kpeh[s * DR + lane]      = h0;
        kpel[s * DR + lane]      = __float2half_rn(y0 - __half2float(h0));
        kpeh[s * DR + lane + 32] = h1;
        kpel[s * DR + lane + 32] = __float2half_rn(y1 - __half2float(h1));
    }
}

// ============ tensor-core flash attention (pre-split fp16 inputs) ============
#define A_QH 0
#define A_QL 24576
#define A_KH 49152
#define A_KL 73728
#define A_VH 98304
#define A_VL 114688
#define A_PH 131072
#define A_PL 139264
#define A_MR 147456
#define A_LR (A_MR + 256)
#define A_PM (A_LR + 256)
#define A_PS (A_PM + 512)
#define ATTN_SMEM_BYTES (A_PS + 512)   // 149504

__global__ __launch_bounds__(256) void attn_mma(
    const __half* __restrict__ qh, const __half* __restrict__ ql,
    const __half* __restrict__ kvh, const __half* __restrict__ kvl,
    const __half* __restrict__ kpeh, const __half* __restrict__ kpel,
    __half* __restrict__ ath, __half* __restrict__ atl)
{
    extern __shared__ char sm[];
    float* mrow = (float*)(sm + A_MR);
    float* lrow = (float*)(sm + A_LR);
    float* pmax = (float*)(sm + A_PM);
    float* psum = (float*)(sm + A_PS);

    const int tid = threadIdx.x, lane = tid & 31, w = tid >> 5;
    const int wm = w & 3, wn = w >> 2;
    const int qb = gridDim.x - 1 - blockIdx.x;
    const int hh_ = blockIdx.y;
    const int q0 = qb * 64;
    const float scale = rsqrtf((float)DQK);

    // ---- Q tile fill (copy pre-split) ----
#pragma unroll
    for (int i = 0; i < 6; ++i) {
        int idx = i * 256 + tid;
        int r = idx / 24, u = idx % 24;
        int sc = u ^ (r & 7);
        int off = r * 384 + sc * 16;
        const size_t go = (size_t)(q0 + r) * QW + hh_ * DQK + u * 8;
        *(uint4*)(sm + A_QH + off) = *(const uint4*)(qh + go);
        *(uint4*)(sm + A_QL + off) = *(const uint4*)(ql + go);
    }
    if (tid < 64) { mrow[tid] = -1e30f; lrow[tid] = 0.f; }

    float acc_o[8][4];
#pragma unroll
    for (int nt = 0; nt < 8; ++nt)
#pragma unroll
        for (int i = 0; i < 4; ++i) acc_o[nt][i] = 0.f;

    __syncthreads();

    const int g = lane >> 2, t = lane & 3;
    const int r0 = wm * 16 + g, r1 = r0 + 8;

    for (int kb = 0; kb <= qb; ++kb) {
        const int k0 = kb * 64;

        // ---- K tile fill ----
#pragma unroll
        for (int i = 0; i < 6; ++i) {
            int idx = i * 256 + tid;
            int r = idx / 24, u = idx % 24;
            int sc = u ^ (r & 7);
            int off = r * 384 + sc * 16;
            if (u < 16) {
                const size_t go = (size_t)(k0 + r) * KVW + hh_ * (DN + DV) + u * 8;
                *(uint4*)(sm + A_KH + off) = *(const uint4*)(kvh + go);
                *(uint4*)(sm + A_KL + off) = *(const uint4*)(kvl + go);
            } else {
                const size_t go = (size_t)(k0 + r) * DR + (u - 16) * 8;
                *(uint4*)(sm + A_KH + off) = *(const uint4*)(kpeh + go);
                *(uint4*)(sm + A_KL + off) = *(const uint4*)(kpel + go);
            }
        }
        // ---- V tile fill ----
#pragma unroll
        for (int i = 0; i < 4; ++i) {
            int idx = i * 256 + tid;
            int r = idx >> 4, u = idx & 15;
            int sc = u ^ (r & 7);
            int off = r * 256 + sc * 16;
            const size_t go = (size_t)(k0 + r) * KVW + hh_ * (DN + DV) + DN + u * 8;
            *(uint4*)(sm + A_VH + off) = *(const uint4*)(kvh + go);
            *(uint4*)(sm + A_VL + off) = *(const uint4*)(kvl + go);
        }
        __syncthreads();

        // ---- S = Q @ K^T (fp16x3) ----
        float acc_s[4][4];
#pragma unroll
        for (int nt = 0; nt < 4; ++nt)
#pragma unroll
            for (int i = 0; i < 4; ++i) acc_s[nt][i] = 0.f;

#pragma unroll
        for (int ks = 0; ks < 12; ++ks) {
            uint32_t qfh[4], qfl[4];
            {
                int row = wm * 16 + (lane & 15);
                int c = 2 * ks + (lane >> 4);
                int sc = c ^ (row & 7);
                uint32_t ad = smem_u32(sm + row * 384 + sc * 16);
                LDSM_X4(qfh[0], qfh[1], qfh[2], qfh[3], ad + A_QH);
                LDSM_X4(qfl[0], qfl[1], qfl[2], qfl[3], ad + (A_QL - A_QH));
            }
#pragma unroll
            for (int nt = 0; nt < 4; ++nt) {
                int krow = wn * 32 + nt * 8 + (lane & 7);
                int kc = 2 * ks + ((lane >> 3) & 1);
                int ksc = kc ^ (krow & 7);
                uint32_t kd = smem_u32(sm + krow * 384 + ksc * 16);
                uint32_t kh0, kh1, kl0, kl1;
                LDSM_X2(kh0, kh1, kd + A_KH);
                LDSM_X2(kl0, kl1, kd + A_KL);
                MMA16816(acc_s[nt], qfh[0], qfh[1], qfh[2], qfh[3], kl0, kl1);
                MMA16816(acc_s[nt], qfl[0], qfl[1], qfl[2], qfl[3], kh0, kh1);
                MMA16816(acc_s[nt], qfh[0], qfh[1], qfh[2], qfh[3], kh0, kh1);
            }
        }

        // ---- scale + causal mask + warp-local max ----
        float vm0 = -1e30f, vm1 = -1e30f;
#pragma unroll
        for (int nt = 0; nt < 4; ++nt) {
            int col = wn * 32 + nt * 8 + 2 * t;
            float v00 = acc_s[nt][0] * scale, v01 = acc_s[nt][1] * scale;
            float v10 = acc_s[nt][2] * scale, v11 = acc_s[nt][3] * scale;
            if (k0 + col     > q0 + r0) v00 = -1e30f;
            if (k0 + col + 1 > q0 + r0) v01 = -1e30f;
            if (k0 + col     > q0 + r1) v10 = -1e30f;
            if (k0 + col + 1 > q0 + r1) v11 = -1e30f;
            acc_s[nt][0] = v00; acc_s[nt][1] = v01;
            acc_s[nt][2] = v10; acc_s[nt][3] = v11;
            vm0 = fmaxf(vm0, fmaxf(v00, v01));
            vm1 = fmaxf(vm1, fmaxf(v10, v11));
        }
        vm0 = fmaxf(vm0, __shfl_xor_sync(0xffffffffu, vm0, 1));
        vm0 = fmaxf(vm0, __shfl_xor_sync(0xffffffffu, vm0, 2));
        vm1 = fmaxf(vm1, __shfl_xor_sync(0xffffffffu, vm1, 1));
        vm1 = fmaxf(vm1, __shfl_xor_sync(0xffffffffu, vm1, 2));
        if (t == 0) { pmax[r0 * 2 + wn] = vm0; pmax[r1 * 2 + wn] = vm1; }
        __syncthreads();

        float mold0 = mrow[r0], mold1 = mrow[r1];
        float mnew0 = fmaxf(mold0, fmaxf(pmax[r0 * 2], pmax[r0 * 2 + 1]));
        float mnew1 = fmaxf(mold1, fmaxf(pmax[r1 * 2], pmax[r1 * 2 + 1]));
        float alpha0 = __expf(mold0 - mnew0);
        float alpha1 = __expf(mold1 - mnew1);

        // ---- exp + P fp16 h/l straight to swizzled smem ----
        float s0 = 0.f, s1 = 0.f;
#pragma unroll
        for (int nt = 0; nt < 4; ++nt) {
            float p00 = __expf(acc_s[nt][0] - mnew0);
            float p01 = __expf(acc_s[nt][1] - mnew0);
            float p10 = __expf(acc_s[nt][2] - mnew1);
            float p11 = __expf(acc_s[nt][3] - mnew1);
            s0 += p00 + p01;
            s1 += p10 + p11;
            uint32_t hh, ll;
            split_h2(p00, p01, hh, ll);
            int off0 = r0 * 128 + (((wn * 4 + nt) ^ (r0 & 7)) << 4) + t * 4;
            *(uint32_t*)(sm + A_PH + off0) = hh;
            *(uint32_t*)(sm + A_PL + off0) = ll;
            split_h2(p10, p11, hh, ll);
            int off1 = r1 * 128 + (((wn * 4 + nt) ^ (r1 & 7)) << 4) + t * 4;
            *(uint32_t*)(sm + A_PH + off1) = hh;
            *(uint32_t*)(sm + A_PL + off1) = ll;
        }
        s0 += __shfl_xor_sync(0xffffffffu, s0, 1);
        s0 += __shfl_xor_sync(0xffffffffu, s0, 2);
        s1 += __shfl_xor_sync(0xffffffffu, s1, 1);
        s1 += __shfl_xor_sync(0xffffffffu, s1, 2);
        if (t == 0) { psum[r0 * 2 + wn] = s0; psum[r1 * 2 + wn] = s1; }
        __syncthreads();

        if (wn == 0 && t == 0) {
            lrow[r0] = lrow[r0] * alpha0 + psum[r0 * 2] + psum[r0 * 2 + 1];
            mrow[r0] = mnew0;
            lrow[r1] = lrow[r1] * alpha1 + psum[r1 * 2] + psum[r1 * 2 + 1];
            mrow[r1] = mnew1;
        }

        // ---- rescale O, then O += P @ V (fp16x3) ----
#pragma unroll
        for (int nt = 0; nt < 8; ++nt) {
            acc_o[nt][0] *= alpha0; acc_o[nt][1] *= alpha0;
            acc_o[nt][2] *= alpha1; acc_o[nt][3] *= alpha1;
        }
#pragma unroll
        for (int ks = 0; ks < 4; ++ks) {
            uint32_t ph[4], pl[4];
            {
                int row = wm * 16 + (lane & 15);
                int c = 2 * ks + (lane >> 4);
                uint32_t pd = smem_u32(sm + row * 128 + ((c ^ (row & 7)) << 4));
                LDSM_X4(ph[0], ph[1], ph[2], ph[3], pd + A_PH);
                LDSM_X4(pl[0], pl[1], pl[2], pl[3], pd + A_PL);
            }
#pragma unroll
            for (int pr = 0; pr < 4; ++pr) {
                int vk = ks * 16 + (lane & 15);
                int vc = wn * 8 + pr * 2 + (lane >> 4);
                int vsc = vc ^ (vk & 7);
                uint32_t vd = smem_u32(sm + vk * 256 + vsc * 16);
                uint32_t b0, b1, b2, b3, c0, c1, c2, c3;
                LDSM_X4_T(b0, b1, b2, b3, vd + A_VH);
                LDSM_X4_T(c0, c1, c2, c3, vd + A_VL);
                int nt0 = 2 * pr, nt1 = 2 * pr + 1;
                MMA16816(acc_o[nt0], ph[0], ph[1], ph[2], ph[3], c0, c1);
                MMA16816(acc_o[nt0], pl[0], pl[1], pl[2], pl[3], b0, b1);
                MMA16816(acc_o[nt0], ph[0], ph[1], ph[2], ph[3], b0, b1);
                MMA16816(acc_o[nt1], ph[0], ph[1], ph[2], ph[3], c2, c3);
                MMA16816(acc_o[nt1], pl[0], pl[1], pl[2], pl[3], b2, b3);
                MMA16816(acc_o[nt1], ph[0], ph[1], ph[2], ph[3], b2, b3);
            }
        }
        __syncthreads();
    }

    // ---- output: split fp16 h/l directly ----
    float inv0 = 1.f / lrow[r0];
    float inv1 = 1.f / lrow[r1];
#pragma unroll
    for (int nt = 0; nt < 8; ++nt) {
        int col = wn * 64 + nt * 8 + 2 * t;
        uint32_t hh, ll;
        split_h2(acc_o[nt][0] * inv0, acc_o[nt][1] * inv0, hh, ll);
        *(uint32_t*)(ath + (size_t)(q0 + r0) * AW + hh_ * DV + col) = hh;
        *(uint32_t*)(atl + (size_t)(q0 + r0) * AW + hh_ * DV + col) = ll;
        split_h2(acc_o[nt][2] * inv1, acc_o[nt][3] * inv1, hh, ll);
        *(uint32_t*)(ath + (size_t)(q0 + r1) * AW + hh_ * DV + col) = hh;
        *(uint32_t*)(atl + (size_t)(q0 + r1) * AW + hh_ * DV + col) = ll;
    }
}

// ---------------- launch ----------------
extern "C" void kernel_launch(void* const* d_in, const int* in_sizes, int n_in,
                              void* d_out, int out_size)
{
    const float* hidden = (const float*)d_in[0];
    const float* cosb   = (const float*)d_in[1];
    const float* sinb   = (const float*)d_in[2];
    const float* w_qa   = (const float*)d_in[3];
    const float* gm_qa  = (const float*)d_in[4];
    const float* w_qb   = (const float*)d_in[5];
    const float* w_kva  = (const float*)d_in[6];
    const float* gm_kva = (const float*)d_in[7];
    const float* w_kvb  = (const float*)d_in[8];
    const float* w_o    = (const float*)d_in[9];
    float* out = (float*)d_out;

    float *qc, *qf;
    __half *hidh, *hidl, *wfh, *wfl, *qbh, *qbl, *kvbh, *kvbl, *oh, *ol;
    __half *qanh, *qanl, *cknh, *cknl, *qsh, *qsl, *kvh, *kvl, *kpeh, *kpel, *ath, *atl;
    cudaGetSymbolAddress((void**)&qc,   g_qc_s);
    cudaGetSymbolAddress((void**)&qf,   g_q_s);
    cudaGetSymbolAddress((void**)&hidh, g_hid_h); cudaGetSymbolAddress((void**)&hidl, g_hid_l);
    cudaGetSymbolAddress((void**)&wfh,  g_wf_h);  cudaGetSymbolAddress((void**)&wfl,  g_wf_l);
    cudaGetSymbolAddress((void**)&qbh,  g_qb_h);  cudaGetSymbolAddress((void**)&qbl,  g_qb_l);
    cudaGetSymbolAddress((void**)&kvbh, g_kvb_h); cudaGetSymbolAddress((void**)&kvbl, g_kvb_l);
    cudaGetSymbolAddress((void**)&oh,   g_o_h);   cudaGetSymbolAddress((void**)&ol,   g_o_l);
    cudaGetSymbolAddress((void**)&qanh, g_qan_h); cudaGetSymbolAddress((void**)&qanl, g_qan_l);
    cudaGetSymbolAddress((void**)&cknh, g_ckn_h); cudaGetSymbolAddress((void**)&cknl, g_ckn_l);
    cudaGetSymbolAddress((void**)&qsh,  g_qs_h);  cudaGetSymbolAddress((void**)&qsl,  g_qs_l);
    cudaGetSymbolAddress((void**)&kvh,  g_kv_h);  cudaGetSymbolAddress((void**)&kvl,  g_kv_l);
    cudaGetSymbolAddress((void**)&kpeh, g_kpe_h); cudaGetSymbolAddress((void**)&kpel, g_kpe_l);
    cudaGetSymbolAddress((void**)&ath,  g_at_h);  cudaGetSymbolAddress((void**)&atl,  g_at_l);

    static bool attr_done = false;
    if (!attr_done) {
        cudaFuncSetAttribute(attn_mma, cudaFuncAttributeMaxDynamicSharedMemorySize,
                             ATTN_SMEM_BYTES);
        cudaFuncSetAttribute(gemm_h<false>, cudaFuncAttributeMaxDynamicSharedMemorySize,
                             GEMM_SMEM_BYTES);
        cudaFuncSetAttribute(gemm_h<true>, cudaFuncAttributeMaxDynamicSharedMemorySize,
                             GEMM_SMEM_BYTES);
        attr_done = true;
    }

    // splits (bandwidth-bound)
    fsplit_kernel<<<(SEQ * HID / 2) / 256, 256>>>(hidden, hidh, hidl, SEQ * HID / 2);
    wfuse_split_kernel<<<(HID * FWP / 2) / 256, 256>>>(w_qa, w_kva, wfh, wfl);
    fsplit_kernel<<<(QL * QW / 2) / 256, 256>>>(w_qb, qbh, qbl, QL * QW / 2);
    fsplit_kernel<<<(KVL * KVW / 2) / 256, 256>>>(w_kvb, kvbh, kvbl, KVL * KVW / 2);
    fsplit_kernel<<<(AW * HID / 2) / 256, 256>>>(w_o, oh, ol, AW * HID / 2);

    // [qa|ckv] = hidden @ wf  (fp32 out)
    gemm_h<false><<<dim3(FWP / 128, SEQ / 128), 256, GEMM_SMEM_BYTES>>>(
        hidh, hidl, HID, wfh, wfl, FWP, qc, ((__half*)0), ((__half*)0), FWP, FW, HID);
    // rmsnorm + split
    rmsnorm_split_kernel<<<SEQ, 256>>>(qc, gm_qa, qanh, qanl, QL, FWP);
    rmsnorm_split_kernel<<<SEQ, 256>>>(qc + QL, gm_kva, cknh, cknl, KVL, FWP);
    // q = qa_n @ w_qb (fp32 out, rope needs it)
    gemm_h<false><<<dim3(QW / 128, SEQ / 128), 256, GEMM_SMEM_BYTES>>>(
        qanh, qanl, QL, qbh, qbl, QW, qf, ((__half*)0), ((__half*)0), QW, QW, QL);
    // kv = ckv_n @ w_kvb (split fp16 out)
    gemm_h<true><<<dim3(KVW / 128, SEQ / 128), 256, GEMM_SMEM_BYTES>>>(
        cknh, cknl, KVL, kvbh, kvbl, KVW, ((float*)0), kvh, kvl, KVW, KVW, KVL);
    // RoPE (q fp32 in place; kpe split out)
    rope_kernel<<<(SEQ * (NH + 1)) / 8, 256>>>(qf, qc, kpeh, kpel, cosb, sinb);
    // split q
    fsplit_kernel<<<(SEQ * QW / 2) / 256, 256>>>(qf, qsh, qsl, SEQ * QW / 2);
    // attention (split in, split out)
    attn_mma<<<dim3(SEQ / 64, NH), 256, ATTN_SMEM_BYTES>>>(
        qsh, qsl, kvh, kvl, kpeh, kpel, ath, atl);
    // out = attn @ w_o (fp32 out)
    gemm_h<false><<<dim3(HID / 128, SEQ / 128), 256, GEMM_SMEM_BYTES>>>(
        ath, atl, AW, oh, ol, HID, out, ((__half*)0), ((__half*)0), HID, HID, AW);
}

// round 9
// speedup vs baseline: 4.5821x; 1.1150x over previous
#include <cuda_runtime.h>
#include <cuda_fp16.h>
#include <cuda_bf16.h>
#include <stdint.h>
#include <math.h>

#define SEQ 2048
#define HID 2048
#define NH 16
#define QL 1536
#define KVL 512
#define DN 128
#define DR 64
#define DV 128
#define DQK 192
#define CKVW (KVL + DR)      // 576
#define FW (QL + CKVW)       // 2112
#define FWP 2176             // FW padded to 128
#define QW (NH * DQK)        // 3072
#define KVW (NH * (DN + DV)) // 4096
#define AW (NH * DV)         // 2048

// ---------------- scratch ----------------
__device__ float  g_qc_s [(size_t)SEQ * FWP];
__device__ float  g_q_s  [(size_t)SEQ * QW];
__device__ __half g_hid_h[(size_t)SEQ * HID];
__device__ __half g_wf_h [(size_t)HID * FWP],  g_wf_l [(size_t)HID * FWP];
__device__ __half g_qb_h [(size_t)QL * QW],    g_qb_l [(size_t)QL * QW];
__device__ __half g_kvb_h[(size_t)KVL * KVW],  g_kvb_l[(size_t)KVL * KVW];
__device__ __half g_o_h  [(size_t)AW * HID],   g_o_l  [(size_t)AW * HID];
__device__ __half g_qan_h[(size_t)SEQ * QL];
__device__ __half g_ckn_h[(size_t)SEQ * KVL];
__device__ __half g_qs_h [(size_t)SEQ * QW],   g_qs_l [(size_t)SEQ * QW];
__device__ __half g_kv_h [(size_t)SEQ * KVW],  g_kv_l [(size_t)SEQ * KVW];
__device__ __half g_kpe_h[(size_t)SEQ * DR],   g_kpe_l[(size_t)SEQ * DR];
__device__ __half g_at_h [(size_t)SEQ * AW];

__device__ __forceinline__ uint32_t smem_u32(const void* p) {
    return (uint32_t)__cvta_generic_to_shared(p);
}

#define LDSM_X4(r0, r1, r2, r3, a)                                            \
    asm volatile("ldmatrix.sync.aligned.m8n8.x4.shared.b16 {%0,%1,%2,%3},[%4];" \
                 : "=r"(r0), "=r"(r1), "=r"(r2), "=r"(r3) : "r"(a))
#define LDSM_X2(r0, r1, a)                                                    \
    asm volatile("ldmatrix.sync.aligned.m8n8.x2.shared.b16 {%0,%1},[%2];"     \
                 : "=r"(r0), "=r"(r1) : "r"(a))
#define LDSM_X4_T(r0, r1, r2, r3, a)                                          \
    asm volatile("ldmatrix.sync.aligned.m8n8.x4.trans.shared.b16 {%0,%1,%2,%3},[%4];" \
                 : "=r"(r0), "=r"(r1), "=r"(r2), "=r"(r3) : "r"(a))

#define MMA16816(d, a0, a1, a2, a3, b0, b1)                                   \
    asm volatile("mma.sync.aligned.m16n8k16.row.col.f32.f16.f16.f32 "         \
                 "{%0,%1,%2,%3},{%4,%5,%6,%7},{%8,%9},{%0,%1,%2,%3};"          \
                 : "+f"(d[0]), "+f"(d[1]), "+f"(d[2]), "+f"(d[3])              \
                 : "r"(a0), "r"(a1), "r"(a2), "r"(a3), "r"(b0), "r"(b1))

#define CP_ASYNC16(dst, src)                                                  \
    asm volatile("cp.async.cg.shared.global [%0], [%1], 16;" :: "r"(dst), "l"(src))
#define CP_COMMIT() asm volatile("cp.async.commit_group;" ::: "memory")
#define CP_WAIT1()  asm volatile("cp.async.wait_group 1;" ::: "memory")

__device__ __forceinline__ void split_h2(float x, float y, uint32_t& h, uint32_t& l) {
    __half hx = __float2half_rn(x), hy = __float2half_rn(y);
    __half2 hp = __halves2half2(hx, hy);
    h = *(uint32_t*)&hp;
    __half2 lp = __halves2half2(__float2half_rn(x - __half2float(hx)),
                                __float2half_rn(y - __half2float(hy)));
    l = *(uint32_t*)&lp;
}

// ---------------- fp32 -> fp16 h/l split ----------------
__global__ __launch_bounds__(256) void fsplit_kernel(
    const float* __restrict__ x, __half* __restrict__ h, __half* __restrict__ l, int n2)
{
    int i = blockIdx.x * 256 + threadIdx.x;
    if (i < n2) {
        float2 v = ((const float2*)x)[i];
        uint32_t hh, ll;
        split_h2(v.x, v.y, hh, ll);
        ((uint32_t*)h)[i] = hh;
        ((uint32_t*)l)[i] = ll;
    }
}

// ---------------- fp32 -> fp16 convert (h only) ----------------
__global__ __launch_bounds__(256) void hconv_kernel(
    const float* __restrict__ x, __half* __restrict__ h, int n2)
{
    int i = blockIdx.x * 256 + threadIdx.x;
    if (i < n2) {
        float2 v = ((const float2*)x)[i];
        ((__half2*)h)[i] = __float22half2_rn(v);
    }
}

// ---------------- fused [w_qa | w_kva] split (padded to FWP) ----------------
__global__ __launch_bounds__(256) void wfuse_split_kernel(
    const float* __restrict__ wqa, const float* __restrict__ wkva,
    __half* __restrict__ h, __half* __restrict__ l)
{
    int i = blockIdx.x * 256 + threadIdx.x;
    int row = i / (FWP / 2), p = i % (FWP / 2);
    int col = 2 * p;
    float x = 0.f, y = 0.f;
    if (col < QL)      { x = wqa[(size_t)row * QL + col];         y = wqa[(size_t)row * QL + col + 1]; }
    else if (col < FW) { x = wkva[(size_t)row * CKVW + col - QL]; y = wkva[(size_t)row * CKVW + col - QL + 1]; }
    uint32_t hh, ll;
    split_h2(x, y, hh, ll);
    ((uint32_t*)h)[(size_t)row * (FWP / 2) + p] = hh;
    ((uint32_t*)l)[(size_t)row * (FWP / 2) + p] = ll;
}

// ---------------- RMSNorm with fp16 output (h only) ----------------
__global__ __launch_bounds__(256) void rmsnorm_h_kernel(
    const float* __restrict__ x, const float* __restrict__ g,
    __half* __restrict__ oh, int width, int stride_in)
{
    __shared__ float red[256];
    const float* p = x + (size_t)blockIdx.x * stride_in;
    float s = 0.f;
    for (int i = threadIdx.x; i < width; i += 256) { float v = p[i]; s += v * v; }
    red[threadIdx.x] = s;
    __syncthreads();
#pragma unroll
    for (int off = 128; off > 0; off >>= 1) {
        if (threadIdx.x < off) red[threadIdx.x] += red[threadIdx.x + off];
        __syncthreads();
    }
    float inv = rsqrtf(red[0] / (float)width + 1e-6f);
    int w2 = width / 2;
    for (int i = threadIdx.x; i < w2; i += 256) {
        float v0 = p[2 * i] * inv * g[2 * i];
        float v1 = p[2 * i + 1] * inv * g[2 * i + 1];
        ((__half2*)oh)[(size_t)blockIdx.x * w2 + i] = __float22half2_rn(make_float2(v0, v1));
    }
}

// ======== fp16x2 GEMM (A fp16, B pre-split h/l; C = Ah*Bh + Ah*Bl) ========
#define G_AT 16384                       // A tile: 128 rows x 128B
#define G_BT 16384                       // B half-tile: 64 rows x 256B
#define G_STAGE (G_AT + 2 * G_BT)        // 49152
#define GEMM_SMEM_BYTES (3 * G_STAGE)    // 147456

template <bool SPLIT_OUT>
__global__ __launch_bounds__(256) void gemm_h(
    const __half* __restrict__ Ah, int lda,
    const __half* __restrict__ Bh, const __half* __restrict__ Bl, int ldb,
    float* __restrict__ C, __half* __restrict__ Ch, __half* __restrict__ Cl,
    int ldc, int N, int K)
{
    extern __shared__ char sm[];
    const uint32_t sbase = smem_u32(sm);

    const int tid  = threadIdx.x;
    const int lane = tid & 31, w = tid >> 5;
    const int wm = w & 3, wn = w >> 2;
    const int row0 = blockIdx.y * 128;
    const int col0 = blockIdx.x * 128;

    float acc[2][8][4];
#pragma unroll
    for (int mt = 0; mt < 2; ++mt)
#pragma unroll
        for (int nt = 0; nt < 8; ++nt)
#pragma unroll
            for (int i = 0; i < 4; ++i) acc[mt][nt][i] = 0.f;

    auto do_cp = [&](int stage, int k0) {
        uint32_t sb = sbase + stage * G_STAGE;
#pragma unroll
        for (int i = 0; i < 4; ++i) {          // A: 1024 16B chunks
            int idx = i * 256 + tid;
            int r = idx >> 3, u = idx & 7;
            uint32_t off = r * 128 + ((u ^ (r & 7)) << 4);
            CP_ASYNC16(sb + off, Ah + (size_t)(row0 + r) * lda + k0 + u * 8);
        }
#pragma unroll
        for (int i = 0; i < 4; ++i) {          // B: 1024 chunks per half-tile
            int idx = i * 256 + tid;
            int r = idx >> 4, u = idx & 15;
            uint32_t off = G_AT + r * 256 + ((u ^ (r & 7)) << 4);
            CP_ASYNC16(sb + off, Bh + (size_t)(k0 + r) * ldb + col0 + u * 8);
            CP_ASYNC16(sb + G_BT + off, Bl + (size_t)(k0 + r) * ldb + col0 + u * 8);
        }
    };

    const int nIter = K >> 6;
    do_cp(0, 0);
    CP_COMMIT();
    if (nIter > 1) do_cp(1, 64);
    CP_COMMIT();

    for (int it = 0; it < nIter; ++it) {
        CP_WAIT1();
        __syncthreads();
        if (it + 2 < nIter) do_cp((it + 2) % 3, (it + 2) << 6);
        CP_COMMIT();

        char* base = sm + (it % 3) * G_STAGE;
#pragma unroll
        for (int kg = 0; kg < 4; ++kg) {
            uint32_t ah[2][4];
#pragma unroll
            for (int mt = 0; mt < 2; ++mt) {
                int row = wm * 32 + mt * 16 + (lane & 15);
                int kc = kg * 2 + (lane >> 4);
                uint32_t ad = smem_u32(base + row * 128 + ((kc ^ (row & 7)) << 4));
                LDSM_X4(ah[mt][0], ah[mt][1], ah[mt][2], ah[mt][3], ad);
            }
            uint32_t bh[8][2], bl[8][2];
#pragma unroll
            for (int pr = 0; pr < 4; ++pr) {
                int k = kg * 16 + (lane & 15);
                int nc = wn * 8 + pr * 2 + (lane >> 4);
                uint32_t bd = smem_u32(base + G_AT + k * 256 + ((nc ^ (k & 7)) << 4));
                uint32_t t0, t1, t2, t3;
                LDSM_X4_T(t0, t1, t2, t3, bd);
                bh[2 * pr][0] = t0; bh[2 * pr][1] = t1;
                bh[2 * pr + 1][0] = t2; bh[2 * pr + 1][1] = t3;
                LDSM_X4_T(t0, t1, t2, t3, bd + G_BT);
                bl[2 * pr][0] = t0; bl[2 * pr][1] = t1;
                bl[2 * pr + 1][0] = t2; bl[2 * pr + 1][1] = t3;
            }
#pragma unroll
            for (int mt = 0; mt < 2; ++mt)
#pragma unroll
                for (int nt = 0; nt < 8; ++nt) {
                    MMA16816(acc[mt][nt], ah[mt][0], ah[mt][1], ah[mt][2], ah[mt][3],
                             bl[nt][0], bl[nt][1]);
                    MMA16816(acc[mt][nt], ah[mt][0], ah[mt][1], ah[mt][2], ah[mt][3],
                             bh[nt][0], bh[nt][1]);
                }
        }
    }

    const int g = lane >> 2, t = lane & 3;
#pragma unroll
    for (int mt = 0; mt < 2; ++mt) {
        int r = row0 + wm * 32 + mt * 16 + g;
#pragma unroll
        for (int nt = 0; nt < 8; ++nt) {
            int c = col0 + wn * 64 + nt * 8 + 2 * t;
            if (SPLIT_OUT) {
                uint32_t hh, ll;
                split_h2(acc[mt][nt][0], acc[mt][nt][1], hh, ll);
                *(uint32_t*)(Ch + (size_t)r * ldc + c) = hh;
                *(uint32_t*)(Cl + (size_t)r * ldc + c) = ll;
                split_h2(acc[mt][nt][2], acc[mt][nt][3], hh, ll);
                *(uint32_t*)(Ch + (size_t)(r + 8) * ldc + c) = hh;
                *(uint32_t*)(Cl + (size_t)(r + 8) * ldc + c) = ll;
            } else if (c < N) {
                *(float2*)(C + (size_t)r * ldc + c)       = make_float2(acc[mt][nt][0], acc[mt][nt][1]);
                *(float2*)(C + (size_t)(r + 8) * ldc + c) = make_float2(acc[mt][nt][2], acc[mt][nt][3]);
            }
        }
    }
}

// ---------------- RoPE (q fp32 in place; kpe -> split fp16) ----------------
__global__ __launch_bounds__(256) void rope_kernel(
    float* __restrict__ q, const float* __restrict__ qc,
    __half* __restrict__ kpeh, __half* __restrict__ kpel,
    const float* __restrict__ cosb, const float* __restrict__ sinb)
{
    int gw   = (blockIdx.x * blockDim.x + threadIdx.x) >> 5;
    int lane = threadIdx.x & 31;
    const int total_q = SEQ * NH;
    if (gw < total_q) {
        int s = gw / NH, h = gw % NH;
        float* x = q + (size_t)s * QW + h * DQK + DN;
        float c  = cosb[s * DR + lane];
        float sn = sinb[s * DR + lane];
        float x0 = x[2 * lane], x1 = x[2 * lane + 1];
        __syncwarp();
        x[lane]      = x0 * c - x1 * sn;
        x[lane + 32] = x1 * c + x0 * sn;
    } else if (gw < total_q + SEQ) {
        int s = gw - total_q;
        const float* x = qc + (size_t)s * FWP + QL + KVL;
        float c  = cosb[s * DR + lane];
        float sn = sinb[s * DR + lane];
        float x0 = x[2 * lane], x1 = x[2 * lane + 1];
        float y0 = x0 * c - x1 * sn;
        float y1 = x1 * c + x0 * sn;
        __half h0 = __float2half_rn(y0);
        __half h1 = __float2half_rn(y1);
        kpeh[s * DR + lane]      = h0;
        kpel[s * DR + lane]      = __float2half_rn(y0 - __half2float(h0));
        kpeh[s * DR + lane + 32] = h1;
        kpel[s * DR + lane + 32] = __float2half_rn(y1 - __half2float(h1));
    }
}

// ==== flash attention: QK fp16x3 (exact S), PV fp16x2, P fp16 ====
#define A_QH 0
#define A_QL 24576
#define A_KH 49152
#define A_KL 73728
#define A_VH 98304
#define A_VL 114688
#define A_PH 131072
#define A_MR 139264
#define A_LR (A_MR + 256)
#define A_PM (A_LR + 256)
#define A_PS (A_PM + 512)
#define ATTN_SMEM_BYTES (A_PS + 512)   // 141312

__global__ __launch_bounds__(256) void attn_mma(
    const __half* __restrict__ qh, const __half* __restrict__ ql,
    const __half* __restrict__ kvh, const __half* __restrict__ kvl,
    const __half* __restrict__ kpeh, const __half* __restrict__ kpel,
    __half* __restrict__ ath)
{
    extern __shared__ char sm[];
    float* mrow = (float*)(sm + A_MR);
    float* lrow = (float*)(sm + A_LR);
    float* pmax = (float*)(sm + A_PM);
    float* psum = (float*)(sm + A_PS);

    const int tid = threadIdx.x, lane = tid & 31, w = tid >> 5;
    const int wm = w & 3, wn = w >> 2;
    const int qb = gridDim.x - 1 - blockIdx.x;
    const int hh_ = blockIdx.y;
    const int q0 = qb * 64;
    const float scale = rsqrtf((float)DQK);

    // ---- Q tile fill (h + l, QK keeps x3) ----
#pragma unroll
    for (int i = 0; i < 6; ++i) {
        int idx = i * 256 + tid;
        int r = idx / 24, u = idx % 24;
        int sc = u ^ (r & 7);
        int off = r * 384 + sc * 16;
        const size_t go = (size_t)(q0 + r) * QW + hh_ * DQK + u * 8;
        *(uint4*)(sm + A_QH + off) = *(const uint4*)(qh + go);
        *(uint4*)(sm + A_QL + off) = *(const uint4*)(ql + go);
    }
    if (tid < 64) { mrow[tid] = -1e30f; lrow[tid] = 0.f; }

    float acc_o[8][4];
#pragma unroll
    for (int nt = 0; nt < 8; ++nt)
#pragma unroll
        for (int i = 0; i < 4; ++i) acc_o[nt][i] = 0.f;

    __syncthreads();

    const int g = lane >> 2, t = lane & 3;
    const int r0 = wm * 16 + g, r1 = r0 + 8;

    for (int kb = 0; kb <= qb; ++kb) {
        const int k0 = kb * 64;

        // ---- K tile fill ----
#pragma unroll
        for (int i = 0; i < 6; ++i) {
            int idx = i * 256 + tid;
            int r = idx / 24, u = idx % 24;
            int sc = u ^ (r & 7);
            int off = r * 384 + sc * 16;
            if (u < 16) {
                const size_t go = (size_t)(k0 + r) * KVW + hh_ * (DN + DV) + u * 8;
                *(uint4*)(sm + A_KH + off) = *(const uint4*)(kvh + go);
                *(uint4*)(sm + A_KL + off) = *(const uint4*)(kvl + go);
            } else {
                const size_t go = (size_t)(k0 + r) * DR + (u - 16) * 8;
                *(uint4*)(sm + A_KH + off) = *(const uint4*)(kpeh + go);
                *(uint4*)(sm + A_KL + off) = *(const uint4*)(kpel + go);
            }
        }
        // ---- V tile fill ----
#pragma unroll
        for (int i = 0; i < 4; ++i) {
            int idx = i * 256 + tid;
            int r = idx >> 4, u = idx & 15;
            int sc = u ^ (r & 7);
            int off = r * 256 + sc * 16;
            const size_t go = (size_t)(k0 + r) * KVW + hh_ * (DN + DV) + DN + u * 8;
            *(uint4*)(sm + A_VH + off) = *(const uint4*)(kvh + go);
            *(uint4*)(sm + A_VL + off) = *(const uint4*)(kvl + go);
        }
        __syncthreads();

        // ---- S = Q @ K^T (fp16x3: exact) ----
        float acc_s[4][4];
#pragma unroll
        for (int nt = 0; nt < 4; ++nt)
#pragma unroll
            for (int i = 0; i < 4; ++i) acc_s[nt][i] = 0.f;

#pragma unroll
        for (int ks = 0; ks < 12; ++ks) {
            uint32_t qfh[4], qfl[4];
            {
                int row = wm * 16 + (lane & 15);
                int c = 2 * ks + (lane >> 4);
                int sc = c ^ (row & 7);
                uint32_t ad = smem_u32(sm + row * 384 + sc * 16);
                LDSM_X4(qfh[0], qfh[1], qfh[2], qfh[3], ad + A_QH);
                LDSM_X4(qfl[0], qfl[1], qfl[2], qfl[3], ad + (A_QL - A_QH));
            }
#pragma unroll
            for (int nt = 0; nt < 4; ++nt) {
                int krow = wn * 32 + nt * 8 + (lane & 7);
                int kc = 2 * ks + ((lane >> 3) & 1);
                int ksc = kc ^ (krow & 7);
                uint32_t kd = smem_u32(sm + krow * 384 + ksc * 16);
                uint32_t kh0, kh1, kl0, kl1;
                LDSM_X2(kh0, kh1, kd + A_KH);
                LDSM_X2(kl0, kl1, kd + A_KL);
                MMA16816(acc_s[nt], qfh[0], qfh[1], qfh[2], qfh[3], kl0, kl1);
                MMA16816(acc_s[nt], qfl[0], qfl[1], qfl[2], qfl[3], kh0, kh1);
                MMA16816(acc_s[nt], qfh[0], qfh[1], qfh[2], qfh[3], kh0, kh1);
            }
        }

        // ---- scale + causal mask + warp-local max ----
        float vm0 = -1e30f, vm1 = -1e30f;
#pragma unroll
        for (int nt = 0; nt < 4; ++nt) {
            int col = wn * 32 + nt * 8 + 2 * t;
            float v00 = acc_s[nt][0] * scale, v01 = acc_s[nt][1] * scale;
            float v10 = acc_s[nt][2] * scale, v11 = acc_s[nt][3] * scale;
            if (k0 + col     > q0 + r0) v00 = -1e30f;
            if (k0 + col + 1 > q0 + r0) v01 = -1e30f;
            if (k0 + col     > q0 + r1) v10 = -1e30f;
            if (k0 + col + 1 > q0 + r1) v11 = -1e30f;
            acc_s[nt][0] = v00; acc_s[nt][1] = v01;
            acc_s[nt][2] = v10; acc_s[nt][3] = v11;
            vm0 = fmaxf(vm0, fmaxf(v00, v01));
            vm1 = fmaxf(vm1, fmaxf(v10, v11));
        }
        vm0 = fmaxf(vm0, __shfl_xor_sync(0xffffffffu, vm0, 1));
        vm0 = fmaxf(vm0, __shfl_xor_sync(0xffffffffu, vm0, 2));
        vm1 = fmaxf(vm1, __shfl_xor_sync(0xffffffffu, vm1, 1));
        vm1 = fmaxf(vm1, __shfl_xor_sync(0xffffffffu, vm1, 2));
        if (t == 0) { pmax[r0 * 2 + wn] = vm0; pmax[r1 * 2 + wn] = vm1; }
        __syncthreads();

        float mold0 = mrow[r0], mold1 = mrow[r1];
        float mnew0 = fmaxf(mold0, fmaxf(pmax[r0 * 2], pmax[r0 * 2 + 1]));
        float mnew1 = fmaxf(mold1, fmaxf(pmax[r1 * 2], pmax[r1 * 2 + 1]));
        float alpha0 = __expf(mold0 - mnew0);
        float alpha1 = __expf(mold1 - mnew1);

        // ---- exp + P fp16 (h only) to swizzled smem ----
        float s0 = 0.f, s1 = 0.f;
#pragma unroll
        for (int nt = 0; nt < 4; ++nt) {
            float p00 = __expf(acc_s[nt][0] - mnew0);
            float p01 = __expf(acc_s[nt][1] - mnew0);
            float p10 = __expf(acc_s[nt][2] - mnew1);
            float p11 = __expf(acc_s[nt][3] - mnew1);
            s0 += p00 + p01;
            s1 += p10 + p11;
            __half2 hp0 = __float22half2_rn(make_float2(p00, p01));
            int off0 = r0 * 128 + (((wn * 4 + nt) ^ (r0 & 7)) << 4) + t * 4;
            *(__half2*)(sm + A_PH + off0) = hp0;
            __half2 hp1 = __float22half2_rn(make_float2(p10, p11));
            int off1 = r1 * 128 + (((wn * 4 + nt) ^ (r1 & 7)) << 4) + t * 4;
            *(__half2*)(sm + A_PH + off1) = hp1;
        }
        s0 += __shfl_xor_sync(0xffffffffu, s0, 1);
        s0 += __shfl_xor_sync(0xffffffffu, s0, 2);
        s1 += __shfl_xor_sync(0xffffffffu, s1, 1);
        s1 += __shfl_xor_sync(0xffffffffu, s1, 2);
        if (t == 0) { psum[r0 * 2 + wn] = s0; psum[r1 * 2 + wn] = s1; }
        __syncthreads();

        if (wn == 0 && t == 0) {
            lrow[r0] = lrow[r0] * alpha0 + psum[r0 * 2] + psum[r0 * 2 + 1];
            mrow[r0] = mnew0;
            lrow[r1] = lrow[r1] * alpha1 + psum[r1 * 2] + psum[r1 * 2 + 1];
            mrow[r1] = mnew1;
        }

        // ---- rescale O, then O += P @ V (fp16x2: Ph*Vh + Ph*Vl) ----
#pragma unroll
        for (int nt = 0; nt < 8; ++nt) {
            acc_o[nt][0] *= alpha0; acc_o[nt][1] *= alpha0;
            acc_o[nt][2] *= alpha1; acc_o[nt][3] *= alpha1;
        }
#pragma unroll
        for (int ks = 0; ks < 4; ++ks) {
            uint32_t ph[4];
            {
                int row = wm * 16 + (lane & 15);
                int c = 2 * ks + (lane >> 4);
                uint32_t pd = smem_u32(sm + row * 128 + ((c ^ (row & 7)) << 4));
                LDSM_X4(ph[0], ph[1], ph[2], ph[3], pd + A_PH);
            }
#pragma unroll
            for (int pr = 0; pr < 4; ++pr) {
                int vk = ks * 16 + (lane & 15);
                int vc = wn * 8 + pr * 2 + (lane >> 4);
                int vsc = vc ^ (vk & 7);
                uint32_t vd = smem_u32(sm + vk * 256 + vsc * 16);
                uint32_t b0, b1, b2, b3, c0, c1, c2, c3;
                LDSM_X4_T(b0, b1, b2, b3, vd + A_VH);
                LDSM_X4_T(c0, c1, c2, c3, vd + A_VL);
                int nt0 = 2 * pr, nt1 = 2 * pr + 1;
                MMA16816(acc_o[nt0], ph[0], ph[1], ph[2], ph[3], c0, c1);
                MMA16816(acc_o[nt0], ph[0], ph[1], ph[2], ph[3], b0, b1);
                MMA16816(acc_o[nt1], ph[0], ph[1], ph[2], ph[3], c2, c3);
                MMA16816(acc_o[nt1], ph[0], ph[1], ph[2], ph[3], b2, b3);
            }
        }
        __syncthreads();
    }

    // ---- output: fp16 (h only) ----
    float inv0 = 1.f / lrow[r0];
    float inv1 = 1.f / lrow[r1];
#pragma unroll
    for (int nt = 0; nt < 8; ++nt) {
        int col = wn * 64 + nt * 8 + 2 * t;
        *(__half2*)(ath + (size_t)(q0 + r0) * AW + hh_ * DV + col) =
            __float22half2_rn(make_float2(acc_o[nt][0] * inv0, acc_o[nt][1] * inv0));
        *(__half2*)(ath + (size_t)(q0 + r1) * AW + hh_ * DV + col) =
            __float22half2_rn(make_float2(acc_o[nt][2] * inv1, acc_o[nt][3] * inv1));
    }
}

// ---------------- launch ----------------
extern "C" void kernel_launch(void* const* d_in, const int* in_sizes, int n_in,
                              void* d_out, int out_size)
{
    const float* hidden = (const float*)d_in[0];
    const float* cosb   = (const float*)d_in[1];
    const float* sinb   = (const float*)d_in[2];
    const float* w_qa   = (const float*)d_in[3];
    const float* gm_qa  = (const float*)d_in[4];
    const float* w_qb   = (const float*)d_in[5];
    const float* w_kva  = (const float*)d_in[6];
    const float* gm_kva = (const float*)d_in[7];
    const float* w_kvb  = (const float*)d_in[8];
    const float* w_o    = (const float*)d_in[9];
    float* out = (float*)d_out;

    float *qc, *qf;
    __half *hidh, *wfh, *wfl, *qbh, *qbl, *kvbh, *kvbl, *oh, *ol;
    __half *qanh, *cknh, *qsh, *qsl, *kvh, *kvl, *kpeh, *kpel, *ath;
    cudaGetSymbolAddress((void**)&qc,   g_qc_s);
    cudaGetSymbolAddress((void**)&qf,   g_q_s);
    cudaGetSymbolAddress((void**)&hidh, g_hid_h);
    cudaGetSymbolAddress((void**)&wfh,  g_wf_h);  cudaGetSymbolAddress((void**)&wfl,  g_wf_l);
    cudaGetSymbolAddress((void**)&qbh,  g_qb_h);  cudaGetSymbolAddress((void**)&qbl,  g_qb_l);
    cudaGetSymbolAddress((void**)&kvbh, g_kvb_h); cudaGetSymbolAddress((void**)&kvbl, g_kvb_l);
    cudaGetSymbolAddress((void**)&oh,   g_o_h);   cudaGetSymbolAddress((void**)&ol,   g_o_l);
    cudaGetSymbolAddress((void**)&qanh, g_qan_h);
    cudaGetSymbolAddress((void**)&cknh, g_ckn_h);
    cudaGetSymbolAddress((void**)&qsh,  g_qs_h);  cudaGetSymbolAddress((void**)&qsl,  g_qs_l);
    cudaGetSymbolAddress((void**)&kvh,  g_kv_h);  cudaGetSymbolAddress((void**)&kvl,  g_kv_l);
    cudaGetSymbolAddress((void**)&kpeh, g_kpe_h); cudaGetSymbolAddress((void**)&kpel, g_kpe_l);
    cudaGetSymbolAddress((void**)&ath,  g_at_h);

    static bool attr_done = false;
    if (!attr_done) {
        cudaFuncSetAttribute(attn_mma, cudaFuncAttributeMaxDynamicSharedMemorySize,
                             ATTN_SMEM_BYTES);
        cudaFuncSetAttribute(gemm_h<false>, cudaFuncAttributeMaxDynamicSharedMemorySize,
                             GEMM_SMEM_BYTES);
        cudaFuncSetAttribute(gemm_h<true>, cudaFuncAttributeMaxDynamicSharedMemorySize,
                             GEMM_SMEM_BYTES);
        attr_done = true;
    }

    // conversions / splits (bandwidth-bound)
    hconv_kernel<<<(SEQ * HID / 2) / 256, 256>>>(hidden, hidh, SEQ * HID / 2);
    wfuse_split_kernel<<<(HID * FWP / 2) / 256, 256>>>(w_qa, w_kva, wfh, wfl);
    fsplit_kernel<<<(QL * QW / 2) / 256, 256>>>(w_qb, qbh, qbl, QL * QW / 2);
    fsplit_kernel<<<(KVL * KVW / 2) / 256, 256>>>(w_kvb, kvbh, kvbl, KVL * KVW / 2);
    fsplit_kernel<<<(AW * HID / 2) / 256, 256>>>(w_o, oh, ol, AW * HID / 2);

    // [qa|ckv] = hidden @ wf  (fp32 out)
    gemm_h<false><<<dim3(FWP / 128, SEQ / 128), 256, GEMM_SMEM_BYTES>>>(
        hidh, HID, wfh, wfl, FWP, qc, ((__half*)0), ((__half*)0), FWP, FW, HID);
    // rmsnorm -> fp16
    rmsnorm_h_kernel<<<SEQ, 256>>>(qc, gm_qa, qanh, QL, FWP);
    rmsnorm_h_kernel<<<SEQ, 256>>>(qc + QL, gm_kva, cknh, KVL, FWP);
    // q = qa_n @ w_qb (fp32 out, rope needs it)
    gemm_h<false><<<dim3(QW / 128, SEQ / 128), 256, GEMM_SMEM_BYTES>>>(
        qanh, QL, qbh, qbl, QW, qf, ((__half*)0), ((__half*)0), QW, QW, QL);
    // kv = ckv_n @ w_kvb (split fp16 out — attention B-side needs h/l)
    gemm_h<true><<<dim3(KVW / 128, SEQ / 128), 256, GEMM_SMEM_BYTES>>>(
        cknh, KVL, kvbh, kvbl, KVW, ((float*)0), kvh, kvl, KVW, KVW, KVL);
    // RoPE (q fp32 in place; kpe split out)
    rope_kernel<<<(SEQ * (NH + 1)) / 8, 256>>>(qf, qc, kpeh, kpel, cosb, sinb);
    // split q (QK stays x3)
    fsplit_kernel<<<(SEQ * QW / 2) / 256, 256>>>(qf, qsh, qsl, SEQ * QW / 2);
    // attention
    attn_mma<<<dim3(SEQ / 64, NH), 256, ATTN_SMEM_BYTES>>>(
        qsh, qsl, kvh, kvl, kpeh, kpel, ath);
    // out = attn @ w_o (fp32 out)
    gemm_h<false><<<dim3(HID / 128, SEQ / 128), 256, GEMM_SMEM_BYTES>>>(
        ath, AW, oh, ol, HID, out, ((__half*)0), ((__half*)0), HID, HID, AW);
}

// round 10
// speedup vs baseline: 5.9134x; 1.2905x over previous
#include <cuda_runtime.h>
#include <cuda_fp16.h>
#include <cuda_bf16.h>
#include <stdint.h>
#include <math.h>

#define SEQ 2048
#define HID 2048
#define NH 16
#define QL 1536
#define KVL 512
#define DN 128
#define DR 64
#define DV 128
#define DQK 192
#define CKVW (KVL + DR)      // 576
#define FW (QL + CKVW)       // 2112
#define FWP 2176             // FW padded to 128
#define QW (NH * DQK)        // 3072
#define KVW (NH * (DN + DV)) // 4096
#define AW (NH * DV)         // 2048

// ---------------- scratch ----------------
__device__ float  g_qc_s [(size_t)SEQ * FWP];
__device__ float  g_q_s  [(size_t)SEQ * QW];
__device__ __half g_hid_h[(size_t)SEQ * HID];
__device__ __half g_wf_h [(size_t)HID * FWP],  g_wf_l [(size_t)HID * FWP];
__device__ __half g_qb_h [(size_t)QL * QW],    g_qb_l [(size_t)QL * QW];
__device__ __half g_kvb_h[(size_t)KVL * KVW],  g_kvb_l[(size_t)KVL * KVW];
__device__ __half g_o_h  [(size_t)AW * HID],   g_o_l  [(size_t)AW * HID];
__device__ __half g_qan_h[(size_t)SEQ * QL];
__device__ __half g_ckn_h[(size_t)SEQ * KVL];
__device__ __half g_qs_h [(size_t)SEQ * QW],   g_qs_l [(size_t)SEQ * QW];
__device__ __half g_kv_h [(size_t)SEQ * KVW],  g_kv_l [(size_t)SEQ * KVW];
__device__ __half g_kpe_h[(size_t)SEQ * DR],   g_kpe_l[(size_t)SEQ * DR];
__device__ __half g_at_h [(size_t)SEQ * AW];

__device__ __forceinline__ uint32_t smem_u32(const void* p) {
    return (uint32_t)__cvta_generic_to_shared(p);
}

#define LDSM_X4(r0, r1, r2, r3, a)                                            \
    asm volatile("ldmatrix.sync.aligned.m8n8.x4.shared.b16 {%0,%1,%2,%3},[%4];" \
                 : "=r"(r0), "=r"(r1), "=r"(r2), "=r"(r3) : "r"(a))
#define LDSM_X2(r0, r1, a)                                                    \
    asm volatile("ldmatrix.sync.aligned.m8n8.x2.shared.b16 {%0,%1},[%2];"     \
                 : "=r"(r0), "=r"(r1) : "r"(a))
#define LDSM_X4_T(r0, r1, r2, r3, a)                                          \
    asm volatile("ldmatrix.sync.aligned.m8n8.x4.trans.shared.b16 {%0,%1,%2,%3},[%4];" \
                 : "=r"(r0), "=r"(r1), "=r"(r2), "=r"(r3) : "r"(a))

#define MMA16816(d, a0, a1, a2, a3, b0, b1)                                   \
    asm volatile("mma.sync.aligned.m16n8k16.row.col.f32.f16.f16.f32 "         \
                 "{%0,%1,%2,%3},{%4,%5,%6,%7},{%8,%9},{%0,%1,%2,%3};"          \
                 : "+f"(d[0]), "+f"(d[1]), "+f"(d[2]), "+f"(d[3])              \
                 : "r"(a0), "r"(a1), "r"(a2), "r"(a3), "r"(b0), "r"(b1))

#define CP_ASYNC16(dst, src)                                                  \
    asm volatile("cp.async.cg.shared.global [%0], [%1], 16;" :: "r"(dst), "l"(src))
#define CP_COMMIT() asm volatile("cp.async.commit_group;" ::: "memory")
#define CP_WAIT1()  asm volatile("cp.async.wait_group 1;" ::: "memory")

__device__ __forceinline__ void split_h2(float x, float y, uint32_t& h, uint32_t& l) {
    __half hx = __float2half_rn(x), hy = __float2half_rn(y);
    __half2 hp = __halves2half2(hx, hy);
    h = *(uint32_t*)&hp;
    __half2 lp = __halves2half2(__float2half_rn(x - __half2float(hx)),
                                __float2half_rn(y - __half2float(hy)));
    l = *(uint32_t*)&lp;
}

// ======== one prep kernel: hconv + all weight splits ========
#define NB1 8192    // hconv: SEQ*HID/2/256
#define NB2 8704    // wfuse: HID*FWP/2/256
#define NB3 9216    // qb:    QL*QW/2/256
#define NB4 4096    // kvb:   KVL*KVW/2/256
#define NB5 8192    // wo:    AW*HID/2/256
#define PREP_BLOCKS (NB1 + NB2 + NB3 + NB4 + NB5)

__global__ __launch_bounds__(256) void prep_kernel(
    const float* __restrict__ hidden,
    const float* __restrict__ wqa, const float* __restrict__ wkva,
    const float* __restrict__ wqb, const float* __restrict__ wkvb,
    const float* __restrict__ wo,
    __half* __restrict__ hidh,
    __half* __restrict__ wfh, __half* __restrict__ wfl,
    __half* __restrict__ qbh, __half* __restrict__ qbl,
    __half* __restrict__ kvbh, __half* __restrict__ kvbl,
    __half* __restrict__ oh, __half* __restrict__ ol)
{
    int b = blockIdx.x;
    if (b < NB1) {
        int i = b * 256 + threadIdx.x;
        float2 v = ((const float2*)hidden)[i];
        ((__half2*)hidh)[i] = __float22half2_rn(v);
    } else if (b < NB1 + NB2) {
        int i = (b - NB1) * 256 + threadIdx.x;
        int row = i / (FWP / 2), p = i % (FWP / 2);
        int col = 2 * p;
        float x = 0.f, y = 0.f;
        if (col < QL)      { x = wqa[(size_t)row * QL + col];         y = wqa[(size_t)row * QL + col + 1]; }
        else if (col < FW) { x = wkva[(size_t)row * CKVW + col - QL]; y = wkva[(size_t)row * CKVW + col - QL + 1]; }
        uint32_t hh, ll;
        split_h2(x, y, hh, ll);
        ((uint32_t*)wfh)[i] = hh;
        ((uint32_t*)wfl)[i] = ll;
    } else if (b < NB1 + NB2 + NB3) {
        int i = (b - NB1 - NB2) * 256 + threadIdx.x;
        float2 v = ((const float2*)wqb)[i];
        uint32_t hh, ll;
        split_h2(v.x, v.y, hh, ll);
        ((uint32_t*)qbh)[i] = hh;
        ((uint32_t*)qbl)[i] = ll;
    } else if (b < NB1 + NB2 + NB3 + NB4) {
        int i = (b - NB1 - NB2 - NB3) * 256 + threadIdx.x;
        float2 v = ((const float2*)wkvb)[i];
        uint32_t hh, ll;
        split_h2(v.x, v.y, hh, ll);
        ((uint32_t*)kvbh)[i] = hh;
        ((uint32_t*)kvbl)[i] = ll;
    } else {
        int i = (b - NB1 - NB2 - NB3 - NB4) * 256 + threadIdx.x;
        float2 v = ((const float2*)wo)[i];
        uint32_t hh, ll;
        split_h2(v.x, v.y, hh, ll);
        ((uint32_t*)oh)[i] = hh;
        ((uint32_t*)ol)[i] = ll;
    }
}

// ---------------- both RMSNorms in one kernel (block = row) ----------------
__global__ __launch_bounds__(256) void rmsnorm2_kernel(
    const float* __restrict__ qc, const float* __restrict__ gqa,
    const float* __restrict__ gkva, __half* __restrict__ qanh,
    __half* __restrict__ cknh)
{
    __shared__ float red[256];
    const float* p = qc + (size_t)blockIdx.x * FWP;
    // --- qa slice ---
    float s = 0.f;
    for (int i = threadIdx.x; i < QL; i += 256) { float v = p[i]; s += v * v; }
    red[threadIdx.x] = s;
    __syncthreads();
#pragma unroll
    for (int off = 128; off > 0; off >>= 1) {
        if (threadIdx.x < off) red[threadIdx.x] += red[threadIdx.x + off];
        __syncthreads();
    }
    float inv = rsqrtf(red[0] / (float)QL + 1e-6f);
    for (int i = threadIdx.x; i < QL / 2; i += 256) {
        float v0 = p[2 * i] * inv * gqa[2 * i];
        float v1 = p[2 * i + 1] * inv * gqa[2 * i + 1];
        ((__half2*)qanh)[(size_t)blockIdx.x * (QL / 2) + i] = __float22half2_rn(make_float2(v0, v1));
    }
    __syncthreads();
    // --- ckv slice ---
    const float* p2 = p + QL;
    s = 0.f;
    for (int i = threadIdx.x; i < KVL; i += 256) { float v = p2[i]; s += v * v; }
    red[threadIdx.x] = s;
    __syncthreads();
#pragma unroll
    for (int off = 128; off > 0; off >>= 1) {
        if (threadIdx.x < off) red[threadIdx.x] += red[threadIdx.x + off];
        __syncthreads();
    }
    inv = rsqrtf(red[0] / (float)KVL + 1e-6f);
    for (int i = threadIdx.x; i < KVL / 2; i += 256) {
        float v0 = p2[2 * i] * inv * gkva[2 * i];
        float v1 = p2[2 * i + 1] * inv * gkva[2 * i + 1];
        ((__half2*)cknh)[(size_t)blockIdx.x * (KVL / 2) + i] = __float22half2_rn(make_float2(v0, v1));
    }
}

// ======== fp16x2 GEMM (A fp16, B pre-split h/l; C = Ah*Bh + Ah*Bl) ========
#define G_AT 16384
#define G_BT 16384
#define G_STAGE (G_AT + 2 * G_BT)        // 49152
#define GEMM_SMEM_BYTES (3 * G_STAGE)    // 147456

template <bool SPLIT_OUT>
__global__ __launch_bounds__(256) void gemm_h(
    const __half* __restrict__ Ah, int lda,
    const __half* __restrict__ Bh, const __half* __restrict__ Bl, int ldb,
    float* __restrict__ C, __half* __restrict__ Ch, __half* __restrict__ Cl,
    int ldc, int N, int K)
{
    extern __shared__ char sm[];
    const uint32_t sbase = smem_u32(sm);

    const int tid  = threadIdx.x;
    const int lane = tid & 31, w = tid >> 5;
    const int wm = w & 3, wn = w >> 2;
    const int row0 = blockIdx.y * 128;
    const int col0 = blockIdx.x * 128;

    float acc[2][8][4];
#pragma unroll
    for (int mt = 0; mt < 2; ++mt)
#pragma unroll
        for (int nt = 0; nt < 8; ++nt)
#pragma unroll
            for (int i = 0; i < 4; ++i) acc[mt][nt][i] = 0.f;

    auto do_cp = [&](int stage, int k0) {
        uint32_t sb = sbase + stage * G_STAGE;
#pragma unroll
        for (int i = 0; i < 4; ++i) {
            int idx = i * 256 + tid;
            int r = idx >> 3, u = idx & 7;
            uint32_t off = r * 128 + ((u ^ (r & 7)) << 4);
            CP_ASYNC16(sb + off, Ah + (size_t)(row0 + r) * lda + k0 + u * 8);
        }
#pragma unroll
        for (int i = 0; i < 4; ++i) {
            int idx = i * 256 + tid;
            int r = idx >> 4, u = idx & 15;
            uint32_t off = G_AT + r * 256 + ((u ^ (r & 7)) << 4);
            CP_ASYNC16(sb + off, Bh + (size_t)(k0 + r) * ldb + col0 + u * 8);
            CP_ASYNC16(sb + G_BT + off, Bl + (size_t)(k0 + r) * ldb + col0 + u * 8);
        }
    };

    const int nIter = K >> 6;
    do_cp(0, 0);
    CP_COMMIT();
    if (nIter > 1) do_cp(1, 64);
    CP_COMMIT();

    for (int it = 0; it < nIter; ++it) {
        CP_WAIT1();
        __syncthreads();
        if (it + 2 < nIter) do_cp((it + 2) % 3, (it + 2) << 6);
        CP_COMMIT();

        char* base = sm + (it % 3) * G_STAGE;
#pragma unroll
        for (int kg = 0; kg < 4; ++kg) {
            uint32_t ah[2][4];
#pragma unroll
            for (int mt = 0; mt < 2; ++mt) {
                int row = wm * 32 + mt * 16 + (lane & 15);
                int kc = kg * 2 + (lane >> 4);
                uint32_t ad = smem_u32(base + row * 128 + ((kc ^ (row & 7)) << 4));
                LDSM_X4(ah[mt][0], ah[mt][1], ah[mt][2], ah[mt][3], ad);
            }
            uint32_t bh[8][2], bl[8][2];
#pragma unroll
            for (int pr = 0; pr < 4; ++pr) {
                int k = kg * 16 + (lane & 15);
                int nc = wn * 8 + pr * 2 + (lane >> 4);
                uint32_t bd = smem_u32(base + G_AT + k * 256 + ((nc ^ (k & 7)) << 4));
                uint32_t t0, t1, t2, t3;
                LDSM_X4_T(t0, t1, t2, t3, bd);
                bh[2 * pr][0] = t0; bh[2 * pr][1] = t1;
                bh[2 * pr + 1][0] = t2; bh[2 * pr + 1][1] = t3;
                LDSM_X4_T(t0, t1, t2, t3, bd + G_BT);
                bl[2 * pr][0] = t0; bl[2 * pr][1] = t1;
                bl[2 * pr + 1][0] = t2; bl[2 * pr + 1][1] = t3;
            }
#pragma unroll
            for (int mt = 0; mt < 2; ++mt)
#pragma unroll
                for (int nt = 0; nt < 8; ++nt) {
                    MMA16816(acc[mt][nt], ah[mt][0], ah[mt][1], ah[mt][2], ah[mt][3],
                             bl[nt][0], bl[nt][1]);
                    MMA16816(acc[mt][nt], ah[mt][0], ah[mt][1], ah[mt][2], ah[mt][3],
                             bh[nt][0], bh[nt][1]);
                }
        }
    }

    const int g = lane >> 2, t = lane & 3;
#pragma unroll
    for (int mt = 0; mt < 2; ++mt) {
        int r = row0 + wm * 32 + mt * 16 + g;
#pragma unroll
        for (int nt = 0; nt < 8; ++nt) {
            int c = col0 + wn * 64 + nt * 8 + 2 * t;
            if (SPLIT_OUT) {
                uint32_t hh, ll;
                split_h2(acc[mt][nt][0], acc[mt][nt][1], hh, ll);
                *(uint32_t*)(Ch + (size_t)r * ldc + c) = hh;
                *(uint32_t*)(Cl + (size_t)r * ldc + c) = ll;
                split_h2(acc[mt][nt][2], acc[mt][nt][3], hh, ll);
                *(uint32_t*)(Ch + (size_t)(r + 8) * ldc + c) = hh;
                *(uint32_t*)(Cl + (size_t)(r + 8) * ldc + c) = ll;
            } else if (c < N) {
                *(float2*)(C + (size_t)r * ldc + c)       = make_float2(acc[mt][nt][0], acc[mt][nt][1]);
                *(float2*)(C + (size_t)(r + 8) * ldc + c) = make_float2(acc[mt][nt][2], acc[mt][nt][3]);
            }
        }
    }
}

// ------- RoPE on q + full q split (smem-staged); kpe in tail blocks -------
__global__ __launch_bounds__(256) void rope_qsplit_kernel(
    const float* __restrict__ qf, const float* __restrict__ qc,
    __half* __restrict__ qsh, __half* __restrict__ qsl,
    __half* __restrict__ kpeh, __half* __restrict__ kpel,
    const float* __restrict__ cosb, const float* __restrict__ sinb)
{
    __shared__ float row[QW];
    int b = blockIdx.x;
    if (b < SEQ) {
        const int s = b;
        const float* src = qf + (size_t)s * QW;
        // stage row
#pragma unroll
        for (int i = 0; i < 3; ++i) {
            int idx = (i * 256 + threadIdx.x) * 4;
            *(float4*)(row + idx) = *(const float4*)(src + idx);
        }
        __syncthreads();
        // rope: 512 items (head, lane), 2 per thread; read-all-then-write
        float y0[2], y1[2];
        int hd[2], ln[2];
#pragma unroll
        for (int e = 0; e < 2; ++e) {
            int item = threadIdx.x + e * 256;
            hd[e] = item >> 5; ln[e] = item & 31;
            float c  = cosb[s * DR + ln[e]];
            float sn = sinb[s * DR + ln[e]];
            float x0 = row[hd[e] * DQK + DN + 2 * ln[e]];
            float x1 = row[hd[e] * DQK + DN + 2 * ln[e] + 1];
            y0[e] = x0 * c - x1 * sn;
            y1[e] = x1 * c + x0 * sn;
        }
        __syncthreads();
#pragma unroll
        for (int e = 0; e < 2; ++e) {
            row[hd[e] * DQK + DN + ln[e]]      = y0[e];
            row[hd[e] * DQK + DN + ln[e] + 32] = y1[e];
        }
        __syncthreads();
        // split whole row
#pragma unroll
        for (int i = 0; i < 6; ++i) {
            int p = i * 256 + threadIdx.x;   // pair index, 1536 pairs
            uint32_t hh, ll;
            split_h2(row[2 * p], row[2 * p + 1], hh, ll);
            ((uint32_t*)qsh)[(size_t)s * (QW / 2) + p] = hh;
            ((uint32_t*)qsl)[(size_t)s * (QW / 2) + p] = ll;
        }
    } else {
        // kpe: 256 blocks x 8 warps = 2048 rows
        int wr = (b - SEQ) * 8 + (threadIdx.x >> 5);
        int lane = threadIdx.x & 31;
        const float* x = qc + (size_t)wr * FWP + QL + KVL;
        float c  = cosb[wr * DR + lane];
        float sn = sinb[wr * DR + lane];
        float x0 = x[2 * lane], x1 = x[2 * lane + 1];
        float z0 = x0 * c - x1 * sn;
        float z1 = x1 * c + x0 * sn;
        __half h0 = __float2half_rn(z0);
        __half h1 = __float2half_rn(z1);
        kpeh[wr * DR + lane]      = h0;
        kpel[wr * DR + lane]      = __float2half_rn(z0 - __half2float(h0));
        kpeh[wr * DR + lane + 32] = h1;
        kpel[wr * DR + lane + 32] = __float2half_rn(z1 - __half2float(h1));
    }
}

// ==== flash attention BQ=128/BK=64: QK fp16x3, PV fp16x2, reg softmax ====
#define A_QH 0
#define A_QL 49152
#define A_KH 98304
#define A_KL 122880
#define A_VH 147456
#define A_VL 163840
#define A_PH 180224
#define ATTN_SMEM_BYTES 196608

__global__ __launch_bounds__(256) void attn_mma(
    const __half* __restrict__ qh, const __half* __restrict__ ql,
    const __half* __restrict__ kvh, const __half* __restrict__ kvl,
    const __half* __restrict__ kpeh, const __half* __restrict__ kpel,
    __half* __restrict__ ath)
{
    extern __shared__ char sm[];

    const int tid = threadIdx.x, lane = tid & 31, wm = tid >> 5;
    const int qb = gridDim.x - 1 - blockIdx.x;
    const int hh_ = blockIdx.y;
    const int q0 = qb * 128;
    const float scale = rsqrtf((float)DQK);

    // ---- Q tile fill: 128 rows x 24 chunks (h + l) ----
#pragma unroll
    for (int i = 0; i < 12; ++i) {
        int idx = i * 256 + tid;
        int r = idx / 24, u = idx % 24;
        int off = r * 384 + ((u ^ (r & 7)) << 4);
        const size_t go = (size_t)(q0 + r) * QW + hh_ * DQK + u * 8;
        *(uint4*)(sm + A_QH + off) = *(const uint4*)(qh + go);
        *(uint4*)(sm + A_QL + off) = *(const uint4*)(ql + go);
    }

    const int g = lane >> 2, t = lane & 3;
    const int r0 = wm * 16 + g, r1 = r0 + 8;

    float m0 = -1e30f, m1 = -1e30f, l0 = 0.f, l1 = 0.f;
    float acc_o[16][4];
#pragma unroll
    for (int nt = 0; nt < 16; ++nt)
#pragma unroll
        for (int i = 0; i < 4; ++i) acc_o[nt][i] = 0.f;

    __syncthreads();

    const int nkb = 2 * qb + 2;
    for (int kb = 0; kb < nkb; ++kb) {
        const int k0 = kb * 64;

        // ---- K tile fill: 64 rows x 24 chunks ----
#pragma unroll
        for (int i = 0; i < 6; ++i) {
            int idx = i * 256 + tid;
            int r = idx / 24, u = idx % 24;
            int off = r * 384 + ((u ^ (r & 7)) << 4);
            if (u < 16) {
                const size_t go = (size_t)(k0 + r) * KVW + hh_ * (DN + DV) + u * 8;
                *(uint4*)(sm + A_KH + off) = *(const uint4*)(kvh + go);
                *(uint4*)(sm + A_KL + off) = *(const uint4*)(kvl + go);
            } else {
                const size_t go = (size_t)(k0 + r) * DR + (u - 16) * 8;
                *(uint4*)(sm + A_KH + off) = *(const uint4*)(kpeh + go);
                *(uint4*)(sm + A_KL + off) = *(const uint4*)(kpel + go);
            }
        }
        // ---- V tile fill: 64 rows x 16 chunks ----
#pragma unroll
        for (int i = 0; i < 4; ++i) {
            int idx = i * 256 + tid;
            int r = idx >> 4, u = idx & 15;
            int off = r * 256 + ((u ^ (r & 7)) << 4);
            const size_t go = (size_t)(k0 + r) * KVW + hh_ * (DN + DV) + DN + u * 8;
            *(uint4*)(sm + A_VH + off) = *(const uint4*)(kvh + go);
            *(uint4*)(sm + A_VL + off) = *(const uint4*)(kvl + go);
        }
        __syncthreads();

        // ---- S = Q @ K^T (fp16x3) : warp rows wm*16..+15, cols 0..63 ----
        float acc_s[8][4];
#pragma unroll
        for (int nt = 0; nt < 8; ++nt)
#pragma unroll
            for (int i = 0; i < 4; ++i) acc_s[nt][i] = 0.f;

#pragma unroll
        for (int ks = 0; ks < 12; ++ks) {
            uint32_t qfh[4], qfl[4];
            {
                int rowi = wm * 16 + (lane & 15);
                int c = 2 * ks + (lane >> 4);
                uint32_t ad = smem_u32(sm + rowi * 384 + ((c ^ (rowi & 7)) << 4));
                LDSM_X4(qfh[0], qfh[1], qfh[2], qfh[3], ad + A_QH);
                LDSM_X4(qfl[0], qfl[1], qfl[2], qfl[3], ad + (A_QL - A_QH));
            }
#pragma unroll
            for (int nt = 0; nt < 8; ++nt) {
                int krow = nt * 8 + (lane & 7);
                int kc = 2 * ks + ((lane >> 3) & 1);
                uint32_t kd = smem_u32(sm + A_KH + krow * 384 + ((kc ^ (krow & 7)) << 4));
                uint32_t kh0, kh1, kl0, kl1;
                LDSM_X2(kh0, kh1, kd);
                LDSM_X2(kl0, kl1, kd + (A_KL - A_KH));
                MMA16816(acc_s[nt], qfh[0], qfh[1], qfh[2], qfh[3], kl0, kl1);
                MMA16816(acc_s[nt], qfl[0], qfl[1], qfl[2], qfl[3], kh0, kh1);
                MMA16816(acc_s[nt], qfh[0], qfh[1], qfh[2], qfh[3], kh0, kh1);
            }
        }

        // ---- scale + causal mask + quad max ----
        float vm0 = -1e30f, vm1 = -1e30f;
#pragma unroll
        for (int nt = 0; nt < 8; ++nt) {
            int col = k0 + nt * 8 + 2 * t;
            float v00 = acc_s[nt][0] * scale, v01 = acc_s[nt][1] * scale;
            float v10 = acc_s[nt][2] * scale, v11 = acc_s[nt][3] * scale;
            if (col     > q0 + r0) v00 = -1e30f;
            if (col + 1 > q0 + r0) v01 = -1e30f;
            if (col     > q0 + r1) v10 = -1e30f;
            if (col + 1 > q0 + r1) v11 = -1e30f;
            acc_s[nt][0] = v00; acc_s[nt][1] = v01;
            acc_s[nt][2] = v10; acc_s[nt][3] = v11;
            vm0 = fmaxf(vm0, fmaxf(v00, v01));
            vm1 = fmaxf(vm1, fmaxf(v10, v11));
        }
        vm0 = fmaxf(vm0, __shfl_xor_sync(0xffffffffu, vm0, 1));
        vm0 = fmaxf(vm0, __shfl_xor_sync(0xffffffffu, vm0, 2));
        vm1 = fmaxf(vm1, __shfl_xor_sync(0xffffffffu, vm1, 1));
        vm1 = fmaxf(vm1, __shfl_xor_sync(0xffffffffu, vm1, 2));

        float mnew0 = fmaxf(m0, vm0);
        float mnew1 = fmaxf(m1, vm1);
        float alpha0 = __expf(m0 - mnew0);
        float alpha1 = __expf(m1 - mnew1);
        m0 = mnew0; m1 = mnew1;

        // ---- exp + P fp16 to warp-local swizzled smem ----
        float s0 = 0.f, s1 = 0.f;
#pragma unroll
        for (int nt = 0; nt < 8; ++nt) {
            float p00 = __expf(acc_s[nt][0] - mnew0);
            float p01 = __expf(acc_s[nt][1] - mnew0);
            float p10 = __expf(acc_s[nt][2] - mnew1);
            float p11 = __expf(acc_s[nt][3] - mnew1);
            s0 += p00 + p01;
            s1 += p10 + p11;
            int off0 = r0 * 128 + ((nt ^ (r0 & 7)) << 4) + t * 4;
            *(__half2*)(sm + A_PH + off0) = __float22half2_rn(make_float2(p00, p01));
            int off1 = r1 * 128 + ((nt ^ (r1 & 7)) << 4) + t * 4;
            *(__half2*)(sm + A_PH + off1) = __float22half2_rn(make_float2(p10, p11));
        }
        s0 += __shfl_xor_sync(0xffffffffu, s0, 1);
        s0 += __shfl_xor_sync(0xffffffffu, s0, 2);
        s1 += __shfl_xor_sync(0xffffffffu, s1, 1);
        s1 += __shfl_xor_sync(0xffffffffu, s1, 2);
        l0 = l0 * alpha0 + s0;
        l1 = l1 * alpha1 + s1;
        __syncwarp();

        // ---- rescale O, then O += P @ V (fp16x2) ----
#pragma unroll
        for (int nt = 0; nt < 16; ++nt) {
            acc_o[nt][0] *= alpha0; acc_o[nt][1] *= alpha0;
            acc_o[nt][2] *= alpha1; acc_o[nt][3] *= alpha1;
        }
#pragma unroll
        for (int ks = 0; ks < 4; ++ks) {
            uint32_t ph[4];
            {
                int rowi = wm * 16 + (lane & 15);
                int c = 2 * ks + (lane >> 4);
                uint32_t pd = smem_u32(sm + A_PH + rowi * 128 + ((c ^ (rowi & 7)) << 4));
                LDSM_X4(ph[0], ph[1], ph[2], ph[3], pd);
            }
#pragma unroll
            for (int pr = 0; pr < 8; ++pr) {
                int vk = ks * 16 + (lane & 15);
                int vc = pr * 2 + (lane >> 4);
                uint32_t vd = smem_u32(sm + A_VH + vk * 256 + ((vc ^ (vk & 7)) << 4));
                uint32_t b0, b1, b2, b3, c0, c1, c2, c3;
                LDSM_X4_T(b0, b1, b2, b3, vd);
                LDSM_X4_T(c0, c1, c2, c3, vd + (A_VL - A_VH));
                int nt0 = 2 * pr, nt1 = 2 * pr + 1;
                MMA16816(acc_o[nt0], ph[0], ph[1], ph[2], ph[3], c0, c1);
                MMA16816(acc_o[nt0], ph[0], ph[1], ph[2], ph[3], b0, b1);
                MMA16816(acc_o[nt1], ph[0], ph[1], ph[2], ph[3], c2, c3);
                MMA16816(acc_o[nt1], ph[0], ph[1], ph[2], ph[3], b2, b3);
            }
        }
        __syncthreads();
    }

    // ---- output: fp16 (h only) ----
    float inv0 = 1.f / l0;
    float inv1 = 1.f / l1;
#pragma unroll
    for (int nt = 0; nt < 16; ++nt) {
        int col = nt * 8 + 2 * t;
        *(__half2*)(ath + (size_t)(q0 + r0) * AW + hh_ * DV + col) =
            __float22half2_rn(make_float2(acc_o[nt][0] * inv0, acc_o[nt][1] * inv0));
        *(__half2*)(ath + (size_t)(q0 + r1) * AW + hh_ * DV + col) =
            __float22half2_rn(make_float2(acc_o[nt][2] * inv1, acc_o[nt][3] * inv1));
    }
}

// ---------------- launch ----------------
extern "C" void kernel_launch(void* const* d_in, const int* in_sizes, int n_in,
                              void* d_out, int out_size)
{
    const float* hidden = (const float*)d_in[0];
    const float* cosb   = (const float*)d_in[1];
    const float* sinb   = (const float*)d_in[2];
    const float* w_qa   = (const float*)d_in[3];
    const float* gm_qa  = (const float*)d_in[4];
    const float* w_qb   = (const float*)d_in[5];
    const float* w_kva  = (const float*)d_in[6];
    const float* gm_kva = (const float*)d_in[7];
    const float* w_kvb  = (const float*)d_in[8];
    const float* w_o    = (const float*)d_in[9];
    float* out = (float*)d_out;

    float *qc, *qf;
    __half *hidh, *wfh, *wfl, *qbh, *qbl, *kvbh, *kvbl, *oh, *ol;
    __half *qanh, *cknh, *qsh, *qsl, *kvh, *kvl, *kpeh, *kpel, *ath;
    cudaGetSymbolAddress((void**)&qc,   g_qc_s);
    cudaGetSymbolAddress((void**)&qf,   g_q_s);
    cudaGetSymbolAddress((void**)&hidh, g_hid_h);
    cudaGetSymbolAddress((void**)&wfh,  g_wf_h);  cudaGetSymbolAddress((void**)&wfl,  g_wf_l);
    cudaGetSymbolAddress((void**)&qbh,  g_qb_h);  cudaGetSymbolAddress((void**)&qbl,  g_qb_l);
    cudaGetSymbolAddress((void**)&kvbh, g_kvb_h); cudaGetSymbolAddress((void**)&kvbl, g_kvb_l);
    cudaGetSymbolAddress((void**)&oh,   g_o_h);   cudaGetSymbolAddress((void**)&ol,   g_o_l);
    cudaGetSymbolAddress((void**)&qanh, g_qan_h);
    cudaGetSymbolAddress((void**)&cknh, g_ckn_h);
    cudaGetSymbolAddress((void**)&qsh,  g_qs_h);  cudaGetSymbolAddress((void**)&qsl,  g_qs_l);
    cudaGetSymbolAddress((void**)&kvh,  g_kv_h);  cudaGetSymbolAddress((void**)&kvl,  g_kv_l);
    cudaGetSymbolAddress((void**)&kpeh, g_kpe_h); cudaGetSymbolAddress((void**)&kpel, g_kpe_l);
    cudaGetSymbolAddress((void**)&ath,  g_at_h);

    static bool attr_done = false;
    if (!attr_done) {
        cudaFuncSetAttribute(attn_mma, cudaFuncAttributeMaxDynamicSharedMemorySize,
                             ATTN_SMEM_BYTES);
        cudaFuncSetAttribute(gemm_h<false>, cudaFuncAttributeMaxDynamicSharedMemorySize,
                             GEMM_SMEM_BYTES);
        cudaFuncSetAttribute(gemm_h<true>, cudaFuncAttributeMaxDynamicSharedMemorySize,
                             GEMM_SMEM_BYTES);
        attr_done = true;
    }

    // all conversions / splits in one launch
    prep_kernel<<<PREP_BLOCKS, 256>>>(hidden, w_qa, w_kva, w_qb, w_kvb, w_o,
                                      hidh, wfh, wfl, qbh, qbl, kvbh, kvbl, oh, ol);
    // [qa|ckv] = hidden @ wf  (fp32 out)
    gemm_h<false><<<dim3(FWP / 128, SEQ / 128), 256, GEMM_SMEM_BYTES>>>(
        hidh, HID, wfh, wfl, FWP, qc, ((__half*)0), ((__half*)0), FWP, FW, HID);
    // both rmsnorms
    rmsnorm2_kernel<<<SEQ, 256>>>(qc, gm_qa, gm_kva, qanh, cknh);
    // q = qa_n @ w_qb (fp32 out)
    gemm_h<false><<<dim3(QW / 128, SEQ / 128), 256, GEMM_SMEM_BYTES>>>(
        qanh, QL, qbh, qbl, QW, qf, ((__half*)0), ((__half*)0), QW, QW, QL);
    // kv = ckv_n @ w_kvb (split fp16 out)
    gemm_h<true><<<dim3(KVW / 128, SEQ / 128), 256, GEMM_SMEM_BYTES>>>(
        cknh, KVL, kvbh, kvbl, KVW, ((float*)0), kvh, kvl, KVW, KVW, KVL);
    // rope + q split + kpe
    rope_qsplit_kernel<<<SEQ + 256, 256>>>(qf, qc, qsh, qsl, kpeh, kpel, cosb, sinb);
    // attention (BQ=128)
    attn_mma<<<dim3(SEQ / 128, NH), 256, ATTN_SMEM_BYTES>>>(
        qsh, qsl, kvh, kvl, kpeh, kpel, ath);
    // out = attn @ w_o (fp32 out)
    gemm_h<false><<<dim3(HID / 128, SEQ / 128), 256, GEMM_SMEM_BYTES>>>(
        ath, AW, oh, ol, HID, out, ((__half*)0), ((__half*)0), HID, HID, AW);
}

// round 11
// speedup vs baseline: 6.3399x; 1.0721x over previous
#include <cuda_runtime.h>
#include <cuda_fp16.h>
#include <cuda_bf16.h>
#include <stdint.h>
#include <math.h>

#define SEQ 2048
#define HID 2048
#define NH 16
#define QL 1536
#define KVL 512
#define DN 128
#define DR 64
#define DV 128
#define DQK 192
#define CKVW (KVL + DR)      // 576
#define FW (QL + CKVW)       // 2112
#define FWP 2176             // FW padded to 128
#define QW (NH * DQK)        // 3072
#define KVW (NH * (DN + DV)) // 4096
#define AW (NH * DV)         // 2048

// ---------------- scratch ----------------
__device__ float  g_qc_s [(size_t)SEQ * FWP];
__device__ float  g_q_s  [(size_t)SEQ * QW];
__device__ __half g_hid_h[(size_t)SEQ * HID];
__device__ __half g_wf_h [(size_t)HID * FWP],  g_wf_l [(size_t)HID * FWP];
__device__ __half g_qb_h [(size_t)QL * QW],    g_qb_l [(size_t)QL * QW];
__device__ __half g_kvb_h[(size_t)KVL * KVW],  g_kvb_l[(size_t)KVL * KVW];
__device__ __half g_o_h  [(size_t)AW * HID],   g_o_l  [(size_t)AW * HID];
__device__ __half g_qan_h[(size_t)SEQ * QL];
__device__ __half g_ckn_h[(size_t)SEQ * KVL];
__device__ __half g_qs_h [(size_t)SEQ * QW],   g_qs_l [(size_t)SEQ * QW];
__device__ __half g_kv_h [(size_t)SEQ * KVW],  g_kv_l [(size_t)SEQ * KVW];
__device__ __half g_kpe_h[(size_t)SEQ * DR],   g_kpe_l[(size_t)SEQ * DR];
__device__ __half g_at_h [(size_t)SEQ * AW];

__device__ __forceinline__ uint32_t smem_u32(const void* p) {
    return (uint32_t)__cvta_generic_to_shared(p);
}

#define LDSM_X4(r0, r1, r2, r3, a)                                            \
    asm volatile("ldmatrix.sync.aligned.m8n8.x4.shared.b16 {%0,%1,%2,%3},[%4];" \
                 : "=r"(r0), "=r"(r1), "=r"(r2), "=r"(r3) : "r"(a))
#define LDSM_X2(r0, r1, a)                                                    \
    asm volatile("ldmatrix.sync.aligned.m8n8.x2.shared.b16 {%0,%1},[%2];"     \
                 : "=r"(r0), "=r"(r1) : "r"(a))
#define LDSM_X4_T(r0, r1, r2, r3, a)                                          \
    asm volatile("ldmatrix.sync.aligned.m8n8.x4.trans.shared.b16 {%0,%1,%2,%3},[%4];" \
                 : "=r"(r0), "=r"(r1), "=r"(r2), "=r"(r3) : "r"(a))

#define MMA16816(d, a0, a1, a2, a3, b0, b1)                                   \
    asm volatile("mma.sync.aligned.m16n8k16.row.col.f32.f16.f16.f32 "         \
                 "{%0,%1,%2,%3},{%4,%5,%6,%7},{%8,%9},{%0,%1,%2,%3};"          \
                 : "+f"(d[0]), "+f"(d[1]), "+f"(d[2]), "+f"(d[3])              \
                 : "r"(a0), "r"(a1), "r"(a2), "r"(a3), "r"(b0), "r"(b1))

#define CP_ASYNC16(dst, src)                                                  \
    asm volatile("cp.async.cg.shared.global [%0], [%1], 16;" :: "r"(dst), "l"(src))
#define CP_COMMIT() asm volatile("cp.async.commit_group;" ::: "memory")
#define CP_WAIT1()  asm volatile("cp.async.wait_group 1;" ::: "memory")

__device__ __forceinline__ void split_h2(float x, float y, uint32_t& h, uint32_t& l) {
    __half hx = __float2half_rn(x), hy = __float2half_rn(y);
    __half2 hp = __halves2half2(hx, hy);
    h = *(uint32_t*)&hp;
    __half2 lp = __halves2half2(__float2half_rn(x - __half2float(hx)),
                                __float2half_rn(y - __half2float(hy)));
    l = *(uint32_t*)&lp;
}

// ======== one prep kernel: hconv + all weight splits ========
#define NB1 8192
#define NB2 8704
#define NB3 9216
#define NB4 4096
#define NB5 8192
#define PREP_BLOCKS (NB1 + NB2 + NB3 + NB4 + NB5)

__global__ __launch_bounds__(256) void prep_kernel(
    const float* __restrict__ hidden,
    const float* __restrict__ wqa, const float* __restrict__ wkva,
    const float* __restrict__ wqb, const float* __restrict__ wkvb,
    const float* __restrict__ wo,
    __half* __restrict__ hidh,
    __half* __restrict__ wfh, __half* __restrict__ wfl,
    __half* __restrict__ qbh, __half* __restrict__ qbl,
    __half* __restrict__ kvbh, __half* __restrict__ kvbl,
    __half* __restrict__ oh, __half* __restrict__ ol)
{
    int b = blockIdx.x;
    if (b < NB1) {
        int i = b * 256 + threadIdx.x;
        float2 v = ((const float2*)hidden)[i];
        ((__half2*)hidh)[i] = __float22half2_rn(v);
    } else if (b < NB1 + NB2) {
        int i = (b - NB1) * 256 + threadIdx.x;
        int row = i / (FWP / 2), p = i % (FWP / 2);
        int col = 2 * p;
        float x = 0.f, y = 0.f;
        if (col < QL)      { x = wqa[(size_t)row * QL + col];         y = wqa[(size_t)row * QL + col + 1]; }
        else if (col < FW) { x = wkva[(size_t)row * CKVW + col - QL]; y = wkva[(size_t)row * CKVW + col - QL + 1]; }
        uint32_t hh, ll;
        split_h2(x, y, hh, ll);
        ((uint32_t*)wfh)[i] = hh;
        ((uint32_t*)wfl)[i] = ll;
    } else if (b < NB1 + NB2 + NB3) {
        int i = (b - NB1 - NB2) * 256 + threadIdx.x;
        float2 v = ((const float2*)wqb)[i];
        uint32_t hh, ll;
        split_h2(v.x, v.y, hh, ll);
        ((uint32_t*)qbh)[i] = hh;
        ((uint32_t*)qbl)[i] = ll;
    } else if (b < NB1 + NB2 + NB3 + NB4) {
        int i = (b - NB1 - NB2 - NB3) * 256 + threadIdx.x;
        float2 v = ((const float2*)wkvb)[i];
        uint32_t hh, ll;
        split_h2(v.x, v.y, hh, ll);
        ((uint32_t*)kvbh)[i] = hh;
        ((uint32_t*)kvbl)[i] = ll;
    } else {
        int i = (b - NB1 - NB2 - NB3 - NB4) * 256 + threadIdx.x;
        float2 v = ((const float2*)wo)[i];
        uint32_t hh, ll;
        split_h2(v.x, v.y, hh, ll);
        ((uint32_t*)oh)[i] = hh;
        ((uint32_t*)ol)[i] = ll;
    }
}

// ---------------- both RMSNorms in one kernel ----------------
__global__ __launch_bounds__(256) void rmsnorm2_kernel(
    const float* __restrict__ qc, const float* __restrict__ gqa,
    const float* __restrict__ gkva, __half* __restrict__ qanh,
    __half* __restrict__ cknh)
{
    __shared__ float red[256];
    const float* p = qc + (size_t)blockIdx.x * FWP;
    float s = 0.f;
    for (int i = threadIdx.x; i < QL; i += 256) { float v = p[i]; s += v * v; }
    red[threadIdx.x] = s;
    __syncthreads();
#pragma unroll
    for (int off = 128; off > 0; off >>= 1) {
        if (threadIdx.x < off) red[threadIdx.x] += red[threadIdx.x + off];
        __syncthreads();
    }
    float inv = rsqrtf(red[0] / (float)QL + 1e-6f);
    for (int i = threadIdx.x; i < QL / 2; i += 256) {
        float v0 = p[2 * i] * inv * gqa[2 * i];
        float v1 = p[2 * i + 1] * inv * gqa[2 * i + 1];
        ((__half2*)qanh)[(size_t)blockIdx.x * (QL / 2) + i] = __float22half2_rn(make_float2(v0, v1));
    }
    __syncthreads();
    const float* p2 = p + QL;
    s = 0.f;
    for (int i = threadIdx.x; i < KVL; i += 256) { float v = p2[i]; s += v * v; }
    red[threadIdx.x] = s;
    __syncthreads();
#pragma unroll
    for (int off = 128; off > 0; off >>= 1) {
        if (threadIdx.x < off) red[threadIdx.x] += red[threadIdx.x + off];
        __syncthreads();
    }
    inv = rsqrtf(red[0] / (float)KVL + 1e-6f);
    for (int i = threadIdx.x; i < KVL / 2; i += 256) {
        float v0 = p2[2 * i] * inv * gkva[2 * i];
        float v1 = p2[2 * i + 1] * inv * gkva[2 * i + 1];
        ((__half2*)cknh)[(size_t)blockIdx.x * (KVL / 2) + i] = __float22half2_rn(make_float2(v0, v1));
    }
}

// ======== fp16x2 GEMM: 2-stage ring, 2 CTAs/SM (occupancy fix) ========
#define G_AT 16384
#define G_BT 16384
#define G_STAGE (G_AT + 2 * G_BT)        // 49152
#define GEMM_SMEM_BYTES (2 * G_STAGE)    // 98304 -> 2 CTAs/SM

template <bool SPLIT_OUT>
__global__ __launch_bounds__(256, 2) void gemm_h(
    const __half* __restrict__ Ah, int lda,
    const __half* __restrict__ Bh, const __half* __restrict__ Bl, int ldb,
    float* __restrict__ C, __half* __restrict__ Ch, __half* __restrict__ Cl,
    int ldc, int N, int K)
{
    extern __shared__ char sm[];
    const uint32_t sbase = smem_u32(sm);

    const int tid  = threadIdx.x;
    const int lane = tid & 31, w = tid >> 5;
    const int wm = w & 3, wn = w >> 2;
    const int row0 = blockIdx.y * 128;
    const int col0 = blockIdx.x * 128;

    float acc[2][8][4];
#pragma unroll
    for (int mt = 0; mt < 2; ++mt)
#pragma unroll
        for (int nt = 0; nt < 8; ++nt)
#pragma unroll
            for (int i = 0; i < 4; ++i) acc[mt][nt][i] = 0.f;

    auto do_cp = [&](int stage, int k0) {
        uint32_t sb = sbase + stage * G_STAGE;
#pragma unroll
        for (int i = 0; i < 4; ++i) {
            int idx = i * 256 + tid;
            int r = idx >> 3, u = idx & 7;
            uint32_t off = r * 128 + ((u ^ (r & 7)) << 4);
            CP_ASYNC16(sb + off, Ah + (size_t)(row0 + r) * lda + k0 + u * 8);
        }
#pragma unroll
        for (int i = 0; i < 4; ++i) {
            int idx = i * 256 + tid;
            int r = idx >> 4, u = idx & 15;
            uint32_t off = G_AT + r * 256 + ((u ^ (r & 7)) << 4);
            CP_ASYNC16(sb + off, Bh + (size_t)(k0 + r) * ldb + col0 + u * 8);
            CP_ASYNC16(sb + G_BT + off, Bl + (size_t)(k0 + r) * ldb + col0 + u * 8);
        }
    };

    const int nIter = K >> 6;
    do_cp(0, 0);
    CP_COMMIT();
    if (nIter > 1) do_cp(1, 64);
    CP_COMMIT();

    for (int it = 0; it < nIter; ++it) {
        CP_WAIT1();                       // group(it) complete
        __syncthreads();

        char* base = sm + (it & 1) * G_STAGE;
#pragma unroll
        for (int kg = 0; kg < 4; ++kg) {
            uint32_t ah[2][4];
#pragma unroll
            for (int mt = 0; mt < 2; ++mt) {
                int row = wm * 32 + mt * 16 + (lane & 15);
                int kc = kg * 2 + (lane >> 4);
                uint32_t ad = smem_u32(base + row * 128 + ((kc ^ (row & 7)) << 4));
                LDSM_X4(ah[mt][0], ah[mt][1], ah[mt][2], ah[mt][3], ad);
            }
            uint32_t bh[8][2], bl[8][2];
#pragma unroll
            for (int pr = 0; pr < 4; ++pr) {
                int k = kg * 16 + (lane & 15);
                int nc = wn * 8 + pr * 2 + (lane >> 4);
                uint32_t bd = smem_u32(base + G_AT + k * 256 + ((nc ^ (k & 7)) << 4));
                uint32_t t0, t1, t2, t3;
                LDSM_X4_T(t0, t1, t2, t3, bd);
                bh[2 * pr][0] = t0; bh[2 * pr][1] = t1;
                bh[2 * pr + 1][0] = t2; bh[2 * pr + 1][1] = t3;
                LDSM_X4_T(t0, t1, t2, t3, bd + G_BT);
                bl[2 * pr][0] = t0; bl[2 * pr][1] = t1;
                bl[2 * pr + 1][0] = t2; bl[2 * pr + 1][1] = t3;
            }
#pragma unroll
            for (int mt = 0; mt < 2; ++mt)
#pragma unroll
                for (int nt = 0; nt < 8; ++nt) {
                    MMA16816(acc[mt][nt], ah[mt][0], ah[mt][1], ah[mt][2], ah[mt][3],
                             bl[nt][0], bl[nt][1]);
                    MMA16816(acc[mt][nt], ah[mt][0], ah[mt][1], ah[mt][2], ah[mt][3],
                             bh[nt][0], bh[nt][1]);
                }
        }
        __syncthreads();                  // all warps done reading stage it&1
        if (it + 2 < nIter) {
            do_cp(it & 1, (it + 2) << 6);
            CP_COMMIT();
        }
    }

    const int g = lane >> 2, t = lane & 3;
#pragma unroll
    for (int mt = 0; mt < 2; ++mt) {
        int r = row0 + wm * 32 + mt * 16 + g;
#pragma unroll
        for (int nt = 0; nt < 8; ++nt) {
            int c = col0 + wn * 64 + nt * 8 + 2 * t;
            if (SPLIT_OUT) {
                uint32_t hh, ll;
                split_h2(acc[mt][nt][0], acc[mt][nt][1], hh, ll);
                *(uint32_t*)(Ch + (size_t)r * ldc + c) = hh;
                *(uint32_t*)(Cl + (size_t)r * ldc + c) = ll;
                split_h2(acc[mt][nt][2], acc[mt][nt][3], hh, ll);
                *(uint32_t*)(Ch + (size_t)(r + 8) * ldc + c) = hh;
                *(uint32_t*)(Cl + (size_t)(r + 8) * ldc + c) = ll;
            } else if (c < N) {
                *(float2*)(C + (size_t)r * ldc + c)       = make_float2(acc[mt][nt][0], acc[mt][nt][1]);
                *(float2*)(C + (size_t)(r + 8) * ldc + c) = make_float2(acc[mt][nt][2], acc[mt][nt][3]);
            }
        }
    }
}

// ------- RoPE on q + full q split (smem-staged); kpe in tail blocks -------
__global__ __launch_bounds__(256) void rope_qsplit_kernel(
    const float* __restrict__ qf, const float* __restrict__ qc,
    __half* __restrict__ qsh, __half* __restrict__ qsl,
    __half* __restrict__ kpeh, __half* __restrict__ kpel,
    const float* __restrict__ cosb, const float* __restrict__ sinb)
{
    __shared__ float row[QW];
    int b = blockIdx.x;
    if (b < SEQ) {
        const int s = b;
        const float* src = qf + (size_t)s * QW;
#pragma unroll
        for (int i = 0; i < 3; ++i) {
            int idx = (i * 256 + threadIdx.x) * 4;
            *(float4*)(row + idx) = *(const float4*)(src + idx);
        }
        __syncthreads();
        float y0[2], y1[2];
        int hd[2], ln[2];
#pragma unroll
        for (int e = 0; e < 2; ++e) {
            int item = threadIdx.x + e * 256;
            hd[e] = item >> 5; ln[e] = item & 31;
            float c  = cosb[s * DR + ln[e]];
            float sn = sinb[s * DR + ln[e]];
            float x0 = row[hd[e] * DQK + DN + 2 * ln[e]];
            float x1 = row[hd[e] * DQK + DN + 2 * ln[e] + 1];
            y0[e] = x0 * c - x1 * sn;
            y1[e] = x1 * c + x0 * sn;
        }
        __syncthreads();
#pragma unroll
        for (int e = 0; e < 2; ++e) {
            row[hd[e] * DQK + DN + ln[e]]      = y0[e];
            row[hd[e] * DQK + DN + ln[e] + 32] = y1[e];
        }
        __syncthreads();
#pragma unroll
        for (int i = 0; i < 6; ++i) {
            int p = i * 256 + threadIdx.x;
            uint32_t hh, ll;
            split_h2(row[2 * p], row[2 * p + 1], hh, ll);
            ((uint32_t*)qsh)[(size_t)s * (QW / 2) + p] = hh;
            ((uint32_t*)qsl)[(size_t)s * (QW / 2) + p] = ll;
        }
    } else {
        int wr = (b - SEQ) * 8 + (threadIdx.x >> 5);
        int lane = threadIdx.x & 31;
        const float* x = qc + (size_t)wr * FWP + QL + KVL;
        float c  = cosb[wr * DR + lane];
        float sn = sinb[wr * DR + lane];
        float x0 = x[2 * lane], x1 = x[2 * lane + 1];
        float z0 = x0 * c - x1 * sn;
        float z1 = x1 * c + x0 * sn;
        __half h0 = __float2half_rn(z0);
        __half h1 = __float2half_rn(z1);
        kpeh[wr * DR + lane]      = h0;
        kpel[wr * DR + lane]      = __float2half_rn(z0 - __half2float(h0));
        kpeh[wr * DR + lane + 32] = h1;
        kpel[wr * DR + lane + 32] = __float2half_rn(z1 - __half2float(h1));
    }
}

// ==== flash attention BQ=128/BK=64: QK fp16x3, PV fp16x2, reg softmax ====
#define A_QH 0
#define A_QL 49152
#define A_KH 98304
#define A_KL 122880
#define A_VH 147456
#define A_VL 163840
#define A_PH 180224
#define ATTN_SMEM_BYTES 196608

__global__ __launch_bounds__(256) void attn_mma(
    const __half* __restrict__ qh, const __half* __restrict__ ql,
    const __half* __restrict__ kvh, const __half* __restrict__ kvl,
    const __half* __restrict__ kpeh, const __half* __restrict__ kpel,
    __half* __restrict__ ath)
{
    extern __shared__ char sm[];

    const int tid = threadIdx.x, lane = tid & 31, wm = tid >> 5;
    const int qb = gridDim.x - 1 - blockIdx.x;
    const int hh_ = blockIdx.y;
    const int q0 = qb * 128;
    const float scale = rsqrtf((float)DQK);

#pragma unroll
    for (int i = 0; i < 12; ++i) {
        int idx = i * 256 + tid;
        int r = idx / 24, u = idx % 24;
        int off = r * 384 + ((u ^ (r & 7)) << 4);
        const size_t go = (size_t)(q0 + r) * QW + hh_ * DQK + u * 8;
        *(uint4*)(sm + A_QH + off) = *(const uint4*)(qh + go);
        *(uint4*)(sm + A_QL + off) = *(const uint4*)(ql + go);
    }

    const int g = lane >> 2, t = lane & 3;
    const int r0 = wm * 16 + g, r1 = r0 + 8;

    float m0 = -1e30f, m1 = -1e30f, l0 = 0.f, l1 = 0.f;
    float acc_o[16][4];
#pragma unroll
    for (int nt = 0; nt < 16; ++nt)
#pragma unroll
        for (int i = 0; i < 4; ++i) acc_o[nt][i] = 0.f;

    __syncthreads();

    const int nkb = 2 * qb + 2;
    for (int kb = 0; kb < nkb; ++kb) {
        const int k0 = kb * 64;

#pragma unroll
        for (int i = 0; i < 6; ++i) {
            int idx = i * 256 + tid;
            int r = idx / 24, u = idx % 24;
            int off = r * 384 + ((u ^ (r & 7)) << 4);
            if (u < 16) {
                const size_t go = (size_t)(k0 + r) * KVW + hh_ * (DN + DV) + u * 8;
                *(uint4*)(sm + A_KH + off) = *(const uint4*)(kvh + go);
                *(uint4*)(sm + A_KL + off) = *(const uint4*)(kvl + go);
            } else {
                const size_t go = (size_t)(k0 + r) * DR + (u - 16) * 8;
                *(uint4*)(sm + A_KH + off) = *(const uint4*)(kpeh + go);
                *(uint4*)(sm + A_KL + off) = *(const uint4*)(kpel + go);
            }
        }
#pragma unroll
        for (int i = 0; i < 4; ++i) {
            int idx = i * 256 + tid;
            int r = idx >> 4, u = idx & 15;
            int off = r * 256 + ((u ^ (r & 7)) << 4);
            const size_t go = (size_t)(k0 + r) * KVW + hh_ * (DN + DV) + DN + u * 8;
            *(uint4*)(sm + A_VH + off) = *(const uint4*)(kvh + go);
            *(uint4*)(sm + A_VL + off) = *(const uint4*)(kvl + go);
        }
        __syncthreads();

        float acc_s[8][4];
#pragma unroll
        for (int nt = 0; nt < 8; ++nt)
#pragma unroll
            for (int i = 0; i < 4; ++i) acc_s[nt][i] = 0.f;

#pragma unroll
        for (int ks = 0; ks < 12; ++ks) {
            uint32_t qfh[4], qfl[4];
            {
                int rowi = wm * 16 + (lane & 15);
                int c = 2 * ks + (lane >> 4);
                uint32_t ad = smem_u32(sm + rowi * 384 + ((c ^ (rowi & 7)) << 4));
                LDSM_X4(qfh[0], qfh[1], qfh[2], qfh[3], ad + A_QH);
                LDSM_X4(qfl[0], qfl[1], qfl[2], qfl[3], ad + (A_QL - A_QH));
            }
#pragma unroll
            for (int nt = 0; nt < 8; ++nt) {
                int krow = nt * 8 + (lane & 7);
                int kc = 2 * ks + ((lane >> 3) & 1);
                uint32_t kd = smem_u32(sm + A_KH + krow * 384 + ((kc ^ (krow & 7)) << 4));
                uint32_t kh0, kh1, kl0, kl1;
                LDSM_X2(kh0, kh1, kd);
                LDSM_X2(kl0, kl1, kd + (A_KL - A_KH));
                MMA16816(acc_s[nt], qfh[0], qfh[1], qfh[2], qfh[3], kl0, kl1);
                MMA16816(acc_s[nt], qfl[0], qfl[1], qfl[2], qfl[3], kh0, kh1);
                MMA16816(acc_s[nt], qfh[0], qfh[1], qfh[2], qfh[3], kh0, kh1);
            }
        }

        float vm0 = -1e30f, vm1 = -1e30f;
#pragma unroll
        for (int nt = 0; nt < 8; ++nt) {
            int col = k0 + nt * 8 + 2 * t;
            float v00 = acc_s[nt][0] * scale, v01 = acc_s[nt][1] * scale;
            float v10 = acc_s[nt][2] * scale, v11 = acc_s[nt][3] * scale;
            if (col     > q0 + r0) v00 = -1e30f;
            if (col + 1 > q0 + r0) v01 = -1e30f;
            if (col     > q0 + r1) v10 = -1e30f;
            if (col + 1 > q0 + r1) v11 = -1e30f;
            acc_s[nt][0] = v00; acc_s[nt][1] = v01;
            acc_s[nt][2] = v10; acc_s[nt][3] = v11;
            vm0 = fmaxf(vm0, fmaxf(v00, v01));
            vm1 = fmaxf(vm1, fmaxf(v10, v11));
        }
        vm0 = fmaxf(vm0, __shfl_xor_sync(0xffffffffu, vm0, 1));
        vm0 = fmaxf(vm0, __shfl_xor_sync(0xffffffffu, vm0, 2));
        vm1 = fmaxf(vm1, __shfl_xor_sync(0xffffffffu, vm1, 1));
        vm1 = fmaxf(vm1, __shfl_xor_sync(0xffffffffu, vm1, 2));

        float mnew0 = fmaxf(m0, vm0);
        float mnew1 = fmaxf(m1, vm1);
        float alpha0 = __expf(m0 - mnew0);
        float alpha1 = __expf(m1 - mnew1);
        m0 = mnew0; m1 = mnew1;

        float s0 = 0.f, s1 = 0.f;
#pragma unroll
        for (int nt = 0; nt < 8; ++nt) {
            float p00 = __expf(acc_s[nt][0] - mnew0);
            float p01 = __expf(acc_s[nt][1] - mnew0);
            float p10 = __expf(acc_s[nt][2] - mnew1);
            float p11 = __expf(acc_s[nt][3] - mnew1);
            s0 += p00 + p01;
            s1 += p10 + p11;
            int off0 = r0 * 128 + ((nt ^ (r0 & 7)) << 4) + t * 4;
            *(__half2*)(sm + A_PH + off0) = __float22half2_rn(make_float2(p00, p01));
            int off1 = r1 * 128 + ((nt ^ (r1 & 7)) << 4) + t * 4;
            *(__half2*)(sm + A_PH + off1) = __float22half2_rn(make_float2(p10, p11));
        }
        s0 += __shfl_xor_sync(0xffffffffu, s0, 1);
        s0 += __shfl_xor_sync(0xffffffffu, s0, 2);
        s1 += __shfl_xor_sync(0xffffffffu, s1, 1);
        s1 += __shfl_xor_sync(0xffffffffu, s1, 2);
        l0 = l0 * alpha0 + s0;
        l1 = l1 * alpha1 + s1;
        __syncwarp();

#pragma unroll
        for (int nt = 0; nt < 16; ++nt) {
            acc_o[nt][0] *= alpha0; acc_o[nt][1] *= alpha0;
            acc_o[nt][2] *= alpha1; acc_o[nt][3] *= alpha1;
        }
#pragma unroll
        for (int ks = 0; ks < 4; ++ks) {
            uint32_t ph[4];
            {
                int rowi = wm * 16 + (lane & 15);
                int c = 2 * ks + (lane >> 4);
                uint32_t pd = smem_u32(sm + A_PH + rowi * 128 + ((c ^ (rowi & 7)) << 4));
                LDSM_X4(ph[0], ph[1], ph[2], ph[3], pd);
            }
#pragma unroll
            for (int pr = 0; pr < 8; ++pr) {
                int vk = ks * 16 + (lane & 15);
                int vc = pr * 2 + (lane >> 4);
                uint32_t vd = smem_u32(sm + A_VH + vk * 256 + ((vc ^ (vk & 7)) << 4));
                uint32_t b0, b1, b2, b3, c0, c1, c2, c3;
                LDSM_X4_T(b0, b1, b2, b3, vd);
                LDSM_X4_T(c0, c1, c2, c3, vd + (A_VL - A_VH));
                int nt0 = 2 * pr, nt1 = 2 * pr + 1;
                MMA16816(acc_o[nt0], ph[0], ph[1], ph[2], ph[3], c0, c1);
                MMA16816(acc_o[nt0], ph[0], ph[1], ph[2], ph[3], b0, b1);
                MMA16816(acc_o[nt1], ph[0], ph[1], ph[2], ph[3], c2, c3);
                MMA16816(acc_o[nt1], ph[0], ph[1], ph[2], ph[3], b2, b3);
            }
        }
        __syncthreads();
    }

    float inv0 = 1.f / l0;
    float inv1 = 1.f / l1;
#pragma unroll
    for (int nt = 0; nt < 16; ++nt) {
        int col = nt * 8 + 2 * t;
        *(__half2*)(ath + (size_t)(q0 + r0) * AW + hh_ * DV + col) =
            __float22half2_rn(make_float2(acc_o[nt][0] * inv0, acc_o[nt][1] * inv0));
        *(__half2*)(ath + (size_t)(q0 + r1) * AW + hh_ * DV + col) =
            __float22half2_rn(make_float2(acc_o[nt][2] * inv1, acc_o[nt][3] * inv1));
    }
}

// ---------------- launch ----------------
extern "C" void kernel_launch(void* const* d_in, const int* in_sizes, int n_in,
                              void* d_out, int out_size)
{
    const float* hidden = (const float*)d_in[0];
    const float* cosb   = (const float*)d_in[1];
    const float* sinb   = (const float*)d_in[2];
    const float* w_qa   = (const float*)d_in[3];
    const float* gm_qa  = (const float*)d_in[4];
    const float* w_qb   = (const float*)d_in[5];
    const float* w_kva  = (const float*)d_in[6];
    const float* gm_kva = (const float*)d_in[7];
    const float* w_kvb  = (const float*)d_in[8];
    const float* w_o    = (const float*)d_in[9];
    float* out = (float*)d_out;

    float *qc, *qf;
    __half *hidh, *wfh, *wfl, *qbh, *qbl, *kvbh, *kvbl, *oh, *ol;
    __half *qanh, *cknh, *qsh, *qsl, *kvh, *kvl, *kpeh, *kpel, *ath;
    cudaGetSymbolAddress((void**)&qc,   g_qc_s);
    cudaGetSymbolAddress((void**)&qf,   g_q_s);
    cudaGetSymbolAddress((void**)&hidh, g_hid_h);
    cudaGetSymbolAddress((void**)&wfh,  g_wf_h);  cudaGetSymbolAddress((void**)&wfl,  g_wf_l);
    cudaGetSymbolAddress((void**)&qbh,  g_qb_h);  cudaGetSymbolAddress((void**)&qbl,  g_qb_l);
    cudaGetSymbolAddress((void**)&kvbh, g_kvb_h); cudaGetSymbolAddress((void**)&kvbl, g_kvb_l);
    cudaGetSymbolAddress((void**)&oh,   g_o_h);   cudaGetSymbolAddress((void**)&ol,   g_o_l);
    cudaGetSymbolAddress((void**)&qanh, g_qan_h);
    cudaGetSymbolAddress((void**)&cknh, g_ckn_h);
    cudaGetSymbolAddress((void**)&qsh,  g_qs_h);  cudaGetSymbolAddress((void**)&qsl,  g_qs_l);
    cudaGetSymbolAddress((void**)&kvh,  g_kv_h);  cudaGetSymbolAddress((void**)&kvl,  g_kv_l);
    cudaGetSymbolAddress((void**)&kpeh, g_kpe_h); cudaGetSymbolAddress((void**)&kpel, g_kpe_l);
    cudaGetSymbolAddress((void**)&ath,  g_at_h);

    static bool attr_done = false;
    if (!attr_done) {
        cudaFuncSetAttribute(attn_mma, cudaFuncAttributeMaxDynamicSharedMemorySize,
                             ATTN_SMEM_BYTES);
        cudaFuncSetAttribute(gemm_h<false>, cudaFuncAttributeMaxDynamicSharedMemorySize,
                             GEMM_SMEM_BYTES);
        cudaFuncSetAttribute(gemm_h<true>, cudaFuncAttributeMaxDynamicSharedMemorySize,
                             GEMM_SMEM_BYTES);
        attr_done = true;
    }

    prep_kernel<<<PREP_BLOCKS, 256>>>(hidden, w_qa, w_kva, w_qb, w_kvb, w_o,
                                      hidh, wfh, wfl, qbh, qbl, kvbh, kvbl, oh, ol);
    gemm_h<false><<<dim3(FWP / 128, SEQ / 128), 256, GEMM_SMEM_BYTES>>>(
        hidh, HID, wfh, wfl, FWP, qc, ((__half*)0), ((__half*)0), FWP, FW, HID);
    rmsnorm2_kernel<<<SEQ, 256>>>(qc, gm_qa, gm_kva, qanh, cknh);
    gemm_h<false><<<dim3(QW / 128, SEQ / 128), 256, GEMM_SMEM_BYTES>>>(
        qanh, QL, qbh, qbl, QW, qf, ((__half*)0), ((__half*)0), QW, QW, QL);
    gemm_h<true><<<dim3(KVW / 128, SEQ / 128), 256, GEMM_SMEM_BYTES>>>(
        cknh, KVL, kvbh, kvbl, KVW, ((float*)0), kvh, kvl, KVW, KVW, KVL);
    rope_qsplit_kernel<<<SEQ + 256, 256>>>(qf, qc, qsh, qsl, kpeh, kpel, cosb, sinb);
    attn_mma<<<dim3(SEQ / 128, NH), 256, ATTN_SMEM_BYTES>>>(
        qsh, qsl, kvh, kvl, kpeh, kpel, ath);
    gemm_h<false><<<dim3(HID / 128, SEQ / 128), 256, GEMM_SMEM_BYTES>>>(
        ath, AW, oh, ol, HID, out, ((__half*)0), ((__half*)0), HID, HID, AW);
}

// round 12
// speedup vs baseline: 6.5357x; 1.0309x over previous
#include <cuda_runtime.h>
#include <cuda_fp16.h>
#include <cuda_bf16.h>
#include <stdint.h>
#include <math.h>

#define SEQ 2048
#define HID 2048
#define NH 16
#define QL 1536
#define KVL 512
#define DN 128
#define DR 64
#define DV 128
#define DQK 192
#define CKVW (KVL + DR)      // 576
#define FW (QL + CKVW)       // 2112
#define FWP 2176
#define QW (NH * DQK)        // 3072
#define KVW (NH * (DN + DV)) // 4096
#define AW (NH * DV)         // 2048

// ---------------- scratch ----------------
__device__ float  g_qc_s [(size_t)SEQ * FWP];
__device__ float  g_q_s  [(size_t)SEQ * QW];
__device__ __half g_hid_h[(size_t)SEQ * HID];
__device__ __half g_wf_h [(size_t)HID * FWP],  g_wf_l [(size_t)HID * FWP];
__device__ __half g_qb_h [(size_t)QL * QW],    g_qb_l [(size_t)QL * QW];
__device__ __half g_kvb_h[(size_t)KVL * KVW],  g_kvb_l[(size_t)KVL * KVW];
__device__ __half g_o_h  [(size_t)AW * HID],   g_o_l  [(size_t)AW * HID];
__device__ __half g_qan_h[(size_t)SEQ * QL];
__device__ __half g_ckn_h[(size_t)SEQ * KVL];
__device__ __half g_qs_h [(size_t)SEQ * QW],   g_qs_l [(size_t)SEQ * QW];
__device__ __half g_kv_h [(size_t)SEQ * KVW],  g_kv_l [(size_t)SEQ * KVW];
__device__ __half g_kpe_h[(size_t)SEQ * DR],   g_kpe_l[(size_t)SEQ * DR];
__device__ __half g_at_h [(size_t)SEQ * AW];

__device__ __forceinline__ uint32_t smem_u32(const void* p) {
    return (uint32_t)__cvta_generic_to_shared(p);
}

#define LDSM_X4(r0, r1, r2, r3, a)                                            \
    asm volatile("ldmatrix.sync.aligned.m8n8.x4.shared.b16 {%0,%1,%2,%3},[%4];" \
                 : "=r"(r0), "=r"(r1), "=r"(r2), "=r"(r3) : "r"(a))
#define LDSM_X2(r0, r1, a)                                                    \
    asm volatile("ldmatrix.sync.aligned.m8n8.x2.shared.b16 {%0,%1},[%2];"     \
                 : "=r"(r0), "=r"(r1) : "r"(a))
#define LDSM_X4_T(r0, r1, r2, r3, a)                                          \
    asm volatile("ldmatrix.sync.aligned.m8n8.x4.trans.shared.b16 {%0,%1,%2,%3},[%4];" \
                 : "=r"(r0), "=r"(r1), "=r"(r2), "=r"(r3) : "r"(a))

#define MMA16816(d, a0, a1, a2, a3, b0, b1)                                   \
    asm volatile("mma.sync.aligned.m16n8k16.row.col.f32.f16.f16.f32 "         \
                 "{%0,%1,%2,%3},{%4,%5,%6,%7},{%8,%9},{%0,%1,%2,%3};"          \
                 : "+f"(d[0]), "+f"(d[1]), "+f"(d[2]), "+f"(d[3])              \
                 : "r"(a0), "r"(a1), "r"(a2), "r"(a3), "r"(b0), "r"(b1))

#define CP_ASYNC16(dst, src)                                                  \
    asm volatile("cp.async.cg.shared.global [%0], [%1], 16;" :: "r"(dst), "l"(src))
#define CP_COMMIT() asm volatile("cp.async.commit_group;" ::: "memory")
#define CP_WAIT1()  asm volatile("cp.async.wait_group 1;" ::: "memory")
#define CP_WAIT0()  asm volatile("cp.async.wait_group 0;" ::: "memory")

__device__ __forceinline__ void split_h2(float x, float y, uint32_t& h, uint32_t& l) {
    __half hx = __float2half_rn(x), hy = __float2half_rn(y);
    __half2 hp = __halves2half2(hx, hy);
    h = *(uint32_t*)&hp;
    __half2 lp = __halves2half2(__float2half_rn(x - __half2float(hx)),
                                __float2half_rn(y - __half2float(hy)));
    l = *(uint32_t*)&lp;
}

// ======== one prep kernel ========
#define NB1 8192
#define NB2 8704
#define NB3 9216
#define NB4 4096
#define NB5 8192
#define PREP_BLOCKS (NB1 + NB2 + NB3 + NB4 + NB5)

__global__ __launch_bounds__(256) void prep_kernel(
    const float* __restrict__ hidden,
    const float* __restrict__ wqa, const float* __restrict__ wkva,
    const float* __restrict__ wqb, const float* __restrict__ wkvb,
    const float* __restrict__ wo,
    __half* __restrict__ hidh,
    __half* __restrict__ wfh, __half* __restrict__ wfl,
    __half* __restrict__ qbh, __half* __restrict__ qbl,
    __half* __restrict__ kvbh, __half* __restrict__ kvbl,
    __half* __restrict__ oh, __half* __restrict__ ol)
{
    int b = blockIdx.x;
    if (b < NB1) {
        int i = b * 256 + threadIdx.x;
        float2 v = ((const float2*)hidden)[i];
        ((__half2*)hidh)[i] = __float22half2_rn(v);
    } else if (b < NB1 + NB2) {
        int i = (b - NB1) * 256 + threadIdx.x;
        int row = i / (FWP / 2), p = i % (FWP / 2);
        int col = 2 * p;
        float x = 0.f, y = 0.f;
        if (col < QL)      { x = wqa[(size_t)row * QL + col];         y = wqa[(size_t)row * QL + col + 1]; }
        else if (col < FW) { x = wkva[(size_t)row * CKVW + col - QL]; y = wkva[(size_t)row * CKVW + col - QL + 1]; }
        uint32_t hh, ll;
        split_h2(x, y, hh, ll);
        ((uint32_t*)wfh)[i] = hh;
        ((uint32_t*)wfl)[i] = ll;
    } else if (b < NB1 + NB2 + NB3) {
        int i = (b - NB1 - NB2) * 256 + threadIdx.x;
        float2 v = ((const float2*)wqb)[i];
        uint32_t hh, ll;
        split_h2(v.x, v.y, hh, ll);
        ((uint32_t*)qbh)[i] = hh;
        ((uint32_t*)qbl)[i] = ll;
    } else if (b < NB1 + NB2 + NB3 + NB4) {
        int i = (b - NB1 - NB2 - NB3) * 256 + threadIdx.x;
        float2 v = ((const float2*)wkvb)[i];
        uint32_t hh, ll;
        split_h2(v.x, v.y, hh, ll);
        ((uint32_t*)kvbh)[i] = hh;
        ((uint32_t*)kvbl)[i] = ll;
    } else {
        int i = (b - NB1 - NB2 - NB3 - NB4) * 256 + threadIdx.x;
        float2 v = ((const float2*)wo)[i];
        uint32_t hh, ll;
        split_h2(v.x, v.y, hh, ll);
        ((uint32_t*)oh)[i] = hh;
        ((uint32_t*)ol)[i] = ll;
    }
}

// ---------------- both RMSNorms ----------------
__global__ __launch_bounds__(256) void rmsnorm2_kernel(
    const float* __restrict__ qc, const float* __restrict__ gqa,
    const float* __restrict__ gkva, __half* __restrict__ qanh,
    __half* __restrict__ cknh)
{
    __shared__ float red[256];
    const float* p = qc + (size_t)blockIdx.x * FWP;
    float s = 0.f;
    for (int i = threadIdx.x; i < QL; i += 256) { float v = p[i]; s += v * v; }
    red[threadIdx.x] = s;
    __syncthreads();
#pragma unroll
    for (int off = 128; off > 0; off >>= 1) {
        if (threadIdx.x < off) red[threadIdx.x] += red[threadIdx.x + off];
        __syncthreads();
    }
    float inv = rsqrtf(red[0] / (float)QL + 1e-6f);
    for (int i = threadIdx.x; i < QL / 2; i += 256) {
        float v0 = p[2 * i] * inv * gqa[2 * i];
        float v1 = p[2 * i + 1] * inv * gqa[2 * i + 1];
        ((__half2*)qanh)[(size_t)blockIdx.x * (QL / 2) + i] = __float22half2_rn(make_float2(v0, v1));
    }
    __syncthreads();
    const float* p2 = p + QL;
    s = 0.f;
    for (int i = threadIdx.x; i < KVL; i += 256) { float v = p2[i]; s += v * v; }
    red[threadIdx.x] = s;
    __syncthreads();
#pragma unroll
    for (int off = 128; off > 0; off >>= 1) {
        if (threadIdx.x < off) red[threadIdx.x] += red[threadIdx.x + off];
        __syncthreads();
    }
    inv = rsqrtf(red[0] / (float)KVL + 1e-6f);
    for (int i = threadIdx.x; i < KVL / 2; i += 256) {
        float v0 = p2[2 * i] * inv * gkva[2 * i];
        float v1 = p2[2 * i + 1] * inv * gkva[2 * i + 1];
        ((__half2*)cknh)[(size_t)blockIdx.x * (KVL / 2) + i] = __float22half2_rn(make_float2(v0, v1));
    }
}

// ======== fp16x2 GEMM core (2-stage ring, 2 CTAs/SM) ========
#define G_AT 16384
#define G_BT 16384
#define G_STAGE (G_AT + 2 * G_BT)        // 49152
#define GEMM_SMEM_BYTES (2 * G_STAGE)    // 98304

__device__ __forceinline__ void gemm_core(
    const __half* __restrict__ Ah, int lda,
    const __half* __restrict__ Bh, const __half* __restrict__ Bl, int ldb,
    float* __restrict__ C, __half* __restrict__ Ch, __half* __restrict__ Cl,
    int ldc, int N, int K, int row0, int col0, bool split_out, char* sm)
{
    const uint32_t sbase = smem_u32(sm);
    const int tid  = threadIdx.x;
    const int lane = tid & 31, w = tid >> 5;
    const int wm = w & 3, wn = w >> 2;

    float acc[2][8][4];
#pragma unroll
    for (int mt = 0; mt < 2; ++mt)
#pragma unroll
        for (int nt = 0; nt < 8; ++nt)
#pragma unroll
            for (int i = 0; i < 4; ++i) acc[mt][nt][i] = 0.f;

    auto do_cp = [&](int stage, int k0) {
        uint32_t sb = sbase + stage * G_STAGE;
#pragma unroll
        for (int i = 0; i < 4; ++i) {
            int idx = i * 256 + tid;
            int r = idx >> 3, u = idx & 7;
            uint32_t off = r * 128 + ((u ^ (r & 7)) << 4);
            CP_ASYNC16(sb + off, Ah + (size_t)(row0 + r) * lda + k0 + u * 8);
        }
#pragma unroll
        for (int i = 0; i < 4; ++i) {
            int idx = i * 256 + tid;
            int r = idx >> 4, u = idx & 15;
            uint32_t off = G_AT + r * 256 + ((u ^ (r & 7)) << 4);
            CP_ASYNC16(sb + off, Bh + (size_t)(k0 + r) * ldb + col0 + u * 8);
            CP_ASYNC16(sb + G_BT + off, Bl + (size_t)(k0 + r) * ldb + col0 + u * 8);
        }
    };

    const int nIter = K >> 6;
    do_cp(0, 0);
    CP_COMMIT();
    if (nIter > 1) do_cp(1, 64);
    CP_COMMIT();

    for (int it = 0; it < nIter; ++it) {
        CP_WAIT1();
        __syncthreads();

        char* base = sm + (it & 1) * G_STAGE;
#pragma unroll
        for (int kg = 0; kg < 4; ++kg) {
            uint32_t ah[2][4];
#pragma unroll
            for (int mt = 0; mt < 2; ++mt) {
                int row = wm * 32 + mt * 16 + (lane & 15);
                int kc = kg * 2 + (lane >> 4);
                uint32_t ad = smem_u32(base + row * 128 + ((kc ^ (row & 7)) << 4));
                LDSM_X4(ah[mt][0], ah[mt][1], ah[mt][2], ah[mt][3], ad);
            }
            uint32_t bh[8][2], bl[8][2];
#pragma unroll
            for (int pr = 0; pr < 4; ++pr) {
                int k = kg * 16 + (lane & 15);
                int nc = wn * 8 + pr * 2 + (lane >> 4);
                uint32_t bd = smem_u32(base + G_AT + k * 256 + ((nc ^ (k & 7)) << 4));
                uint32_t t0, t1, t2, t3;
                LDSM_X4_T(t0, t1, t2, t3, bd);
                bh[2 * pr][0] = t0; bh[2 * pr][1] = t1;
                bh[2 * pr + 1][0] = t2; bh[2 * pr + 1][1] = t3;
                LDSM_X4_T(t0, t1, t2, t3, bd + G_BT);
                bl[2 * pr][0] = t0; bl[2 * pr][1] = t1;
                bl[2 * pr + 1][0] = t2; bl[2 * pr + 1][1] = t3;
            }
#pragma unroll
            for (int mt = 0; mt < 2; ++mt)
#pragma unroll
                for (int nt = 0; nt < 8; ++nt) {
                    MMA16816(acc[mt][nt], ah[mt][0], ah[mt][1], ah[mt][2], ah[mt][3],
                             bl[nt][0], bl[nt][1]);
                    MMA16816(acc[mt][nt], ah[mt][0], ah[mt][1], ah[mt][2], ah[mt][3],
                             bh[nt][0], bh[nt][1]);
                }
        }
        __syncthreads();
        if (it + 2 < nIter) {
            do_cp(it & 1, (it + 2) << 6);
            CP_COMMIT();
        }
    }

    const int g = lane >> 2, t = lane & 3;
#pragma unroll
    for (int mt = 0; mt < 2; ++mt) {
        int r = row0 + wm * 32 + mt * 16 + g;
#pragma unroll
        for (int nt = 0; nt < 8; ++nt) {
            int c = col0 + wn * 64 + nt * 8 + 2 * t;
            if (split_out) {
                uint32_t hh, ll;
                split_h2(acc[mt][nt][0], acc[mt][nt][1], hh, ll);
                *(uint32_t*)(Ch + (size_t)r * ldc + c) = hh;
                *(uint32_t*)(Cl + (size_t)r * ldc + c) = ll;
                split_h2(acc[mt][nt][2], acc[mt][nt][3], hh, ll);
                *(uint32_t*)(Ch + (size_t)(r + 8) * ldc + c) = hh;
                *(uint32_t*)(Cl + (size_t)(r + 8) * ldc + c) = ll;
            } else if (c < N) {
                *(float2*)(C + (size_t)r * ldc + c)       = make_float2(acc[mt][nt][0], acc[mt][nt][1]);
                *(float2*)(C + (size_t)(r + 8) * ldc + c) = make_float2(acc[mt][nt][2], acc[mt][nt][3]);
            }
        }
    }
}

__global__ __launch_bounds__(256, 2) void gemm_f32out(
    const __half* __restrict__ Ah, int lda,
    const __half* __restrict__ Bh, const __half* __restrict__ Bl, int ldb,
    float* __restrict__ C, int ldc, int N, int K)
{
    extern __shared__ char sm[];
    gemm_core(Ah, lda, Bh, Bl, ldb, C, (__half*)0, (__half*)0, ldc, N, K,
              blockIdx.y * 128, blockIdx.x * 128, false, sm);
}

// merged GEMM2 (q = qa_n @ w_qb, fp32 out) + GEMM3 (kv = ckn @ w_kvb, split out)
#define G2_TILES 384   // 24 x 16
#define G3_TILES 512   // 32 x 16
__global__ __launch_bounds__(256, 2) void gemm_dual(
    const __half* __restrict__ A2, const __half* __restrict__ B2h,
    const __half* __restrict__ B2l, float* __restrict__ C2,
    const __half* __restrict__ A3, const __half* __restrict__ B3h,
    const __half* __restrict__ B3l, __half* __restrict__ C3h, __half* __restrict__ C3l)
{
    extern __shared__ char sm[];
    int b = blockIdx.x;
    if (b < G2_TILES) {
        gemm_core(A2, QL, B2h, B2l, QW, C2, (__half*)0, (__half*)0, QW, QW, QL,
                  (b / 24) * 128, (b % 24) * 128, false, sm);
    } else {
        int r = b - G2_TILES;
        gemm_core(A3, KVL, B3h, B3l, KVW, (float*)0, C3h, C3l, KVW, KVW, KVL,
                  (r / 32) * 128, (r % 32) * 128, true, sm);
    }
}

// ------- RoPE on q + full q split; kpe in tail blocks -------
__global__ __launch_bounds__(256) void rope_qsplit_kernel(
    const float* __restrict__ qf, const float* __restrict__ qc,
    __half* __restrict__ qsh, __half* __restrict__ qsl,
    __half* __restrict__ kpeh, __half* __restrict__ kpel,
    const float* __restrict__ cosb, const float* __restrict__ sinb)
{
    __shared__ float row[QW];
    int b = blockIdx.x;
    if (b < SEQ) {
        const int s = b;
        const float* src = qf + (size_t)s * QW;
#pragma unroll
        for (int i = 0; i < 3; ++i) {
            int idx = (i * 256 + threadIdx.x) * 4;
            *(float4*)(row + idx) = *(const float4*)(src + idx);
        }
        __syncthreads();
        float y0[2], y1[2];
        int hd[2], ln[2];
#pragma unroll
        for (int e = 0; e < 2; ++e) {
            int item = threadIdx.x + e * 256;
            hd[e] = item >> 5; ln[e] = item & 31;
            float c  = cosb[s * DR + ln[e]];
            float sn = sinb[s * DR + ln[e]];
            float x0 = row[hd[e] * DQK + DN + 2 * ln[e]];
            float x1 = row[hd[e] * DQK + DN + 2 * ln[e] + 1];
            y0[e] = x0 * c - x1 * sn;
            y1[e] = x1 * c + x0 * sn;
        }
        __syncthreads();
#pragma unroll
        for (int e = 0; e < 2; ++e) {
            row[hd[e] * DQK + DN + ln[e]]      = y0[e];
            row[hd[e] * DQK + DN + ln[e] + 32] = y1[e];
        }
        __syncthreads();
#pragma unroll
        for (int i = 0; i < 6; ++i) {
            int p = i * 256 + threadIdx.x;
            uint32_t hh, ll;
            split_h2(row[2 * p], row[2 * p + 1], hh, ll);
            ((uint32_t*)qsh)[(size_t)s * (QW / 2) + p] = hh;
            ((uint32_t*)qsl)[(size_t)s * (QW / 2) + p] = ll;
        }
    } else {
        int wr = (b - SEQ) * 8 + (threadIdx.x >> 5);
        int lane = threadIdx.x & 31;
        const float* x = qc + (size_t)wr * FWP + QL + KVL;
        float c  = cosb[wr * DR + lane];
        float sn = sinb[wr * DR + lane];
        float x0 = x[2 * lane], x1 = x[2 * lane + 1];
        float z0 = x0 * c - x1 * sn;
        float z1 = x1 * c + x0 * sn;
        __half h0 = __float2half_rn(z0);
        __half h1 = __float2half_rn(z1);
        kpeh[wr * DR + lane]      = h0;
        kpel[wr * DR + lane]      = __float2half_rn(z0 - __half2float(h0));
        kpeh[wr * DR + lane + 32] = h1;
        kpel[wr * DR + lane + 32] = __float2half_rn(z1 - __half2float(h1));
    }
}

// ==== flash attention BQ=128/BK=64, cp.async phase-pipelined fills ====
#define A_QH 0
#define A_QL 49152
#define A_KH 98304
#define A_KL 122880
#define A_VH 147456
#define A_VL 163840
#define A_PH 180224
#define ATTN_SMEM_BYTES 196608

__global__ __launch_bounds__(256) void attn_mma(
    const __half* __restrict__ qh, const __half* __restrict__ ql,
    const __half* __restrict__ kvh, const __half* __restrict__ kvl,
    const __half* __restrict__ kpeh, const __half* __restrict__ kpel,
    __half* __restrict__ ath)
{
    extern __shared__ char sm[];
    const uint32_t sb = smem_u32(sm);

    const int tid = threadIdx.x, lane = tid & 31, wm = tid >> 5;
    const int qb = gridDim.x - 1 - blockIdx.x;
    const int hh_ = blockIdx.y;
    const int q0 = qb * 128;
    const float scale = rsqrtf((float)DQK);
    const int nkb = 2 * qb + 2;

    auto fill_K = [&](int kb) {
        const int k0 = kb * 64;
#pragma unroll
        for (int i = 0; i < 6; ++i) {
            int idx = i * 256 + tid;
            int r = idx / 24, u = idx % 24;
            uint32_t off = r * 384 + ((u ^ (r & 7)) << 4);
            if (u < 16) {
                const size_t go = (size_t)(k0 + r) * KVW + hh_ * (DN + DV) + u * 8;
                CP_ASYNC16(sb + A_KH + off, kvh + go);
                CP_ASYNC16(sb + A_KL + off, kvl + go);
            } else {
                const size_t go = (size_t)(k0 + r) * DR + (u - 16) * 8;
                CP_ASYNC16(sb + A_KH + off, kpeh + go);
                CP_ASYNC16(sb + A_KL + off, kpel + go);
            }
        }
    };
    auto fill_V = [&](int kb) {
        const int k0 = kb * 64;
#pragma unroll
        for (int i = 0; i < 4; ++i) {
            int idx = i * 256 + tid;
            int r = idx >> 4, u = idx & 15;
            uint32_t off = r * 256 + ((u ^ (r & 7)) << 4);
            const size_t go = (size_t)(k0 + r) * KVW + hh_ * (DN + DV) + DN + u * 8;
            CP_ASYNC16(sb + A_VH + off, kvh + go);
            CP_ASYNC16(sb + A_VL + off, kvl + go);
        }
    };

    // prologue: K0, V0 in flight; Q fill via regular stores
    fill_K(0); CP_COMMIT();
    fill_V(0); CP_COMMIT();
#pragma unroll
    for (int i = 0; i < 12; ++i) {
        int idx = i * 256 + tid;
        int r = idx / 24, u = idx % 24;
        int off = r * 384 + ((u ^ (r & 7)) << 4);
        const size_t go = (size_t)(q0 + r) * QW + hh_ * DQK + u * 8;
        *(uint4*)(sm + A_QH + off) = *(const uint4*)(qh + go);
        *(uint4*)(sm + A_QL + off) = *(const uint4*)(ql + go);
    }

    const int g = lane >> 2, t = lane & 3;
    const int r0 = wm * 16 + g, r1 = r0 + 8;

    float m0 = -1e30f, m1 = -1e30f, l0 = 0.f, l1 = 0.f;
    float acc_o[16][4];
#pragma unroll
    for (int nt = 0; nt < 16; ++nt)
#pragma unroll
        for (int i = 0; i < 4; ++i) acc_o[nt][i] = 0.f;

    for (int kb = 0; kb < nkb; ++kb) {
        const int k0 = kb * 64;
        const bool more = (kb + 1 < nkb);

        // K(kb) ready (V(kb) may still be in flight)
        CP_WAIT1();
        __syncthreads();

        // ---- S = Q @ K^T (fp16x3) ----
        float acc_s[8][4];
#pragma unroll
        for (int nt = 0; nt < 8; ++nt)
#pragma unroll
            for (int i = 0; i < 4; ++i) acc_s[nt][i] = 0.f;

#pragma unroll
        for (int ks = 0; ks < 12; ++ks) {
            uint32_t qfh[4], qfl[4];
            {
                int rowi = wm * 16 + (lane & 15);
                int c = 2 * ks + (lane >> 4);
                uint32_t ad = smem_u32(sm + rowi * 384 + ((c ^ (rowi & 7)) << 4));
                LDSM_X4(qfh[0], qfh[1], qfh[2], qfh[3], ad + A_QH);
                LDSM_X4(qfl[0], qfl[1], qfl[2], qfl[3], ad + (A_QL - A_QH));
            }
#pragma unroll
            for (int nt = 0; nt < 8; ++nt) {
                int krow = nt * 8 + (lane & 7);
                int kc = 2 * ks + ((lane >> 3) & 1);
                uint32_t kd = smem_u32(sm + A_KH + krow * 384 + ((kc ^ (krow & 7)) << 4));
                uint32_t kh0, kh1, kl0, kl1;
                LDSM_X2(kh0, kh1, kd);
                LDSM_X2(kl0, kl1, kd + (A_KL - A_KH));
                MMA16816(acc_s[nt], qfh[0], qfh[1], qfh[2], qfh[3], kl0, kl1);
                MMA16816(acc_s[nt], qfl[0], qfl[1], qfl[2], qfl[3], kh0, kh1);
                MMA16816(acc_s[nt], qfh[0], qfh[1], qfh[2], qfh[3], kh0, kh1);
            }
        }
        // all warps done reading K -> safe to start K(kb+1)
        __syncthreads();
        if (more) fill_K(kb + 1);
        CP_COMMIT();

        // ---- scale + mask + quad max ----
        float vm0 = -1e30f, vm1 = -1e30f;
#pragma unroll
        for (int nt = 0; nt < 8; ++nt) {
            int col = k0 + nt * 8 + 2 * t;
            float v00 = acc_s[nt][0] * scale, v01 = acc_s[nt][1] * scale;
            float v10 = acc_s[nt][2] * scale, v11 = acc_s[nt][3] * scale;
            if (col     > q0 + r0) v00 = -1e30f;
            if (col + 1 > q0 + r0) v01 = -1e30f;
            if (col     > q0 + r1) v10 = -1e30f;
            if (col + 1 > q0 + r1) v11 = -1e30f;
            acc_s[nt][0] = v00; acc_s[nt][1] = v01;
            acc_s[nt][2] = v10; acc_s[nt][3] = v11;
            vm0 = fmaxf(vm0, fmaxf(v00, v01));
            vm1 = fmaxf(vm1, fmaxf(v10, v11));
        }
        vm0 = fmaxf(vm0, __shfl_xor_sync(0xffffffffu, vm0, 1));
        vm0 = fmaxf(vm0, __shfl_xor_sync(0xffffffffu, vm0, 2));
        vm1 = fmaxf(vm1, __shfl_xor_sync(0xffffffffu, vm1, 1));
        vm1 = fmaxf(vm1, __shfl_xor_sync(0xffffffffu, vm1, 2));

        float mnew0 = fmaxf(m0, vm0);
        float mnew1 = fmaxf(m1, vm1);
        float alpha0 = __expf(m0 - mnew0);
        float alpha1 = __expf(m1 - mnew1);
        m0 = mnew0; m1 = mnew1;

        // ---- exp + P fp16 to warp-local swizzled smem ----
        float s0 = 0.f, s1 = 0.f;
#pragma unroll
        for (int nt = 0; nt < 8; ++nt) {
            float p00 = __expf(acc_s[nt][0] - mnew0);
            float p01 = __expf(acc_s[nt][1] - mnew0);
            float p10 = __expf(acc_s[nt][2] - mnew1);
            float p11 = __expf(acc_s[nt][3] - mnew1);
            s0 += p00 + p01;
            s1 += p10 + p11;
            int off0 = r0 * 128 + ((nt ^ (r0 & 7)) << 4) + t * 4;
            *(__half2*)(sm + A_PH + off0) = __float22half2_rn(make_float2(p00, p01));
            int off1 = r1 * 128 + ((nt ^ (r1 & 7)) << 4) + t * 4;
            *(__half2*)(sm + A_PH + off1) = __float22half2_rn(make_float2(p10, p11));
        }
        s0 += __shfl_xor_sync(0xffffffffu, s0, 1);
        s0 += __shfl_xor_sync(0xffffffffu, s0, 2);
        s1 += __shfl_xor_sync(0xffffffffu, s1, 1);
        s1 += __shfl_xor_sync(0xffffffffu, s1, 2);
        l0 = l0 * alpha0 + s0;
        l1 = l1 * alpha1 + s1;
        __syncwarp();

        // V(kb) ready: outstanding = {V(kb), K(kb+1)} normally
        if (more) { CP_WAIT1(); } else { CP_WAIT0(); }
        __syncthreads();

        // ---- rescale O, then O += P @ V ----
#pragma unroll
        for (int nt = 0; nt < 16; ++nt) {
            acc_o[nt][0] *= alpha0; acc_o[nt][1] *= alpha0;
            acc_o[nt][2] *= alpha1; acc_o[nt][3] *= alpha1;
        }
#pragma unroll
        for (int ks = 0; ks < 4; ++ks) {
            uint32_t ph[4];
            {
                int rowi = wm * 16 + (lane & 15);
                int c = 2 * ks + (lane >> 4);
                uint32_t pd = smem_u32(sm + A_PH + rowi * 128 + ((c ^ (rowi & 7)) << 4));
                LDSM_X4(ph[0], ph[1], ph[2], ph[3], pd);
            }
#pragma unroll
            for (int pr = 0; pr < 8; ++pr) {
                int vk = ks * 16 + (lane & 15);
                int vc = pr * 2 + (lane >> 4);
                uint32_t vd = smem_u32(sm + A_VH + vk * 256 + ((vc ^ (vk & 7)) << 4));
                uint32_t b0, b1, b2, b3, c0, c1, c2, c3;
                LDSM_X4_T(b0, b1, b2, b3, vd);
                LDSM_X4_T(c0, c1, c2, c3, vd + (A_VL - A_VH));
                int nt0 = 2 * pr, nt1 = 2 * pr + 1;
                MMA16816(acc_o[nt0], ph[0], ph[1], ph[2], ph[3], c0, c1);
                MMA16816(acc_o[nt0], ph[0], ph[1], ph[2], ph[3], b0, b1);
                MMA16816(acc_o[nt1], ph[0], ph[1], ph[2], ph[3], c2, c3);
                MMA16816(acc_o[nt1], ph[0], ph[1], ph[2], ph[3], b2, b3);
            }
        }
        // all warps done reading V -> safe to start V(kb+1)
        __syncthreads();
        if (more) fill_V(kb + 1);
        CP_COMMIT();
    }

    float inv0 = 1.f / l0;
    float inv1 = 1.f / l1;
#pragma unroll
    for (int nt = 0; nt < 16; ++nt) {
        int col = nt * 8 + 2 * t;
        *(__half2*)(ath + (size_t)(q0 + r0) * AW + hh_ * DV + col) =
            __float22half2_rn(make_float2(acc_o[nt][0] * inv0, acc_o[nt][1] * inv0));
        *(__half2*)(ath + (size_t)(q0 + r1) * AW + hh_ * DV + col) =
            __float22half2_rn(make_float2(acc_o[nt][2] * inv1, acc_o[nt][3] * inv1));
    }
}

// ---------------- launch ----------------
extern "C" void kernel_launch(void* const* d_in, const int* in_sizes, int n_in,
                              void* d_out, int out_size)
{
    const float* hidden = (const float*)d_in[0];
    const float* cosb   = (const float*)d_in[1];
    const float* sinb   = (const float*)d_in[2];
    const float* w_qa   = (const float*)d_in[3];
    const float* gm_qa  = (const float*)d_in[4];
    const float* w_qb   = (const float*)d_in[5];
    const float* w_kva  = (const float*)d_in[6];
    const float* gm_kva = (const float*)d_in[7];
    const float* w_kvb  = (const float*)d_in[8];
    const float* w_o    = (const float*)d_in[9];
    float* out = (float*)d_out;

    float *qc, *qf;
    __half *hidh, *wfh, *wfl, *qbh, *qbl, *kvbh, *kvbl, *oh, *ol;
    __half *qanh, *cknh, *qsh, *qsl, *kvh, *kvl, *kpeh, *kpel, *ath;
    cudaGetSymbolAddress((void**)&qc,   g_qc_s);
    cudaGetSymbolAddress((void**)&qf,   g_q_s);
    cudaGetSymbolAddress((void**)&hidh, g_hid_h);
    cudaGetSymbolAddress((void**)&wfh,  g_wf_h);  cudaGetSymbolAddress((void**)&wfl,  g_wf_l);
    cudaGetSymbolAddress((void**)&qbh,  g_qb_h);  cudaGetSymbolAddress((void**)&qbl,  g_qb_l);
    cudaGetSymbolAddress((void**)&kvbh, g_kvb_h); cudaGetSymbolAddress((void**)&kvbl, g_kvb_l);
    cudaGetSymbolAddress((void**)&oh,   g_o_h);   cudaGetSymbolAddress((void**)&ol,   g_o_l);
    cudaGetSymbolAddress((void**)&qanh, g_qan_h);
    cudaGetSymbolAddress((void**)&cknh, g_ckn_h);
    cudaGetSymbolAddress((void**)&qsh,  g_qs_h);  cudaGetSymbolAddress((void**)&qsl,  g_qs_l);
    cudaGetSymbolAddress((void**)&kvh,  g_kv_h);  cudaGetSymbolAddress((void**)&kvl,  g_kv_l);
    cudaGetSymbolAddress((void**)&kpeh, g_kpe_h); cudaGetSymbolAddress((void**)&kpel, g_kpe_l);
    cudaGetSymbolAddress((void**)&ath,  g_at_h);

    static bool attr_done = false;
    if (!attr_done) {
        cudaFuncSetAttribute(attn_mma, cudaFuncAttributeMaxDynamicSharedMemorySize,
                             ATTN_SMEM_BYTES);
        cudaFuncSetAttribute(gemm_f32out, cudaFuncAttributeMaxDynamicSharedMemorySize,
                             GEMM_SMEM_BYTES);
        cudaFuncSetAttribute(gemm_dual, cudaFuncAttributeMaxDynamicSharedMemorySize,
                             GEMM_SMEM_BYTES);
        attr_done = true;
    }

    prep_kernel<<<PREP_BLOCKS, 256>>>(hidden, w_qa, w_kva, w_qb, w_kvb, w_o,
                                      hidh, wfh, wfl, qbh, qbl, kvbh, kvbl, oh, ol);
    // GEMM1: [qa|ckv] = hidden @ wf
    gemm_f32out<<<dim3(FWP / 128, SEQ / 128), 256, GEMM_SMEM_BYTES>>>(
        hidh, HID, wfh, wfl, FWP, qc, FWP, FW, HID);
    rmsnorm2_kernel<<<SEQ, 256>>>(qc, gm_qa, gm_kva, qanh, cknh);
    // merged GEMM2 + GEMM3 (independent, share one wave structure)
    gemm_dual<<<G2_TILES + G3_TILES, 256, GEMM_SMEM_BYTES>>>(
        qanh, qbh, qbl, qf, cknh, kvbh, kvbl, kvh, kvl);
    rope_qsplit_kernel<<<SEQ + 256, 256>>>(qf, qc, qsh, qsl, kpeh, kpel, cosb, sinb);
    attn_mma<<<dim3(SEQ / 128, NH), 256, ATTN_SMEM_BYTES>>>(
        qsh, qsl, kvh, kvl, kpeh, kpel, ath);
    // GEMM4: out = attn @ w_o
    gemm_f32out<<<dim3(HID / 128, SEQ / 128), 256, GEMM_SMEM_BYTES>>>(
        ath, AW, oh, ol, HID, out, HID, HID, AW);
}